// round 1
// baseline (speedup 1.0000x reference)
#include <cuda_runtime.h>

// Problem constants
#define BB 4
#define SS 2048
#define HH 16
#define DK 64
#define DM 1024
#define MROWS (BB*SS)                       // 8192
#define OUT_ELEMS ((size_t)MROWS*DM)        // 8,388,608
#define ATTN_ELEMS ((size_t)BB*HH*SS*SS)    // 268,435,456

// ---------------- scratch (device globals; no allocations allowed) ----------
__device__ float g_qh[(size_t)BB*HH*SS*DK];
__device__ float g_kh[(size_t)BB*HH*SS*DK];
__device__ float g_vh[(size_t)BB*HH*SS*DK];
__device__ float g_ctx[(size_t)MROWS*DM];
__device__ float g_attn[(size_t)BB*HH*SS*SS];   // used only if attn not in d_out

// ---------------------------------------------------------------------------
// Generic NT GEMM with bias: C = A[M,K] @ W[N,K]^T + bias[N]
// HEADMODE=1 scatters output into per-head layout [B,H,S,DK].
// Tiling: 128x128x8, 256 threads, 8x8 per-thread micro tile.
// ---------------------------------------------------------------------------
template<int HEADMODE>
__global__ void __launch_bounds__(256) gemm_bias_kernel(
    const float* __restrict__ A, const float* __restrict__ W,
    const float* __restrict__ bias, float* __restrict__ C,
    int M, int N, int K)
{
    const int BM = 128, BN = 128, BK = 8;
    __shared__ float As[BK][BM];
    __shared__ float Bs[BK][BN];

    int tid = threadIdx.x;
    int tx = tid & 15, ty = tid >> 4;
    int row0 = blockIdx.y * BM, col0 = blockIdx.x * BN;

    int lr = tid >> 1;            // 0..127
    int lc = (tid & 1) * 4;       // 0 or 4

    float acc[8][8];
    #pragma unroll
    for (int i = 0; i < 8; i++)
        #pragma unroll
        for (int j = 0; j < 8; j++) acc[i][j] = 0.0f;

    const float* Aptr = A + (size_t)(row0 + lr) * K + lc;
    const float* Wptr = W + (size_t)(col0 + lr) * K + lc;

    for (int k0 = 0; k0 < K; k0 += BK) {
        float4 av = *(const float4*)(Aptr + k0);
        float4 bv = *(const float4*)(Wptr + k0);
        As[lc + 0][lr] = av.x; As[lc + 1][lr] = av.y;
        As[lc + 2][lr] = av.z; As[lc + 3][lr] = av.w;
        Bs[lc + 0][lr] = bv.x; Bs[lc + 1][lr] = bv.y;
        Bs[lc + 2][lr] = bv.z; Bs[lc + 3][lr] = bv.w;
        __syncthreads();
        #pragma unroll
        for (int kk = 0; kk < BK; kk++) {
            float a[8], b[8];
            #pragma unroll
            for (int i = 0; i < 8; i++) a[i] = As[kk][ty * 8 + i];
            #pragma unroll
            for (int j = 0; j < 8; j++) b[j] = Bs[kk][tx * 8 + j];
            #pragma unroll
            for (int i = 0; i < 8; i++)
                #pragma unroll
                for (int j = 0; j < 8; j++) acc[i][j] += a[i] * b[j];
        }
        __syncthreads();
    }

    #pragma unroll
    for (int i = 0; i < 8; i++) {
        int r = row0 + ty * 8 + i;
        #pragma unroll
        for (int j = 0; j < 8; j++) {
            int c = col0 + tx * 8 + j;
            float val = acc[i][j] + bias[c];
            if (HEADMODE) {
                int b = r >> 11, s = r & (SS - 1);
                int h = c >> 6, d = c & (DK - 1);
                C[((((size_t)b * HH + h) * SS) + s) * DK + d] = val;
            } else {
                C[(size_t)r * N + c] = val;
            }
        }
    }
}

// ---------------------------------------------------------------------------
// Batched scores: P[bh][s][t] = (Qh[bh][s] . Kh[bh][t]) / 8
// ---------------------------------------------------------------------------
__global__ void __launch_bounds__(256) scores_kernel(
    const float* __restrict__ Qh, const float* __restrict__ Kh,
    float* __restrict__ P)
{
    const int BM = 128, BN = 128, BK = 8;
    __shared__ float As[BK][BM];
    __shared__ float Bs[BK][BN];

    int tid = threadIdx.x;
    int tx = tid & 15, ty = tid >> 4;
    int row0 = blockIdx.y * BM, col0 = blockIdx.x * BN;
    int bh = blockIdx.z;

    const float* Q  = Qh + (size_t)bh * SS * DK;
    const float* Kp = Kh + (size_t)bh * SS * DK;

    int lr = tid >> 1;
    int lc = (tid & 1) * 4;

    float acc[8][8];
    #pragma unroll
    for (int i = 0; i < 8; i++)
        #pragma unroll
        for (int j = 0; j < 8; j++) acc[i][j] = 0.0f;

    for (int k0 = 0; k0 < DK; k0 += BK) {
        float4 av = *(const float4*)&Q [(size_t)(row0 + lr) * DK + k0 + lc];
        float4 bv = *(const float4*)&Kp[(size_t)(col0 + lr) * DK + k0 + lc];
        As[lc + 0][lr] = av.x; As[lc + 1][lr] = av.y;
        As[lc + 2][lr] = av.z; As[lc + 3][lr] = av.w;
        Bs[lc + 0][lr] = bv.x; Bs[lc + 1][lr] = bv.y;
        Bs[lc + 2][lr] = bv.z; Bs[lc + 3][lr] = bv.w;
        __syncthreads();
        #pragma unroll
        for (int kk = 0; kk < BK; kk++) {
            float a[8], b[8];
            #pragma unroll
            for (int i = 0; i < 8; i++) a[i] = As[kk][ty * 8 + i];
            #pragma unroll
            for (int j = 0; j < 8; j++) b[j] = Bs[kk][tx * 8 + j];
            #pragma unroll
            for (int i = 0; i < 8; i++)
                #pragma unroll
                for (int j = 0; j < 8; j++) acc[i][j] += a[i] * b[j];
        }
        __syncthreads();
    }

    float* Pb = P + (size_t)bh * SS * SS;
    #pragma unroll
    for (int i = 0; i < 8; i++) {
        int r = row0 + ty * 8 + i;
        #pragma unroll
        for (int j = 0; j < 8; j++) {
            int c = col0 + tx * 8 + j;
            Pb[(size_t)r * SS + c] = acc[i][j] * 0.125f;   // 1/sqrt(64)
        }
    }
}

// ---------------------------------------------------------------------------
// Row softmax in place. One block (256 threads) per row of 2048.
// ---------------------------------------------------------------------------
__global__ void __launch_bounds__(256) softmax_kernel(float* __restrict__ P)
{
    __shared__ float red[256];
    size_t row = blockIdx.x;
    float* p = P + row * SS;
    int tid = threadIdx.x;

    float v[8];
    float m = -1e30f;
    #pragma unroll
    for (int i = 0; i < 8; i++) {
        v[i] = p[tid + i * 256];
        m = fmaxf(m, v[i]);
    }
    red[tid] = m;
    __syncthreads();
    for (int s = 128; s > 0; s >>= 1) {
        if (tid < s) red[tid] = fmaxf(red[tid], red[tid + s]);
        __syncthreads();
    }
    m = red[0];
    __syncthreads();

    float sum = 0.0f;
    #pragma unroll
    for (int i = 0; i < 8; i++) {
        v[i] = __expf(v[i] - m);
        sum += v[i];
    }
    red[tid] = sum;
    __syncthreads();
    for (int s = 128; s > 0; s >>= 1) {
        if (tid < s) red[tid] += red[tid + s];
        __syncthreads();
    }
    float inv = 1.0f / red[0];

    #pragma unroll
    for (int i = 0; i < 8; i++)
        p[tid + i * 256] = v[i] * inv;
}

// ---------------------------------------------------------------------------
// AV: ctx[b][s][h*64+d] = sum_t P[bh][s][t] * Vh[bh][t][d]
// Tiling: 128x64x16, 256 threads, 8x4 per-thread micro tile.
// ---------------------------------------------------------------------------
__global__ void __launch_bounds__(256) av_kernel(
    const float* __restrict__ P, const float* __restrict__ Vh,
    float* __restrict__ ctx)
{
    const int BM = 128, BK = 16;
    __shared__ float As[BK][BM];
    __shared__ float Bs[BK][DK];

    int tid = threadIdx.x;
    int tx = tid & 15, ty = tid >> 4;
    int m0 = blockIdx.x * BM;
    int bh = blockIdx.z;
    int bb = bh >> 4, hh = bh & 15;

    const float* Pb = P  + (size_t)bh * SS * SS;
    const float* Vb = Vh + (size_t)bh * SS * DK;

    int lrA = tid >> 1;            // 0..127
    int lcA = (tid & 1) * 8;       // 0 or 8
    int krB = tid >> 4;            // 0..15
    int ncB = (tid & 15) * 4;      // 0..60

    float acc[8][4];
    #pragma unroll
    for (int i = 0; i < 8; i++)
        #pragma unroll
        for (int j = 0; j < 4; j++) acc[i][j] = 0.0f;

    for (int k0 = 0; k0 < SS; k0 += BK) {
        float4 a0 = *(const float4*)&Pb[(size_t)(m0 + lrA) * SS + k0 + lcA];
        float4 a1 = *(const float4*)&Pb[(size_t)(m0 + lrA) * SS + k0 + lcA + 4];
        float4 b0 = *(const float4*)&Vb[(size_t)(k0 + krB) * DK + ncB];
        As[lcA + 0][lrA] = a0.x; As[lcA + 1][lrA] = a0.y;
        As[lcA + 2][lrA] = a0.z; As[lcA + 3][lrA] = a0.w;
        As[lcA + 4][lrA] = a1.x; As[lcA + 5][lrA] = a1.y;
        As[lcA + 6][lrA] = a1.z; As[lcA + 7][lrA] = a1.w;
        Bs[krB][ncB + 0] = b0.x; Bs[krB][ncB + 1] = b0.y;
        Bs[krB][ncB + 2] = b0.z; Bs[krB][ncB + 3] = b0.w;
        __syncthreads();
        #pragma unroll
        for (int kk = 0; kk < BK; kk++) {
            float a[8], b[4];
            #pragma unroll
            for (int i = 0; i < 8; i++) a[i] = As[kk][ty * 8 + i];
            #pragma unroll
            for (int j = 0; j < 4; j++) b[j] = Bs[kk][tx * 4 + j];
            #pragma unroll
            for (int i = 0; i < 8; i++)
                #pragma unroll
                for (int j = 0; j < 4; j++) acc[i][j] += a[i] * b[j];
        }
        __syncthreads();
    }

    #pragma unroll
    for (int i = 0; i < 8; i++) {
        int s = m0 + ty * 8 + i;
        #pragma unroll
        for (int j = 0; j < 4; j++) {
            int d = tx * 4 + j;
            ctx[((size_t)bb * SS + s) * DM + hh * DK + d] = acc[i][j];
        }
    }
}

// ---------------------------------------------------------------------------
extern "C" void kernel_launch(void* const* d_in, const int* in_sizes, int n_in,
                              void* d_out, int out_size)
{
    const float* q   = (const float*)d_in[0];
    const float* k   = (const float*)d_in[1];
    const float* v   = (const float*)d_in[2];
    const float* w_q = (const float*)d_in[3];
    const float* b_q = (const float*)d_in[4];
    const float* w_k = (const float*)d_in[5];
    const float* b_k = (const float*)d_in[6];
    const float* w_v = (const float*)d_in[7];
    const float* b_v = (const float*)d_in[8];
    const float* w_o = (const float*)d_in[9];
    const float* b_o = (const float*)d_in[10];
    float* out = (float*)d_out;

    float *qh, *kh, *vh, *ctx;
    cudaGetSymbolAddress((void**)&qh,  g_qh);
    cudaGetSymbolAddress((void**)&kh,  g_kh);
    cudaGetSymbolAddress((void**)&vh,  g_vh);
    cudaGetSymbolAddress((void**)&ctx, g_ctx);

    // Reference returns (out, attn): if the harness wants both, attn follows
    // out inside d_out; otherwise keep it in scratch.
    float* attn;
    if ((size_t)out_size >= OUT_ELEMS + ATTN_ELEMS) {
        attn = out + OUT_ELEMS;
    } else {
        cudaGetSymbolAddress((void**)&attn, g_attn);
    }

    dim3 gproj(DM / 128, MROWS / 128);              // (8, 64)
    gemm_bias_kernel<1><<<gproj, 256>>>(q, w_q, b_q, qh, MROWS, DM, DM);
    gemm_bias_kernel<1><<<gproj, 256>>>(k, w_k, b_k, kh, MROWS, DM, DM);
    gemm_bias_kernel<1><<<gproj, 256>>>(v, w_v, b_v, vh, MROWS, DM, DM);

    scores_kernel<<<dim3(SS / 128, SS / 128, BB * HH), 256>>>(qh, kh, attn);

    softmax_kernel<<<dim3(BB * HH * SS), 256>>>(attn);

    av_kernel<<<dim3(SS / 128, 1, BB * HH), 256>>>(attn, vh, ctx);

    gemm_bias_kernel<0><<<gproj, 256>>>(ctx, w_o, b_o, out, MROWS, DM, DM);
}

// round 3
// speedup vs baseline: 1.5666x; 1.5666x over previous
#include <cuda_runtime.h>
#include <cuda_bf16.h>
#include <cstdint>

// ---------------- problem constants ----------------
#define BB 4
#define SS 2048
#define HH 16
#define DK 64
#define DM 1024
#define MROWS (BB*SS)                        // 8192
#define OUT_ELEMS ((size_t)MROWS*DM)         // 8,388,608
#define ATTN_ELEMS ((size_t)BB*HH*SS*SS)     // 268,435,456

// ---------------- device-global scratch (no allocations allowed) -----------
__device__ __nv_bfloat16 g_qh_h[(size_t)MROWS*DM], g_qh_l[(size_t)MROWS*DM];
__device__ __nv_bfloat16 g_kh_h[(size_t)MROWS*DM], g_kh_l[(size_t)MROWS*DM];
__device__ __nv_bfloat16 g_vh_h[(size_t)MROWS*DM], g_vh_l[(size_t)MROWS*DM];
__device__ __nv_bfloat16 g_cx_h[(size_t)MROWS*DM], g_cx_l[(size_t)MROWS*DM];
__device__ float g_attn[ATTN_ELEMS];   // used only if attn not part of d_out

// ---------------- helpers ----------------
#define SWZ(o) ((o) ^ (((o) >> 3) & 0x70))

__device__ __forceinline__ uint32_t smem_u32(const void* p) {
    uint32_t a;
    asm("{ .reg .u64 t; cvta.to.shared.u64 t, %1; cvt.u32.u64 %0, t; }"
        : "=r"(a) : "l"(p));
    return a;
}
__device__ __forceinline__ void ldm_x4(uint32_t addr, uint32_t& r0, uint32_t& r1,
                                       uint32_t& r2, uint32_t& r3) {
    asm volatile("ldmatrix.sync.aligned.m8n8.x4.shared.b16 {%0,%1,%2,%3}, [%4];"
                 : "=r"(r0), "=r"(r1), "=r"(r2), "=r"(r3) : "r"(addr));
}
__device__ __forceinline__ void mma_bf16(float* c, uint32_t a0, uint32_t a1,
                                         uint32_t a2, uint32_t a3,
                                         uint32_t b0, uint32_t b1) {
    asm volatile("mma.sync.aligned.m16n8k16.row.col.f32.bf16.bf16.f32 "
                 "{%0,%1,%2,%3}, {%4,%5,%6,%7}, {%8,%9}, {%0,%1,%2,%3};"
                 : "+f"(c[0]), "+f"(c[1]), "+f"(c[2]), "+f"(c[3])
                 : "r"(a0), "r"(a1), "r"(a2), "r"(a3), "r"(b0), "r"(b1));
}
__device__ __forceinline__ uint32_t pk2(__nv_bfloat16 a, __nv_bfloat16 b) {
    return ((uint32_t)__bfloat16_as_ushort(b) << 16) | (uint32_t)__bfloat16_as_ushort(a);
}
__device__ __forceinline__ void split1(float x, __nv_bfloat16& h, __nv_bfloat16& l) {
    h = __float2bfloat16(x);
    l = __float2bfloat16(x - __bfloat162float(h));
}

// ---------------------------------------------------------------------------
// Unified mma.sync bf16x3 GEMM.
// VAR 0 = projection : C[8192,1024] = A(fp32) @ W(fp32)^T + bias -> hi/lo head planes
// VAR 1 = out proj   : C = A(planes) @ W(fp32)^T + bias -> fp32 out
// VAR 2 = scores     : per bh: Q(planes)[2048,64] @ K(planes)^T * 0.125 -> fp32
// VAR 3 = AV         : per bh: P(fp32)[2048,2048] @ V(planes)[2048,64]^T' -> hi/lo planes
// Block tile: 128 x NT, K chunk 64. 8 warps (2x4), warp tile 64 x NT/4.
// ---------------------------------------------------------------------------
template<int VAR>
__global__ void __launch_bounds__(256) mma_gemm(
    const float* __restrict__ Af,
    const __nv_bfloat16* __restrict__ Ah, const __nv_bfloat16* __restrict__ Al,
    const float* __restrict__ Bf,
    const __nv_bfloat16* __restrict__ Bh, const __nv_bfloat16* __restrict__ Bl,
    const float* __restrict__ bias,
    float* __restrict__ Cf,
    __nv_bfloat16* __restrict__ Ch, __nv_bfloat16* __restrict__ Cl)
{
    constexpr int NT  = (VAR == 3) ? 64 : 128;
    constexpr int NF  = NT / 32;             // n-tiles (8 wide) per warp
    constexpr int NC  = (VAR == 2) ? 1 : ((VAR == 3) ? 32 : 16);
    constexpr int LDA = (VAR == 2) ? DK : ((VAR == 3) ? SS : DM);
    constexpr int ASZ = 128 * 128;           // bytes per A plane (128 rows x 128B)
    constexpr int BSZ = NT * 128;            // bytes per B plane

    extern __shared__ char smem[];
    const uint32_t sb = smem_u32(smem);
    const int tid = threadIdx.x, wid = tid >> 5, lid = tid & 31;
    const int warp_m = wid >> 2;             // 0..1  -> 64 rows
    const int warp_n = wid & 3;              // 0..3  -> NT/4 cols

    const int m0   = blockIdx.y * 128;
    const int col0 = blockIdx.x * NT;
    const int z    = blockIdx.z;

    const float* Afp = Af;
    const __nv_bfloat16 *Ahp = Ah, *Alp = Al, *Bhp = Bh, *Blp = Bl;
    if (VAR == 2) {
        Ahp += (size_t)z * SS * DK; Alp += (size_t)z * SS * DK;
        Bhp += (size_t)z * SS * DK; Blp += (size_t)z * SS * DK;
    }
    if (VAR == 3) {
        Afp += (size_t)z * SS * SS;
        Bhp += (size_t)z * SS * DK; Blp += (size_t)z * SS * DK;
    }

    float acc[4][NF][4];
    #pragma unroll
    for (int i = 0; i < 4; i++)
        #pragma unroll
        for (int j = 0; j < NF; j++)
            #pragma unroll
            for (int t = 0; t < 4; t++) acc[i][j][t] = 0.0f;

    // per-lane ldmatrix offsets (bytes within tile, pre-swizzle)
    const uint32_t a_base = (uint32_t)((warp_m * 64 + (lid & 15)) * 128 + ((lid >> 4) << 4));
    const uint32_t b_base = (uint32_t)((warp_n * (NT/4) + ((lid >> 4) << 3) + (lid & 7)) * 128
                                       + (((lid >> 3) & 1) << 4));

    for (int ci = 0; ci < NC; ci++) {
        const int kb = ci * 64;

        // ---------------- stage A (128 x 64 -> hi/lo planes) ----------------
        if (VAR == 0 || VAR == 3) {
            const float* src = Afp + (size_t)m0 * LDA + kb;
            #pragma unroll
            for (int it = 0; it < 8; it++) {
                int v = tid + it * 256;
                int row = v >> 4, c4 = (v & 15) << 2;
                float4 x = *(const float4*)(src + (size_t)row * LDA + c4);
                __nv_bfloat16 h0,h1,h2,h3,l0,l1,l2,l3;
                split1(x.x,h0,l0); split1(x.y,h1,l1); split1(x.z,h2,l2); split1(x.w,h3,l3);
                int so = SWZ(row * 128 + (c4 << 1));
                *(uint2*)(smem + so)       = make_uint2(pk2(h0,h1), pk2(h2,h3));
                *(uint2*)(smem + ASZ + so) = make_uint2(pk2(l0,l1), pk2(l2,l3));
            }
        } else {
            const __nv_bfloat16* sh = Ahp + (size_t)m0 * LDA + kb;
            const __nv_bfloat16* sl = Alp + (size_t)m0 * LDA + kb;
            #pragma unroll
            for (int it = 0; it < 8; it++) {
                int v = tid + it * 256;
                int row = v >> 4, c4 = (v & 15) << 2;
                uint2 hv = *(const uint2*)(sh + (size_t)row * LDA + c4);
                uint2 lv = *(const uint2*)(sl + (size_t)row * LDA + c4);
                int so = SWZ(row * 128 + (c4 << 1));
                *(uint2*)(smem + so) = hv;
                *(uint2*)(smem + ASZ + so) = lv;
            }
        }
        // ---------------- stage B (NT x 64 -> hi/lo planes) ----------------
        if (VAR == 0 || VAR == 1) {
            const float* src = Bf + (size_t)col0 * DM + kb;
            #pragma unroll
            for (int it = 0; it < 8; it++) {
                int v = tid + it * 256;
                int row = v >> 4, c4 = (v & 15) << 2;
                float4 x = *(const float4*)(src + (size_t)row * DM + c4);
                __nv_bfloat16 h0,h1,h2,h3,l0,l1,l2,l3;
                split1(x.x,h0,l0); split1(x.y,h1,l1); split1(x.z,h2,l2); split1(x.w,h3,l3);
                int so = SWZ(row * 128 + (c4 << 1));
                *(uint2*)(smem + 2*ASZ + so)       = make_uint2(pk2(h0,h1), pk2(h2,h3));
                *(uint2*)(smem + 2*ASZ + BSZ + so) = make_uint2(pk2(l0,l1), pk2(l2,l3));
            }
        } else if (VAR == 2) {
            const __nv_bfloat16* sh = Bhp + (size_t)col0 * DK;
            const __nv_bfloat16* sl = Blp + (size_t)col0 * DK;
            #pragma unroll
            for (int it = 0; it < 8; it++) {
                int v = tid + it * 256;
                int row = v >> 4, c4 = (v & 15) << 2;
                uint2 hv = *(const uint2*)(sh + (size_t)row * DK + c4);
                uint2 lv = *(const uint2*)(sl + (size_t)row * DK + c4);
                int so = SWZ(row * 128 + (c4 << 1));
                *(uint2*)(smem + 2*ASZ + so) = hv;
                *(uint2*)(smem + 2*ASZ + BSZ + so) = lv;
            }
        } else {  // VAR 3: transpose V[t,d] -> smem[d][t]
            #pragma unroll
            for (int it = 0; it < 4; it++) {
                int v = tid + it * 256;
                int tt = v >> 4, d0 = (v & 15) << 2;
                uint2 hv = *(const uint2*)(Bhp + (size_t)(kb + tt) * DK + d0);
                uint2 lv = *(const uint2*)(Blp + (size_t)(kb + tt) * DK + d0);
                ushort hs[4], ls[4];
                hs[0] = hv.x & 0xFFFF; hs[1] = hv.x >> 16; hs[2] = hv.y & 0xFFFF; hs[3] = hv.y >> 16;
                ls[0] = lv.x & 0xFFFF; ls[1] = lv.x >> 16; ls[2] = lv.y & 0xFFFF; ls[3] = lv.y >> 16;
                #pragma unroll
                for (int j = 0; j < 4; j++) {
                    int so = SWZ((d0 + j) * 128 + (tt << 1));
                    *(ushort*)(smem + 2*ASZ + so)       = hs[j];
                    *(ushort*)(smem + 2*ASZ + BSZ + so) = ls[j];
                }
            }
        }
        __syncthreads();

        // ---------------- compute: 4 ksteps of 16 ----------------
        #pragma unroll
        for (int ks = 0; ks < 4; ks++) {
            uint32_t bh[2*NF], bl[2*NF];
            #pragma unroll
            for (int ng = 0; ng < NF/2; ng++) {
                uint32_t ofs = b_base + (uint32_t)(ng * 16 * 128 + ks * 32);
                ldm_x4(sb + 2*ASZ +       SWZ(ofs), bh[4*ng], bh[4*ng+1], bh[4*ng+2], bh[4*ng+3]);
                ldm_x4(sb + 2*ASZ + BSZ + SWZ(ofs), bl[4*ng], bl[4*ng+1], bl[4*ng+2], bl[4*ng+3]);
            }
            #pragma unroll
            for (int mf = 0; mf < 4; mf++) {
                uint32_t ofs = a_base + (uint32_t)(mf * 16 * 128 + ks * 32);
                uint32_t ah0,ah1,ah2,ah3, al0,al1,al2,al3;
                ldm_x4(sb +       SWZ(ofs), ah0, ah1, ah2, ah3);
                ldm_x4(sb + ASZ + SWZ(ofs), al0, al1, al2, al3);
                #pragma unroll
                for (int nf = 0; nf < NF; nf++) {
                    float* c = acc[mf][nf];
                    mma_bf16(c, ah0, ah1, ah2, ah3, bh[2*nf], bh[2*nf+1]);
                    mma_bf16(c, ah0, ah1, ah2, ah3, bl[2*nf], bl[2*nf+1]);
                    mma_bf16(c, al0, al1, al2, al3, bh[2*nf], bh[2*nf+1]);
                }
            }
        }
        __syncthreads();
    }

    // ---------------- epilogue (regs -> global) ----------------
    #pragma unroll
    for (int mf = 0; mf < 4; mf++) {
        #pragma unroll
        for (int nf = 0; nf < NF; nf++) {
            const float* c = acc[mf][nf];
            int r  = m0 + warp_m * 64 + mf * 16 + (lid >> 2);
            int cc = col0 + warp_n * (NT/4) + nf * 8 + (lid & 3) * 2;
            #pragma unroll
            for (int half = 0; half < 2; half++) {
                int gr = r + half * 8;
                float v0 = c[half * 2 + 0], v1 = c[half * 2 + 1];
                if (VAR == 0) {
                    v0 += __ldg(bias + cc); v1 += __ldg(bias + cc + 1);
                    int b = gr >> 11, s = gr & (SS - 1), h = cc >> 6, d = cc & (DK - 1);
                    size_t idx = ((((size_t)b * HH + h) * SS) + s) * DK + d;
                    __nv_bfloat16 hh, ll;
                    split1(v0, hh, ll); Ch[idx] = hh;     Cl[idx] = ll;
                    split1(v1, hh, ll); Ch[idx + 1] = hh; Cl[idx + 1] = ll;
                } else if (VAR == 1) {
                    v0 += __ldg(bias + cc); v1 += __ldg(bias + cc + 1);
                    size_t idx = (size_t)gr * DM + cc;
                    Cf[idx] = v0; Cf[idx + 1] = v1;
                } else if (VAR == 2) {
                    size_t idx = (size_t)z * SS * SS + (size_t)gr * SS + cc;
                    Cf[idx] = v0 * 0.125f; Cf[idx + 1] = v1 * 0.125f;
                } else {
                    int b = z >> 4, h = z & (HH - 1);
                    size_t idx = ((size_t)(b * SS + gr)) * DM + h * DK + cc;
                    __nv_bfloat16 hh, ll;
                    split1(v0, hh, ll); Ch[idx] = hh;     Cl[idx] = ll;
                    split1(v1, hh, ll); Ch[idx + 1] = hh; Cl[idx + 1] = ll;
                }
            }
        }
    }
}

// ---------------------------------------------------------------------------
// Row softmax in place, fp32. One block (256 threads) per row of 2048.
// ---------------------------------------------------------------------------
__global__ void __launch_bounds__(256) softmax_kernel(float* __restrict__ P)
{
    __shared__ float red[256];
    size_t row = blockIdx.x;
    float* p = P + row * SS;
    int tid = threadIdx.x;

    float v[8];
    float m = -1e30f;
    #pragma unroll
    for (int i = 0; i < 8; i++) { v[i] = p[tid + i * 256]; m = fmaxf(m, v[i]); }
    red[tid] = m;
    __syncthreads();
    for (int s = 128; s > 0; s >>= 1) {
        if (tid < s) red[tid] = fmaxf(red[tid], red[tid + s]);
        __syncthreads();
    }
    m = red[0];
    __syncthreads();

    float sum = 0.0f;
    #pragma unroll
    for (int i = 0; i < 8; i++) { v[i] = __expf(v[i] - m); sum += v[i]; }
    red[tid] = sum;
    __syncthreads();
    for (int s = 128; s > 0; s >>= 1) {
        if (tid < s) red[tid] += red[tid + s];
        __syncthreads();
    }
    float inv = 1.0f / red[0];

    #pragma unroll
    for (int i = 0; i < 8; i++) p[tid + i * 256] = v[i] * inv;
}

// ---------------------------------------------------------------------------
extern "C" void kernel_launch(void* const* d_in, const int* in_sizes, int n_in,
                              void* d_out, int out_size)
{
    const float* q   = (const float*)d_in[0];
    const float* k   = (const float*)d_in[1];
    const float* v   = (const float*)d_in[2];
    const float* w_q = (const float*)d_in[3];
    const float* b_q = (const float*)d_in[4];
    const float* w_k = (const float*)d_in[5];
    const float* b_k = (const float*)d_in[6];
    const float* w_v = (const float*)d_in[7];
    const float* b_v = (const float*)d_in[8];
    const float* w_o = (const float*)d_in[9];
    const float* b_o = (const float*)d_in[10];
    float* out = (float*)d_out;

    __nv_bfloat16 *qh_h,*qh_l,*kh_h,*kh_l,*vh_h,*vh_l,*cx_h,*cx_l;
    cudaGetSymbolAddress((void**)&qh_h, g_qh_h); cudaGetSymbolAddress((void**)&qh_l, g_qh_l);
    cudaGetSymbolAddress((void**)&kh_h, g_kh_h); cudaGetSymbolAddress((void**)&kh_l, g_kh_l);
    cudaGetSymbolAddress((void**)&vh_h, g_vh_h); cudaGetSymbolAddress((void**)&vh_l, g_vh_l);
    cudaGetSymbolAddress((void**)&cx_h, g_cx_h); cudaGetSymbolAddress((void**)&cx_l, g_cx_l);

    float* attn;
    if ((size_t)out_size >= OUT_ELEMS + ATTN_ELEMS) {
        attn = out + OUT_ELEMS;
    } else {
        cudaGetSymbolAddress((void**)&attn, g_attn);
    }

    const int SM01 = 2*16384 + 2*16384;      // 64 KB (proj / out / scores)
    const int SM3  = 2*16384 + 2*8192;       // 48 KB (AV)
    cudaFuncSetAttribute(mma_gemm<0>, cudaFuncAttributeMaxDynamicSharedMemorySize, SM01);
    cudaFuncSetAttribute(mma_gemm<1>, cudaFuncAttributeMaxDynamicSharedMemorySize, SM01);
    cudaFuncSetAttribute(mma_gemm<2>, cudaFuncAttributeMaxDynamicSharedMemorySize, SM01);
    cudaFuncSetAttribute(mma_gemm<3>, cudaFuncAttributeMaxDynamicSharedMemorySize, SM3);

    dim3 gproj(DM / 128, MROWS / 128);               // (8, 64)

    mma_gemm<0><<<gproj, 256, SM01>>>(q, nullptr, nullptr, w_q, nullptr, nullptr,
                                      b_q, nullptr, qh_h, qh_l);
    mma_gemm<0><<<gproj, 256, SM01>>>(k, nullptr, nullptr, w_k, nullptr, nullptr,
                                      b_k, nullptr, kh_h, kh_l);
    mma_gemm<0><<<gproj, 256, SM01>>>(v, nullptr, nullptr, w_v, nullptr, nullptr,
                                      b_v, nullptr, vh_h, vh_l);

    mma_gemm<2><<<dim3(SS/128, SS/128, BB*HH), 256, SM01>>>(
        nullptr, qh_h, qh_l, nullptr, kh_h, kh_l, nullptr, attn, nullptr, nullptr);

    softmax_kernel<<<dim3(BB*HH*SS), 256>>>(attn);

    mma_gemm<3><<<dim3(1, SS/128, BB*HH), 256, SM3>>>(
        attn, nullptr, nullptr, nullptr, vh_h, vh_l, nullptr, nullptr, cx_h, cx_l);

    mma_gemm<1><<<gproj, 256, SM01>>>(nullptr, cx_h, cx_l, w_o, nullptr, nullptr,
                                      b_o, out, nullptr, nullptr);
}

// round 4
// speedup vs baseline: 1.7977x; 1.1475x over previous
#include <cuda_runtime.h>
#include <cuda_bf16.h>
#include <cstdint>

// ---------------- problem constants ----------------
#define BB 4
#define SS 2048
#define HH 16
#define DK 64
#define DM 1024
#define MROWS (BB*SS)                        // 8192
#define OUT_ELEMS ((size_t)MROWS*DM)         // 8,388,608
#define ATTN_ELEMS ((size_t)BB*HH*SS*SS)     // 268,435,456

// ---------------- device-global scratch (no allocations allowed) -----------
__device__ __nv_bfloat16 g_qh_h[(size_t)MROWS*DM], g_qh_l[(size_t)MROWS*DM];
__device__ __nv_bfloat16 g_kh_h[(size_t)MROWS*DM], g_kh_l[(size_t)MROWS*DM];
__device__ __nv_bfloat16 g_vh_h[(size_t)MROWS*DM], g_vh_l[(size_t)MROWS*DM];
__device__ __nv_bfloat16 g_cx_h[(size_t)MROWS*DM], g_cx_l[(size_t)MROWS*DM];
__device__ float g_attn[ATTN_ELEMS];   // used only if attn not part of d_out
__device__ float g_rowsum[(size_t)BB*HH*SS];   // per-row exp sums

// ---------------- helpers ----------------
#define SWZ(o) ((o) ^ (((o) >> 3) & 0x70))

__device__ __forceinline__ uint32_t smem_u32(const void* p) {
    uint32_t a;
    asm("{ .reg .u64 t; cvta.to.shared.u64 t, %1; cvt.u32.u64 %0, t; }"
        : "=r"(a) : "l"(p));
    return a;
}
__device__ __forceinline__ void ldm_x4(uint32_t addr, uint32_t& r0, uint32_t& r1,
                                       uint32_t& r2, uint32_t& r3) {
    asm volatile("ldmatrix.sync.aligned.m8n8.x4.shared.b16 {%0,%1,%2,%3}, [%4];"
                 : "=r"(r0), "=r"(r1), "=r"(r2), "=r"(r3) : "r"(addr));
}
__device__ __forceinline__ void mma_bf16(float* c, uint32_t a0, uint32_t a1,
                                         uint32_t a2, uint32_t a3,
                                         uint32_t b0, uint32_t b1) {
    asm volatile("mma.sync.aligned.m16n8k16.row.col.f32.bf16.bf16.f32 "
                 "{%0,%1,%2,%3}, {%4,%5,%6,%7}, {%8,%9}, {%0,%1,%2,%3};"
                 : "+f"(c[0]), "+f"(c[1]), "+f"(c[2]), "+f"(c[3])
                 : "r"(a0), "r"(a1), "r"(a2), "r"(a3), "r"(b0), "r"(b1));
}
__device__ __forceinline__ uint32_t pk2(__nv_bfloat16 a, __nv_bfloat16 b) {
    return ((uint32_t)__bfloat16_as_ushort(b) << 16) | (uint32_t)__bfloat16_as_ushort(a);
}
__device__ __forceinline__ void split1(float x, __nv_bfloat16& h, __nv_bfloat16& l) {
    h = __float2bfloat16(x);
    l = __float2bfloat16(x - __bfloat162float(h));
}
// split 4 floats -> packed hi uint2 / lo uint2
__device__ __forceinline__ void split4(float4 x, uint2& hi, uint2& lo) {
    __nv_bfloat16 h0,h1,h2,h3,l0,l1,l2,l3;
    split1(x.x,h0,l0); split1(x.y,h1,l1); split1(x.z,h2,l2); split1(x.w,h3,l3);
    hi = make_uint2(pk2(h0,h1), pk2(h2,h3));
    lo = make_uint2(pk2(l0,l1), pk2(l2,l3));
}

__global__ void zero_rowsum_kernel(float* rs) {
    rs[(size_t)blockIdx.x * 256 + threadIdx.x] = 0.0f;
}

// ---------------------------------------------------------------------------
// Unified mma.sync bf16x3 GEMM.
// VAR 0 = projection : C = A(fp32) @ W(fp32)^T + bias -> hi/lo head planes
// VAR 1 = out proj   : C = A(planes) @ W(fp32)^T + bias -> fp32 out
// VAR 2 = scores+exp : per bh: E = exp(Q@K^T/8) -> fp32; rowsum atomics
// VAR 3 = AV+norm    : per bh: (E*inv) @ V -> ctx planes; optional attn writeback
// Block tile: 128 x NT, K chunk 64. 8 warps (2x4), warp tile 64 x NT/4.
// ---------------------------------------------------------------------------
template<int VAR>
__global__ void __launch_bounds__(256) mma_gemm(
    const float* __restrict__ Af,
    const __nv_bfloat16* __restrict__ Ah, const __nv_bfloat16* __restrict__ Al,
    const float* __restrict__ Bf,
    const __nv_bfloat16* __restrict__ Bh, const __nv_bfloat16* __restrict__ Bl,
    const float* __restrict__ bias,
    float* __restrict__ Cf,
    __nv_bfloat16* __restrict__ Ch, __nv_bfloat16* __restrict__ Cl,
    float* __restrict__ rowsum, int write_attn)
{
    constexpr int NT  = (VAR == 3) ? 64 : 128;
    constexpr int NF  = NT / 32;             // n-frag pairs per warp
    constexpr int NC  = (VAR == 2) ? 1 : ((VAR == 3) ? 32 : 16);
    constexpr int LDA = (VAR == 2) ? DK : ((VAR == 3) ? SS : DM);
    constexpr int ASZ = 128 * 128;           // bytes per A plane
    constexpr int BSZ = NT * 128;            // bytes per B plane
    constexpr int INV_OFF = 2*ASZ + 2*BSZ;   // VAR3 inv-rowsum region

    extern __shared__ char smem[];
    const uint32_t sb = smem_u32(smem);
    const int tid = threadIdx.x, wid = tid >> 5, lid = tid & 31;
    const int warp_m = wid >> 2;             // 0..1  -> 64 rows
    const int warp_n = wid & 3;              // 0..3  -> NT/4 cols

    const int m0   = blockIdx.y * 128;
    const int col0 = blockIdx.x * NT;
    const int z    = blockIdx.z;

    const float* Afp = Af;
    const __nv_bfloat16 *Ahp = Ah, *Alp = Al, *Bhp = Bh, *Blp = Bl;
    if (VAR == 2) {
        Ahp += (size_t)z * SS * DK; Alp += (size_t)z * SS * DK;
        Bhp += (size_t)z * SS * DK; Blp += (size_t)z * SS * DK;
    }
    if (VAR == 3) {
        Afp += (size_t)z * SS * SS;
        Bhp += (size_t)z * SS * DK; Blp += (size_t)z * SS * DK;
    }

    if (VAR == 3) {
        if (tid < 128) {
            float rs = rowsum[(size_t)z * SS + m0 + tid];
            *(float*)(smem + INV_OFF + tid * 4) = 1.0f / rs;
        }
        __syncthreads();
    }

    float acc[4][NF][4];
    #pragma unroll
    for (int i = 0; i < 4; i++)
        #pragma unroll
        for (int j = 0; j < NF; j++)
            #pragma unroll
            for (int t = 0; t < 4; t++) acc[i][j][t] = 0.0f;

    const uint32_t a_base = (uint32_t)((warp_m * 64 + (lid & 15)) * 128 + ((lid >> 4) << 4));
    const uint32_t b_base = (uint32_t)((warp_n * (NT/4) + ((lid >> 4) << 3) + (lid & 7)) * 128
                                       + (((lid >> 3) & 1) << 4));

    for (int ci = 0; ci < NC; ci++) {
        const int kb = ci * 64;

        // ---------------- stage A (128 x 64 -> hi/lo planes) ----------------
        if (VAR == 0) {
            const float* src = Afp + (size_t)m0 * LDA + kb;
            #pragma unroll
            for (int it = 0; it < 4; it++) {
                int v = tid + it * 256;          // 1024: row=v>>3, c8=(v&7)*8
                int row = v >> 3, c8 = (v & 7) << 3;
                float4 x0 = *(const float4*)(src + (size_t)row * LDA + c8);
                float4 x1 = *(const float4*)(src + (size_t)row * LDA + c8 + 4);
                uint2 h0, l0, h1, l1;
                split4(x0, h0, l0); split4(x1, h1, l1);
                int so = SWZ(row * 128 + (c8 << 1));
                *(uint4*)(smem + so)       = make_uint4(h0.x, h0.y, h1.x, h1.y);
                *(uint4*)(smem + ASZ + so) = make_uint4(l0.x, l0.y, l1.x, l1.y);
            }
        } else if (VAR == 3) {
            const float* src = Afp + (size_t)m0 * LDA + kb;
            float* wb = Cf + (size_t)z * SS * SS + (size_t)m0 * SS + kb;
            #pragma unroll
            for (int it = 0; it < 4; it++) {
                int v = tid + it * 256;
                int row = v >> 3, c8 = (v & 7) << 3;
                float inv = *(const float*)(smem + INV_OFF + row * 4);
                float4 x0 = *(const float4*)(src + (size_t)row * LDA + c8);
                float4 x1 = *(const float4*)(src + (size_t)row * LDA + c8 + 4);
                x0.x *= inv; x0.y *= inv; x0.z *= inv; x0.w *= inv;
                x1.x *= inv; x1.y *= inv; x1.z *= inv; x1.w *= inv;
                if (write_attn) {
                    *(float4*)(wb + (size_t)row * SS + c8)     = x0;
                    *(float4*)(wb + (size_t)row * SS + c8 + 4) = x1;
                }
                uint2 h0, l0, h1, l1;
                split4(x0, h0, l0); split4(x1, h1, l1);
                int so = SWZ(row * 128 + (c8 << 1));
                *(uint4*)(smem + so)       = make_uint4(h0.x, h0.y, h1.x, h1.y);
                *(uint4*)(smem + ASZ + so) = make_uint4(l0.x, l0.y, l1.x, l1.y);
            }
        } else {
            const __nv_bfloat16* sh = Ahp + (size_t)m0 * LDA + kb;
            const __nv_bfloat16* sl = Alp + (size_t)m0 * LDA + kb;
            #pragma unroll
            for (int it = 0; it < 4; it++) {
                int v = tid + it * 256;
                int row = v >> 3, c8 = (v & 7) << 3;
                uint4 hv = *(const uint4*)(sh + (size_t)row * LDA + c8);
                uint4 lv = *(const uint4*)(sl + (size_t)row * LDA + c8);
                int so = SWZ(row * 128 + (c8 << 1));
                *(uint4*)(smem + so) = hv;
                *(uint4*)(smem + ASZ + so) = lv;
            }
        }
        // ---------------- stage B (NT x 64 -> hi/lo planes) ----------------
        if (VAR == 0 || VAR == 1) {
            const float* src = Bf + (size_t)col0 * DM + kb;
            #pragma unroll
            for (int it = 0; it < 4; it++) {
                int v = tid + it * 256;
                int row = v >> 3, c8 = (v & 7) << 3;
                float4 x0 = *(const float4*)(src + (size_t)row * DM + c8);
                float4 x1 = *(const float4*)(src + (size_t)row * DM + c8 + 4);
                uint2 h0, l0, h1, l1;
                split4(x0, h0, l0); split4(x1, h1, l1);
                int so = SWZ(row * 128 + (c8 << 1));
                *(uint4*)(smem + 2*ASZ + so)       = make_uint4(h0.x, h0.y, h1.x, h1.y);
                *(uint4*)(smem + 2*ASZ + BSZ + so) = make_uint4(l0.x, l0.y, l1.x, l1.y);
            }
        } else if (VAR == 2) {
            const __nv_bfloat16* sh = Bhp + (size_t)col0 * DK;
            const __nv_bfloat16* sl = Blp + (size_t)col0 * DK;
            #pragma unroll
            for (int it = 0; it < 4; it++) {
                int v = tid + it * 256;
                int row = v >> 3, c8 = (v & 7) << 3;
                uint4 hv = *(const uint4*)(sh + (size_t)row * DK + c8);
                uint4 lv = *(const uint4*)(sl + (size_t)row * DK + c8);
                int so = SWZ(row * 128 + (c8 << 1));
                *(uint4*)(smem + 2*ASZ + so) = hv;
                *(uint4*)(smem + 2*ASZ + BSZ + so) = lv;
            }
        } else {  // VAR 3: transpose V[t,d] -> smem[d][t]
            #pragma unroll
            for (int it = 0; it < 4; it++) {
                int v = tid + it * 256;
                int tt = v >> 4, d0 = (v & 15) << 2;
                uint2 hv = *(const uint2*)(Bhp + (size_t)(kb + tt) * DK + d0);
                uint2 lv = *(const uint2*)(Blp + (size_t)(kb + tt) * DK + d0);
                ushort hs[4], ls[4];
                hs[0] = hv.x & 0xFFFF; hs[1] = hv.x >> 16; hs[2] = hv.y & 0xFFFF; hs[3] = hv.y >> 16;
                ls[0] = lv.x & 0xFFFF; ls[1] = lv.x >> 16; ls[2] = lv.y & 0xFFFF; ls[3] = lv.y >> 16;
                #pragma unroll
                for (int j = 0; j < 4; j++) {
                    int so = SWZ((d0 + j) * 128 + (tt << 1));
                    *(ushort*)(smem + 2*ASZ + so)       = hs[j];
                    *(ushort*)(smem + 2*ASZ + BSZ + so) = ls[j];
                }
            }
        }
        __syncthreads();

        // ---------------- compute: 4 ksteps of 16 ----------------
        #pragma unroll
        for (int ks = 0; ks < 4; ks++) {
            uint32_t bhf[2*NF], blf[2*NF];
            #pragma unroll
            for (int ng = 0; ng < NF/2; ng++) {
                uint32_t ofs = b_base + (uint32_t)(ng * 16 * 128 + ks * 32);
                ldm_x4(sb + 2*ASZ +       SWZ(ofs), bhf[4*ng], bhf[4*ng+1], bhf[4*ng+2], bhf[4*ng+3]);
                ldm_x4(sb + 2*ASZ + BSZ + SWZ(ofs), blf[4*ng], blf[4*ng+1], blf[4*ng+2], blf[4*ng+3]);
            }
            #pragma unroll
            for (int mf = 0; mf < 4; mf++) {
                uint32_t ofs = a_base + (uint32_t)(mf * 16 * 128 + ks * 32);
                uint32_t ah0,ah1,ah2,ah3, al0,al1,al2,al3;
                ldm_x4(sb +       SWZ(ofs), ah0, ah1, ah2, ah3);
                ldm_x4(sb + ASZ + SWZ(ofs), al0, al1, al2, al3);
                #pragma unroll
                for (int nf = 0; nf < NF; nf++) {
                    float* c = acc[mf][nf];
                    mma_bf16(c, ah0, ah1, ah2, ah3, bhf[2*nf], bhf[2*nf+1]);
                    mma_bf16(c, ah0, ah1, ah2, ah3, blf[2*nf], blf[2*nf+1]);
                    mma_bf16(c, al0, al1, al2, al3, bhf[2*nf], bhf[2*nf+1]);
                }
            }
        }
        __syncthreads();
    }

    // ---------------- epilogue ----------------
    if (VAR == 2) {
        // E = exp(score/8), store, accumulate row sums
        #pragma unroll
        for (int mf = 0; mf < 4; mf++) {
            #pragma unroll
            for (int half = 0; half < 2; half++) {
                int gr = m0 + warp_m * 64 + mf * 16 + (lid >> 2) + half * 8;
                float rs = 0.0f;
                #pragma unroll
                for (int nf = 0; nf < NF; nf++) {
                    const float* c = acc[mf][nf];
                    int cc = col0 + warp_n * (NT/4) + nf * 8 + (lid & 3) * 2;
                    float e0 = __expf(c[half*2 + 0] * 0.125f);
                    float e1 = __expf(c[half*2 + 1] * 0.125f);
                    size_t idx = (size_t)z * SS * SS + (size_t)gr * SS + cc;
                    Cf[idx] = e0; Cf[idx + 1] = e1;
                    rs += e0 + e1;
                }
                rs += __shfl_xor_sync(0xffffffffu, rs, 1);
                rs += __shfl_xor_sync(0xffffffffu, rs, 2);
                if ((lid & 3) == 0) atomicAdd(&rowsum[(size_t)z * SS + gr], rs);
            }
        }
        return;
    }

    #pragma unroll
    for (int mf = 0; mf < 4; mf++) {
        #pragma unroll
        for (int nf = 0; nf < NF; nf++) {
            const float* c = acc[mf][nf];
            int r  = m0 + warp_m * 64 + mf * 16 + (lid >> 2);
            int cc = col0 + warp_n * (NT/4) + nf * 8 + (lid & 3) * 2;
            #pragma unroll
            for (int half = 0; half < 2; half++) {
                int gr = r + half * 8;
                float v0 = c[half * 2 + 0], v1 = c[half * 2 + 1];
                if (VAR == 0) {
                    v0 += __ldg(bias + cc); v1 += __ldg(bias + cc + 1);
                    int b = gr >> 11, s = gr & (SS - 1), h = cc >> 6, d = cc & (DK - 1);
                    size_t idx = ((((size_t)b * HH + h) * SS) + s) * DK + d;
                    __nv_bfloat16 hh, ll;
                    split1(v0, hh, ll); Ch[idx] = hh;     Cl[idx] = ll;
                    split1(v1, hh, ll); Ch[idx + 1] = hh; Cl[idx + 1] = ll;
                } else if (VAR == 1) {
                    v0 += __ldg(bias + cc); v1 += __ldg(bias + cc + 1);
                    size_t idx = (size_t)gr * DM + cc;
                    Cf[idx] = v0; Cf[idx + 1] = v1;
                } else {  // VAR 3
                    int b = z >> 4, h = z & (HH - 1);
                    size_t idx = ((size_t)(b * SS + gr)) * DM + h * DK + cc;
                    __nv_bfloat16 hh, ll;
                    split1(v0, hh, ll); Ch[idx] = hh;     Cl[idx] = ll;
                    split1(v1, hh, ll); Ch[idx + 1] = hh; Cl[idx + 1] = ll;
                }
            }
        }
    }
}

// ---------------------------------------------------------------------------
extern "C" void kernel_launch(void* const* d_in, const int* in_sizes, int n_in,
                              void* d_out, int out_size)
{
    const float* q   = (const float*)d_in[0];
    const float* k   = (const float*)d_in[1];
    const float* v   = (const float*)d_in[2];
    const float* w_q = (const float*)d_in[3];
    const float* b_q = (const float*)d_in[4];
    const float* w_k = (const float*)d_in[5];
    const float* b_k = (const float*)d_in[6];
    const float* w_v = (const float*)d_in[7];
    const float* b_v = (const float*)d_in[8];
    const float* w_o = (const float*)d_in[9];
    const float* b_o = (const float*)d_in[10];
    float* out = (float*)d_out;

    __nv_bfloat16 *qh_h,*qh_l,*kh_h,*kh_l,*vh_h,*vh_l,*cx_h,*cx_l;
    cudaGetSymbolAddress((void**)&qh_h, g_qh_h); cudaGetSymbolAddress((void**)&qh_l, g_qh_l);
    cudaGetSymbolAddress((void**)&kh_h, g_kh_h); cudaGetSymbolAddress((void**)&kh_l, g_kh_l);
    cudaGetSymbolAddress((void**)&vh_h, g_vh_h); cudaGetSymbolAddress((void**)&vh_l, g_vh_l);
    cudaGetSymbolAddress((void**)&cx_h, g_cx_h); cudaGetSymbolAddress((void**)&cx_l, g_cx_l);

    float* rowsum;
    cudaGetSymbolAddress((void**)&rowsum, g_rowsum);

    float* attn;
    int write_attn;
    if ((size_t)out_size >= OUT_ELEMS + ATTN_ELEMS) {
        attn = out + OUT_ELEMS;
        write_attn = 1;
    } else {
        cudaGetSymbolAddress((void**)&attn, g_attn);
        write_attn = 0;
    }

    const int SM01 = 2*16384 + 2*16384;            // 64 KB (proj / out / scores)
    const int SM3  = 2*16384 + 2*8192 + 512;       // 48.5 KB (AV)
    cudaFuncSetAttribute(mma_gemm<0>, cudaFuncAttributeMaxDynamicSharedMemorySize, SM01);
    cudaFuncSetAttribute(mma_gemm<1>, cudaFuncAttributeMaxDynamicSharedMemorySize, SM01);
    cudaFuncSetAttribute(mma_gemm<2>, cudaFuncAttributeMaxDynamicSharedMemorySize, SM01);
    cudaFuncSetAttribute(mma_gemm<3>, cudaFuncAttributeMaxDynamicSharedMemorySize, SM3);

    zero_rowsum_kernel<<<dim3(BB*HH*SS/256), 256>>>(rowsum);

    dim3 gproj(DM / 128, MROWS / 128);             // (8, 64)

    mma_gemm<0><<<gproj, 256, SM01>>>(q, nullptr, nullptr, w_q, nullptr, nullptr,
                                      b_q, nullptr, qh_h, qh_l, nullptr, 0);
    mma_gemm<0><<<gproj, 256, SM01>>>(k, nullptr, nullptr, w_k, nullptr, nullptr,
                                      b_k, nullptr, kh_h, kh_l, nullptr, 0);
    mma_gemm<0><<<gproj, 256, SM01>>>(v, nullptr, nullptr, w_v, nullptr, nullptr,
                                      b_v, nullptr, vh_h, vh_l, nullptr, 0);

    mma_gemm<2><<<dim3(SS/128, SS/128, BB*HH), 256, SM01>>>(
        nullptr, qh_h, qh_l, nullptr, kh_h, kh_l, nullptr, attn, nullptr, nullptr,
        rowsum, 0);

    mma_gemm<3><<<dim3(1, SS/128, BB*HH), 256, SM3>>>(
        attn, nullptr, nullptr, nullptr, vh_h, vh_l, nullptr, attn, cx_h, cx_l,
        rowsum, write_attn);

    mma_gemm<1><<<gproj, 256, SM01>>>(nullptr, cx_h, cx_l, w_o, nullptr, nullptr,
                                      b_o, out, nullptr, nullptr, nullptr, 0);
}

// round 5
// speedup vs baseline: 2.9644x; 1.6490x over previous
#include <cuda_runtime.h>
#include <cuda_fp16.h>
#include <cstdint>

// ---------------- problem constants ----------------
#define BB 4
#define SS 2048
#define HH 16
#define DK 64
#define DM 1024
#define MROWS (BB*SS)                        // 8192
#define OUT_ELEMS ((size_t)MROWS*DM)         // 8,388,608
#define ATTN_ELEMS ((size_t)BB*HH*SS*SS)     // 268,435,456

// ---------------- device-global scratch ----------------
__device__ __half g_in_h[3][(size_t)MROWS*DM], g_in_l[3][(size_t)MROWS*DM];
__device__ __half g_w_h[4][(size_t)DM*DM];
__device__ __half g_qh_h[(size_t)MROWS*DM], g_qh_l[(size_t)MROWS*DM];
__device__ __half g_kh_h[(size_t)MROWS*DM];
__device__ __half g_vh_h[(size_t)MROWS*DM];
__device__ __half g_cx_h[(size_t)MROWS*DM], g_cx_l[(size_t)MROWS*DM];
__device__ float g_attn[ATTN_ELEMS];
__device__ float g_rowsum[(size_t)BB*HH*SS];

// ---------------- helpers ----------------
#define SWZ(o) ((o) ^ (((o) >> 3) & 0x70))

__device__ __forceinline__ uint32_t smem_u32(const void* p) {
    uint32_t a;
    asm("{ .reg .u64 t; cvta.to.shared.u64 t, %1; cvt.u32.u64 %0, t; }"
        : "=r"(a) : "l"(p));
    return a;
}
__device__ __forceinline__ void cp16(uint32_t dst, const void* src) {
    asm volatile("cp.async.cg.shared.global [%0], [%1], 16;" :: "r"(dst), "l"(src) : "memory");
}
__device__ __forceinline__ void cp_commit() { asm volatile("cp.async.commit_group;" ::: "memory"); }
__device__ __forceinline__ void cp_wait0()  { asm volatile("cp.async.wait_group 0;" ::: "memory"); }
__device__ __forceinline__ void cp_wait1()  { asm volatile("cp.async.wait_group 1;" ::: "memory"); }

__device__ __forceinline__ void ldm_x4(uint32_t addr, uint32_t& r0, uint32_t& r1,
                                       uint32_t& r2, uint32_t& r3) {
    asm volatile("ldmatrix.sync.aligned.m8n8.x4.shared.b16 {%0,%1,%2,%3}, [%4];"
                 : "=r"(r0), "=r"(r1), "=r"(r2), "=r"(r3) : "r"(addr));
}
__device__ __forceinline__ void mma_f16(float* c, uint32_t a0, uint32_t a1,
                                        uint32_t a2, uint32_t a3,
                                        uint32_t b0, uint32_t b1) {
    asm volatile("mma.sync.aligned.m16n8k16.row.col.f32.f16.f16.f32 "
                 "{%0,%1,%2,%3}, {%4,%5,%6,%7}, {%8,%9}, {%0,%1,%2,%3};"
                 : "+f"(c[0]), "+f"(c[1]), "+f"(c[2]), "+f"(c[3])
                 : "r"(a0), "r"(a1), "r"(a2), "r"(a3), "r"(b0), "r"(b1));
}
__device__ __forceinline__ uint32_t pk2h(__half a, __half b) {
    __half2 t = __halves2half2(a, b);
    return *(uint32_t*)&t;
}
__device__ __forceinline__ void split1h(float x, __half& h, __half& l) {
    h = __float2half_rn(x);
    l = __float2half_rn(x - __half2float(h));
}
__device__ __forceinline__ void split4h(float4 x, uint2& hi, uint2& lo) {
    __half h0,h1,h2,h3,l0,l1,l2,l3;
    split1h(x.x,h0,l0); split1h(x.y,h1,l1); split1h(x.z,h2,l2); split1h(x.w,h3,l3);
    hi = make_uint2(pk2h(h0,h1), pk2h(h2,h3));
    lo = make_uint2(pk2h(l0,l1), pk2h(l2,l3));
}

// fp16x2 compute: 4 ksteps of k16 over one staged 64-K chunk.
// A hi+lo planes (128x64), B hi plane (NT x 64).
template<int NF>
__device__ __forceinline__ void compute_chunk(uint32_t aHi, uint32_t aLo, uint32_t bHi,
                                              uint32_t a_base, uint32_t b_base,
                                              float (&acc)[4][NF][4]) {
    #pragma unroll
    for (int ks = 0; ks < 4; ks++) {
        uint32_t bf[2*NF];
        #pragma unroll
        for (int ng = 0; ng < NF/2; ng++) {
            uint32_t ofs = b_base + (uint32_t)(ng * 16 * 128 + ks * 32);
            ldm_x4(bHi + SWZ(ofs), bf[4*ng], bf[4*ng+1], bf[4*ng+2], bf[4*ng+3]);
        }
        #pragma unroll
        for (int mf = 0; mf < 4; mf++) {
            uint32_t ofs = a_base + (uint32_t)(mf * 16 * 128 + ks * 32);
            uint32_t h0,h1,h2,h3, l0,l1,l2,l3;
            ldm_x4(aHi + SWZ(ofs), h0,h1,h2,h3);
            ldm_x4(aLo + SWZ(ofs), l0,l1,l2,l3);
            #pragma unroll
            for (int nf = 0; nf < NF; nf++) {
                mma_f16(acc[mf][nf], h0,h1,h2,h3, bf[2*nf], bf[2*nf+1]);
                mma_f16(acc[mf][nf], l0,l1,l2,l3, bf[2*nf], bf[2*nf+1]);
            }
        }
    }
}

// cp.async copy of an R-row x 128B tile (hi/lo fp16 plane layout), swizzled.
template<int ITEMS>
__device__ __forceinline__ void stage_cp(uint32_t dstBase, const char* src,
                                         size_t strideB, int tid) {
    #pragma unroll
    for (int it = 0; it < ITEMS; it++) {
        int v = tid + it * 256;
        int row = v >> 3, c16 = (v & 7) * 16;
        cp16(dstBase + SWZ(row * 128 + c16), src + (size_t)row * strideB + c16);
    }
}

// ---------------- pre-split kernels ----------------
__global__ void __launch_bounds__(256) split_kernel(
    const float* __restrict__ s0, const float* __restrict__ s1,
    const float* __restrict__ s2, const float* __restrict__ s3,
    __half* h0, __half* h1, __half* h2, __half* h3,
    __half* l0, __half* l1, __half* l2, __half* l3, int n)
{
    int z = blockIdx.z;
    const float* s = z==0?s0 : z==1?s1 : z==2?s2 : s3;
    __half* h = z==0?h0 : z==1?h1 : z==2?h2 : h3;
    __half* l = z==0?l0 : z==1?l1 : z==2?l2 : l3;
    int i = (blockIdx.x * 256 + threadIdx.x) * 4;
    if (i >= n) return;
    float4 x = *(const float4*)(s + i);
    uint2 hi, lo;
    split4h(x, hi, lo);
    *(uint2*)(h + i) = hi;
    if (l) *(uint2*)(l + i) = lo;
}

__global__ void zero_rowsum_kernel(float* rs) {
    rs[(size_t)blockIdx.x * 256 + threadIdx.x] = 0.0f;
}

// ---------------- projection kernel (q/k/v merged via z) ----------------
struct ProjArgs {
    const __half* ah[3]; const __half* al[3]; const __half* bh[3];
    const float*  bias[3];
    __half* ch[3]; __half* cl[3];
};

__global__ void __launch_bounds__(256) proj_kernel(ProjArgs P)
{
    constexpr int NF = 4, NC = 16;
    constexpr int BUF = 49152;               // AHI 16K + ALO 16K + BHI 16K
    extern __shared__ char smem[];
    const uint32_t sb = smem_u32(smem);
    const int tid = threadIdx.x, wid = tid >> 5, lid = tid & 31;
    const int warp_m = wid >> 2, warp_n = wid & 3;
    const int m0 = blockIdx.y * 128, col0 = blockIdx.x * 128, z = blockIdx.z;

    const char* Ah = (const char*)P.ah[z];
    const char* Al = (const char*)P.al[z];
    const char* Bh = (const char*)P.bh[z];
    const float* bias = P.bias[z];
    __half* Ch = P.ch[z];
    __half* Cl = P.cl[z];

    float acc[4][NF][4];
    #pragma unroll
    for (int i=0;i<4;i++) for (int j=0;j<NF;j++) for (int t=0;t<4;t++) acc[i][j][t]=0.0f;

    const uint32_t a_base = (uint32_t)((warp_m*64 + (lid&15))*128 + ((lid>>4)<<4));
    const uint32_t b_base = (uint32_t)((warp_n*32 + ((lid>>4)<<3) + (lid&7))*128
                                       + (((lid>>3)&1)<<4));

    auto stage = [&](int ci, int bi) {
        size_t aofs = ((size_t)m0 * DM + ci * 64) * 2;
        size_t bofs = ((size_t)col0 * DM + ci * 64) * 2;
        uint32_t d = sb + bi * BUF;
        stage_cp<4>(d,         Ah + aofs, DM*2, tid);
        stage_cp<4>(d + 16384, Al + aofs, DM*2, tid);
        stage_cp<4>(d + 32768, Bh + bofs, DM*2, tid);
    };

    stage(0, 0); cp_commit();
    for (int ci = 0; ci < NC; ci++) {
        if (ci + 1 < NC) { stage(ci+1, (ci+1)&1); cp_commit(); cp_wait1(); }
        else cp_wait0();
        __syncthreads();
        uint32_t d = sb + (ci&1) * BUF;
        compute_chunk<NF>(d, d + 16384, d + 32768, a_base, b_base, acc);
        __syncthreads();
    }

    #pragma unroll
    for (int mf = 0; mf < 4; mf++)
        #pragma unroll
        for (int nf = 0; nf < NF; nf++) {
            int r  = m0 + warp_m*64 + mf*16 + (lid>>2);
            int cc = col0 + warp_n*32 + nf*8 + (lid&3)*2;
            float bv0 = __ldg(bias + cc), bv1 = __ldg(bias + cc + 1);
            #pragma unroll
            for (int half = 0; half < 2; half++) {
                int gr = r + half*8;
                float v0 = acc[mf][nf][half*2+0] + bv0;
                float v1 = acc[mf][nf][half*2+1] + bv1;
                int b = gr >> 11, s = gr & (SS-1), h = cc >> 6, dd = cc & (DK-1);
                size_t idx = ((((size_t)b*HH + h)*SS) + s)*DK + dd;
                __half hh, ll;
                split1h(v0, hh, ll); Ch[idx] = hh;   if (Cl) Cl[idx] = ll;
                split1h(v1, hh, ll); Ch[idx+1] = hh; if (Cl) Cl[idx+1] = ll;
            }
        }
}

// ---------------- scores kernel: E = exp(Q K^T / 8), rowsum atomics ----------
__global__ void __launch_bounds__(256) scores_kernel(
    const __half* __restrict__ Qh, const __half* __restrict__ Ql,
    const __half* __restrict__ Kh,
    float* __restrict__ E, float* __restrict__ rowsum)
{
    constexpr int NF = 4;
    extern __shared__ char smem[];
    const uint32_t sb = smem_u32(smem);
    const int tid = threadIdx.x, wid = tid >> 5, lid = tid & 31;
    const int warp_m = wid >> 2, warp_n = wid & 3;
    const int m0 = blockIdx.y * 128, col0 = blockIdx.x * 128, z = blockIdx.z;

    const char* Ah = (const char*)(Qh + (size_t)z*SS*DK + (size_t)m0*DK);
    const char* Al = (const char*)(Ql + (size_t)z*SS*DK + (size_t)m0*DK);
    const char* Bh = (const char*)(Kh + (size_t)z*SS*DK + (size_t)col0*DK);

    float acc[4][NF][4];
    #pragma unroll
    for (int i=0;i<4;i++) for (int j=0;j<NF;j++) for (int t=0;t<4;t++) acc[i][j][t]=0.0f;

    const uint32_t a_base = (uint32_t)((warp_m*64 + (lid&15))*128 + ((lid>>4)<<4));
    const uint32_t b_base = (uint32_t)((warp_n*32 + ((lid>>4)<<3) + (lid&7))*128
                                       + (((lid>>3)&1)<<4));

    stage_cp<4>(sb,         Ah, 128, tid);
    stage_cp<4>(sb + 16384, Al, 128, tid);
    stage_cp<4>(sb + 32768, Bh, 128, tid);
    cp_commit(); cp_wait0();
    __syncthreads();
    compute_chunk<NF>(sb, sb + 16384, sb + 32768, a_base, b_base, acc);

    #pragma unroll
    for (int mf = 0; mf < 4; mf++) {
        #pragma unroll
        for (int half = 0; half < 2; half++) {
            int gr = m0 + warp_m*64 + mf*16 + (lid>>2) + half*8;
            float rs = 0.0f;
            #pragma unroll
            for (int nf = 0; nf < NF; nf++) {
                int cc = col0 + warp_n*32 + nf*8 + (lid&3)*2;
                float e0 = __expf(acc[mf][nf][half*2+0] * 0.125f);
                float e1 = __expf(acc[mf][nf][half*2+1] * 0.125f);
                size_t idx = (size_t)z*SS*SS + (size_t)gr*SS + cc;
                E[idx] = e0; E[idx+1] = e1;
                rs += e0 + e1;
            }
            rs += __shfl_xor_sync(0xffffffffu, rs, 1);
            rs += __shfl_xor_sync(0xffffffffu, rs, 2);
            if ((lid & 3) == 0) atomicAdd(&rowsum[(size_t)z*SS + gr], rs);
        }
    }
}

// ---------------- AV kernel: ctx = (E/rowsum) @ V ----------------
// smem: Ebuf0 34816 | Ebuf1 34816 | AHI 16K | ALO 16K | Vb0 8K | Vb1 8K | INV 512
__global__ void __launch_bounds__(256) av_kernel(
    const float* __restrict__ E, const __half* __restrict__ Vh,
    const float* __restrict__ rowsum,
    __half* __restrict__ Ch, __half* __restrict__ Cl,
    float* __restrict__ attn_wb, int write_attn)
{
    constexpr int NF = 2, NC = 32;
    constexpr int EB0 = 0, EB1 = 34816, AHI = 69632, ALO = 86016;
    constexpr int VB0 = 102400, VB1 = 110592, INV = 118784;
    extern __shared__ char smem[];
    const uint32_t sb = smem_u32(smem);
    const int tid = threadIdx.x, wid = tid >> 5, lid = tid & 31;
    const int warp_m = wid >> 2, warp_n = wid & 3;
    const int m0 = blockIdx.y * 128, z = blockIdx.z;

    const float* Eb = E + (size_t)z*SS*SS + (size_t)m0*SS;
    const __half* Vb = Vh + (size_t)z*SS*DK;
    float* wb = attn_wb + (size_t)z*SS*SS + (size_t)m0*SS;

    if (tid < 128)
        *(float*)(smem + INV + tid*4) = 1.0f / rowsum[(size_t)z*SS + m0 + tid];

    float acc[4][NF][4];
    #pragma unroll
    for (int i=0;i<4;i++) for (int j=0;j<NF;j++) for (int t=0;t<4;t++) acc[i][j][t]=0.0f;

    const uint32_t a_base = (uint32_t)((warp_m*64 + (lid&15))*128 + ((lid>>4)<<4));
    const uint32_t b_base = (uint32_t)((warp_n*16 + ((lid>>4)<<3) + (lid&7))*128
                                       + (((lid>>3)&1)<<4));

    auto stageE = [&](int ci, int bi) {        // cp.async E chunk (fp32, padded 272B rows)
        const char* src = (const char*)(Eb + ci*64);
        uint32_t d = sb + (bi ? EB1 : EB0);
        #pragma unroll
        for (int it = 0; it < 8; it++) {
            int v = tid + it*256;
            int row = v >> 4, c16 = (v & 15) * 16;
            cp16(d + row*272 + c16, src + (size_t)row*(SS*4) + c16);
        }
    };
    auto stageV = [&](int ci, int bi) {        // scalar transpose V[t,d] -> smem[d][t]
        uint32_t d = sb + (bi ? VB1 : VB0);
        #pragma unroll
        for (int it = 0; it < 4; it++) {
            int v = tid + it*256;
            int tt = v >> 4, d0 = (v & 15) << 2;
            uint2 hv = *(const uint2*)(Vb + (size_t)(ci*64 + tt)*DK + d0);
            ushort hs[4];
            hs[0] = hv.x & 0xFFFF; hs[1] = hv.x >> 16;
            hs[2] = hv.y & 0xFFFF; hs[3] = hv.y >> 16;
            #pragma unroll
            for (int j = 0; j < 4; j++)
                *(ushort*)(smem + (bi ? VB1 : VB0) + SWZ((d0+j)*128 + (tt<<1))) = hs[j];
            (void)d;
        }
    };

    stageE(0, 0); cp_commit();
    stageV(0, 0);
    for (int ci = 0; ci < NC; ci++) {
        if (ci + 1 < NC) { stageE(ci+1, (ci+1)&1); cp_commit(); cp_wait1(); }
        else cp_wait0();
        __syncthreads();
        if (ci + 1 < NC) stageV(ci+1, (ci+1)&1);
        // transform E fp32 smem -> hi/lo fp16 planes (+optional attn writeback)
        {
            const char* eb = smem + ((ci&1) ? EB1 : EB0);
            #pragma unroll
            for (int it = 0; it < 4; it++) {
                int v = tid + it*256;
                int row = v >> 3, c8 = (v & 7) << 3;
                float inv = *(const float*)(smem + INV + row*4);
                float4 x0 = *(const float4*)(eb + row*272 + c8*4);
                float4 x1 = *(const float4*)(eb + row*272 + c8*4 + 16);
                x0.x*=inv; x0.y*=inv; x0.z*=inv; x0.w*=inv;
                x1.x*=inv; x1.y*=inv; x1.z*=inv; x1.w*=inv;
                if (write_attn) {
                    *(float4*)(wb + (size_t)row*SS + ci*64 + c8)     = x0;
                    *(float4*)(wb + (size_t)row*SS + ci*64 + c8 + 4) = x1;
                }
                uint2 h0,l0,h1,l1;
                split4h(x0, h0, l0); split4h(x1, h1, l1);
                int so = SWZ(row*128 + (c8<<1));
                *(uint4*)(smem + AHI + so) = make_uint4(h0.x, h0.y, h1.x, h1.y);
                *(uint4*)(smem + ALO + so) = make_uint4(l0.x, l0.y, l1.x, l1.y);
            }
        }
        __syncthreads();
        compute_chunk<NF>(sb + AHI, sb + ALO, sb + ((ci&1) ? VB1 : VB0),
                          a_base, b_base, acc);
        __syncthreads();
    }

    #pragma unroll
    for (int mf = 0; mf < 4; mf++)
        #pragma unroll
        for (int nf = 0; nf < NF; nf++) {
            int r  = m0 + warp_m*64 + mf*16 + (lid>>2);
            int cc = warp_n*16 + nf*8 + (lid&3)*2;
            #pragma unroll
            for (int half = 0; half < 2; half++) {
                int gr = r + half*8;
                float v0 = acc[mf][nf][half*2+0], v1 = acc[mf][nf][half*2+1];
                int b = z >> 4, h = z & (HH-1);
                size_t idx = ((size_t)(b*SS + gr))*DM + h*DK + cc;
                __half hh, ll;
                split1h(v0, hh, ll); Ch[idx] = hh;   Cl[idx] = ll;
                split1h(v1, hh, ll); Ch[idx+1] = hh; Cl[idx+1] = ll;
            }
        }
}

// ---------------- output projection ----------------
__global__ void __launch_bounds__(256) outproj_kernel(
    const __half* __restrict__ Ah, const __half* __restrict__ Al,
    const __half* __restrict__ Bh, const float* __restrict__ bias,
    float* __restrict__ out)
{
    constexpr int NF = 4, NC = 16;
    constexpr int BUF = 49152;
    extern __shared__ char smem[];
    const uint32_t sb = smem_u32(smem);
    const int tid = threadIdx.x, wid = tid >> 5, lid = tid & 31;
    const int warp_m = wid >> 2, warp_n = wid & 3;
    const int m0 = blockIdx.y * 128, col0 = blockIdx.x * 128;

    float acc[4][NF][4];
    #pragma unroll
    for (int i=0;i<4;i++) for (int j=0;j<NF;j++) for (int t=0;t<4;t++) acc[i][j][t]=0.0f;

    const uint32_t a_base = (uint32_t)((warp_m*64 + (lid&15))*128 + ((lid>>4)<<4));
    const uint32_t b_base = (uint32_t)((warp_n*32 + ((lid>>4)<<3) + (lid&7))*128
                                       + (((lid>>3)&1)<<4));

    auto stage = [&](int ci, int bi) {
        size_t aofs = ((size_t)m0 * DM + ci*64) * 2;
        size_t bofs = ((size_t)col0 * DM + ci*64) * 2;
        uint32_t d = sb + bi * BUF;
        stage_cp<4>(d,         (const char*)Ah + aofs, DM*2, tid);
        stage_cp<4>(d + 16384, (const char*)Al + aofs, DM*2, tid);
        stage_cp<4>(d + 32768, (const char*)Bh + bofs, DM*2, tid);
    };

    stage(0, 0); cp_commit();
    for (int ci = 0; ci < NC; ci++) {
        if (ci + 1 < NC) { stage(ci+1, (ci+1)&1); cp_commit(); cp_wait1(); }
        else cp_wait0();
        __syncthreads();
        uint32_t d = sb + (ci&1) * BUF;
        compute_chunk<NF>(d, d + 16384, d + 32768, a_base, b_base, acc);
        __syncthreads();
    }

    #pragma unroll
    for (int mf = 0; mf < 4; mf++)
        #pragma unroll
        for (int nf = 0; nf < NF; nf++) {
            int r  = m0 + warp_m*64 + mf*16 + (lid>>2);
            int cc = col0 + warp_n*32 + nf*8 + (lid&3)*2;
            float bv0 = __ldg(bias + cc), bv1 = __ldg(bias + cc + 1);
            #pragma unroll
            for (int half = 0; half < 2; half++) {
                int gr = r + half*8;
                size_t idx = (size_t)gr*DM + cc;
                out[idx]   = acc[mf][nf][half*2+0] + bv0;
                out[idx+1] = acc[mf][nf][half*2+1] + bv1;
            }
        }
}

// ---------------------------------------------------------------------------
extern "C" void kernel_launch(void* const* d_in, const int* in_sizes, int n_in,
                              void* d_out, int out_size)
{
    const float* q   = (const float*)d_in[0];
    const float* k   = (const float*)d_in[1];
    const float* v   = (const float*)d_in[2];
    const float* w_q = (const float*)d_in[3];
    const float* b_q = (const float*)d_in[4];
    const float* w_k = (const float*)d_in[5];
    const float* b_k = (const float*)d_in[6];
    const float* w_v = (const float*)d_in[7];
    const float* b_v = (const float*)d_in[8];
    const float* w_o = (const float*)d_in[9];
    const float* b_o = (const float*)d_in[10];
    float* out = (float*)d_out;

    __half *in_h, *in_l, *w_h, *qh_h, *qh_l, *kh_h, *vh_h, *cx_h, *cx_l;
    cudaGetSymbolAddress((void**)&in_h, g_in_h);
    cudaGetSymbolAddress((void**)&in_l, g_in_l);
    cudaGetSymbolAddress((void**)&w_h,  g_w_h);
    cudaGetSymbolAddress((void**)&qh_h, g_qh_h);
    cudaGetSymbolAddress((void**)&qh_l, g_qh_l);
    cudaGetSymbolAddress((void**)&kh_h, g_kh_h);
    cudaGetSymbolAddress((void**)&vh_h, g_vh_h);
    cudaGetSymbolAddress((void**)&cx_h, g_cx_h);
    cudaGetSymbolAddress((void**)&cx_l, g_cx_l);
    float* rowsum; cudaGetSymbolAddress((void**)&rowsum, g_rowsum);

    const size_t NN = (size_t)MROWS * DM;      // 8M
    const size_t WW = (size_t)DM * DM;         // 1M

    float* attn;
    int write_attn;
    if ((size_t)out_size >= OUT_ELEMS + ATTN_ELEMS) {
        attn = out + OUT_ELEMS; write_attn = 1;
    } else {
        cudaGetSymbolAddress((void**)&attn, g_attn); write_attn = 0;
    }

    const int SMP = 2 * 49152;                 // 96 KB proj / outproj
    const int SMS = 49152;                     // 48 KB scores
    const int SMA = 119296;                    // AV
    cudaFuncSetAttribute(proj_kernel,    cudaFuncAttributeMaxDynamicSharedMemorySize, SMP);
    cudaFuncSetAttribute(outproj_kernel, cudaFuncAttributeMaxDynamicSharedMemorySize, SMP);
    cudaFuncSetAttribute(scores_kernel,  cudaFuncAttributeMaxDynamicSharedMemorySize, SMS);
    cudaFuncSetAttribute(av_kernel,      cudaFuncAttributeMaxDynamicSharedMemorySize, SMA);

    // pre-split inputs (hi+lo) and weights (hi only)
    split_kernel<<<dim3((int)(NN/4/256), 1, 3), 256>>>(
        q, k, v, q,
        in_h, in_h + NN, in_h + 2*NN, in_h,
        in_l, in_l + NN, in_l + 2*NN, in_l, (int)NN);
    split_kernel<<<dim3((int)(WW/4/256), 1, 4), 256>>>(
        w_q, w_k, w_v, w_o,
        w_h, w_h + WW, w_h + 2*WW, w_h + 3*WW,
        nullptr, nullptr, nullptr, nullptr, (int)WW);

    zero_rowsum_kernel<<<dim3(BB*HH*SS/256), 256>>>(rowsum);

    // projections (q needs lo plane; k, v hi only)
    ProjArgs P;
    P.ah[0] = in_h;        P.ah[1] = in_h + NN;   P.ah[2] = in_h + 2*NN;
    P.al[0] = in_l;        P.al[1] = in_l + NN;   P.al[2] = in_l + 2*NN;
    P.bh[0] = w_h;         P.bh[1] = w_h + WW;    P.bh[2] = w_h + 2*WW;
    P.bias[0] = b_q;       P.bias[1] = b_k;       P.bias[2] = b_v;
    P.ch[0] = qh_h;        P.ch[1] = kh_h;        P.ch[2] = vh_h;
    P.cl[0] = qh_l;        P.cl[1] = nullptr;     P.cl[2] = nullptr;
    proj_kernel<<<dim3(DM/128, MROWS/128, 3), 256, SMP>>>(P);

    scores_kernel<<<dim3(SS/128, SS/128, BB*HH), 256, SMS>>>(
        qh_h, qh_l, kh_h, attn, rowsum);

    av_kernel<<<dim3(1, SS/128, BB*HH), 256, SMA>>>(
        attn, vh_h, rowsum, cx_h, cx_l, attn, write_attn);

    outproj_kernel<<<dim3(DM/128, MROWS/128), 256, SMP>>>(
        cx_h, cx_l, w_h + 3*WW, b_o, out);
}

// round 8
// speedup vs baseline: 3.0696x; 1.0355x over previous
#include <cuda_runtime.h>
#include <cuda_fp16.h>
#include <cstdint>

// ---------------- problem constants ----------------
#define BB 4
#define SS 2048
#define HH 16
#define DK 64
#define DM 1024
#define MROWS (BB*SS)                        // 8192
#define OUT_ELEMS ((size_t)MROWS*DM)         // 8,388,608
#define ATTN_ELEMS ((size_t)BB*HH*SS*SS)     // 268,435,456

// ---------------- device-global scratch ----------------
__device__ __half g_in_h[3][(size_t)MROWS*DM], g_in_l[3][(size_t)MROWS*DM];
__device__ __half g_w_h[4][(size_t)DM*DM];
__device__ __half g_qh_h[(size_t)MROWS*DM], g_qh_l[(size_t)MROWS*DM];
__device__ __half g_kh_h[(size_t)MROWS*DM];
__device__ __half g_vh_h[(size_t)MROWS*DM];
__device__ __half g_cx_h[(size_t)MROWS*DM], g_cx_l[(size_t)MROWS*DM];
__device__ float g_attn[ATTN_ELEMS];
__device__ float g_rowsum[(size_t)BB*HH*SS];

// ---------------- helpers ----------------
#define SWZ(o) ((o) ^ (((o) >> 3) & 0x70))

__device__ __forceinline__ uint32_t smem_u32(const void* p) {
    uint32_t a;
    asm("{ .reg .u64 t; cvta.to.shared.u64 t, %1; cvt.u32.u64 %0, t; }"
        : "=r"(a) : "l"(p));
    return a;
}
__device__ __forceinline__ void cp16(uint32_t dst, const void* src) {
    asm volatile("cp.async.cg.shared.global [%0], [%1], 16;" :: "r"(dst), "l"(src) : "memory");
}
__device__ __forceinline__ void cp_commit() { asm volatile("cp.async.commit_group;" ::: "memory"); }
__device__ __forceinline__ void cp_wait0()  { asm volatile("cp.async.wait_group 0;" ::: "memory"); }
__device__ __forceinline__ void cp_wait1()  { asm volatile("cp.async.wait_group 1;" ::: "memory"); }

__device__ __forceinline__ void ldm_x4(uint32_t addr, uint32_t& r0, uint32_t& r1,
                                       uint32_t& r2, uint32_t& r3) {
    asm volatile("ldmatrix.sync.aligned.m8n8.x4.shared.b16 {%0,%1,%2,%3}, [%4];"
                 : "=r"(r0), "=r"(r1), "=r"(r2), "=r"(r3) : "r"(addr));
}
__device__ __forceinline__ void mma_f16(float* c, uint32_t a0, uint32_t a1,
                                        uint32_t a2, uint32_t a3,
                                        uint32_t b0, uint32_t b1) {
    asm volatile("mma.sync.aligned.m16n8k16.row.col.f32.f16.f16.f32 "
                 "{%0,%1,%2,%3}, {%4,%5,%6,%7}, {%8,%9}, {%0,%1,%2,%3};"
                 : "+f"(c[0]), "+f"(c[1]), "+f"(c[2]), "+f"(c[3])
                 : "r"(a0), "r"(a1), "r"(a2), "r"(a3), "r"(b0), "r"(b1));
}
__device__ __forceinline__ uint32_t pk2h(__half a, __half b) {
    __half2 t = __halves2half2(a, b);
    return *(uint32_t*)&t;
}
__device__ __forceinline__ void split1h(float x, __half& h, __half& l) {
    h = __float2half_rn(x);
    l = __float2half_rn(x - __half2float(h));
}
__device__ __forceinline__ void split4h(float4 x, uint2& hi, uint2& lo) {
    __half h0,h1,h2,h3,l0,l1,l2,l3;
    split1h(x.x,h0,l0); split1h(x.y,h1,l1); split1h(x.z,h2,l2); split1h(x.w,h3,l3);
    hi = make_uint2(pk2h(h0,h1), pk2h(h2,h3));
    lo = make_uint2(pk2h(l0,l1), pk2h(l2,l3));
}

// fp16x2 compute: 4 ksteps of k16 over one staged 64-K chunk.
template<int NF>
__device__ __forceinline__ void compute_chunk(uint32_t aHi, uint32_t aLo, uint32_t bHi,
                                              uint32_t a_base, uint32_t b_base,
                                              float (&acc)[4][NF][4]) {
    #pragma unroll
    for (int ks = 0; ks < 4; ks++) {
        uint32_t bf[2*NF];
        #pragma unroll
        for (int ng = 0; ng < NF/2; ng++) {
            uint32_t ofs = b_base + (uint32_t)(ng * 16 * 128 + ks * 32);
            ldm_x4(bHi + SWZ(ofs), bf[4*ng], bf[4*ng+1], bf[4*ng+2], bf[4*ng+3]);
        }
        #pragma unroll
        for (int mf = 0; mf < 4; mf++) {
            uint32_t ofs = a_base + (uint32_t)(mf * 16 * 128 + ks * 32);
            uint32_t h0,h1,h2,h3, l0,l1,l2,l3;
            ldm_x4(aHi + SWZ(ofs), h0,h1,h2,h3);
            ldm_x4(aLo + SWZ(ofs), l0,l1,l2,l3);
            #pragma unroll
            for (int nf = 0; nf < NF; nf++) {
                mma_f16(acc[mf][nf], h0,h1,h2,h3, bf[2*nf], bf[2*nf+1]);
                mma_f16(acc[mf][nf], l0,l1,l2,l3, bf[2*nf], bf[2*nf+1]);
            }
        }
    }
}

template<int ITEMS>
__device__ __forceinline__ void stage_cp(uint32_t dstBase, const char* src,
                                         size_t strideB, int tid) {
    #pragma unroll
    for (int it = 0; it < ITEMS; it++) {
        int v = tid + it * 256;
        int row = v >> 3, c16 = (v & 7) * 16;
        cp16(dstBase + SWZ(row * 128 + c16), src + (size_t)row * strideB + c16);
    }
}

// ---------------- pre-split kernels ----------------
__global__ void __launch_bounds__(256) split_kernel(
    const float* __restrict__ s0, const float* __restrict__ s1,
    const float* __restrict__ s2, const float* __restrict__ s3,
    __half* h0, __half* h1, __half* h2, __half* h3,
    __half* l0, __half* l1, __half* l2, __half* l3, int n)
{
    int z = blockIdx.z;
    const float* s = z==0?s0 : z==1?s1 : z==2?s2 : s3;
    __half* h = z==0?h0 : z==1?h1 : z==2?h2 : h3;
    __half* l = z==0?l0 : z==1?l1 : z==2?l2 : l3;
    int i = (blockIdx.x * 256 + threadIdx.x) * 4;
    if (i >= n) return;
    float4 x = *(const float4*)(s + i);
    uint2 hi, lo;
    split4h(x, hi, lo);
    *(uint2*)(h + i) = hi;
    if (l) *(uint2*)(l + i) = lo;
}

__global__ void zero_rowsum_kernel(float* rs) {
    rs[(size_t)blockIdx.x * 256 + threadIdx.x] = 0.0f;
}

// ---------------- projection kernel (q/k/v merged via z) ----------------
struct ProjArgs {
    const __half* ah[3]; const __half* al[3]; const __half* bh[3];
    const float*  bias[3];
    __half* ch[3]; __half* cl[3];
};

__global__ void __launch_bounds__(256, 2) proj_kernel(ProjArgs P)
{
    constexpr int NF = 4, NC = 16;
    constexpr int BUF = 49152;
    extern __shared__ char smem[];
    const uint32_t sb = smem_u32(smem);
    const int tid = threadIdx.x, wid = tid >> 5, lid = tid & 31;
    const int warp_m = wid >> 2, warp_n = wid & 3;
    const int m0 = blockIdx.y * 128, col0 = blockIdx.x * 128, z = blockIdx.z;

    const char* Ah = (const char*)P.ah[z];
    const char* Al = (const char*)P.al[z];
    const char* Bh = (const char*)P.bh[z];
    const float* bias = P.bias[z];
    __half* Ch = P.ch[z];
    __half* Cl = P.cl[z];

    float acc[4][NF][4];
    #pragma unroll
    for (int i=0;i<4;i++) for (int j=0;j<NF;j++) for (int t=0;t<4;t++) acc[i][j][t]=0.0f;

    const uint32_t a_base = (uint32_t)((warp_m*64 + (lid&15))*128 + ((lid>>4)<<4));
    const uint32_t b_base = (uint32_t)((warp_n*32 + ((lid>>4)<<3) + (lid&7))*128
                                       + (((lid>>3)&1)<<4));

    auto stage = [&](int ci, int bi) {
        size_t aofs = ((size_t)m0 * DM + ci * 64) * 2;
        size_t bofs = ((size_t)col0 * DM + ci * 64) * 2;
        uint32_t d = sb + bi * BUF;
        stage_cp<4>(d,         Ah + aofs, DM*2, tid);
        stage_cp<4>(d + 16384, Al + aofs, DM*2, tid);
        stage_cp<4>(d + 32768, Bh + bofs, DM*2, tid);
    };

    stage(0, 0); cp_commit();
    for (int ci = 0; ci < NC; ci++) {
        if (ci + 1 < NC) { stage(ci+1, (ci+1)&1); cp_commit(); cp_wait1(); }
        else cp_wait0();
        __syncthreads();
        uint32_t d = sb + (ci&1) * BUF;
        compute_chunk<NF>(d, d + 16384, d + 32768, a_base, b_base, acc);
        __syncthreads();
    }

    #pragma unroll
    for (int mf = 0; mf < 4; mf++)
        #pragma unroll
        for (int nf = 0; nf < NF; nf++) {
            int r  = m0 + warp_m*64 + mf*16 + (lid>>2);
            int cc = col0 + warp_n*32 + nf*8 + (lid&3)*2;
            float bv0 = __ldg(bias + cc), bv1 = __ldg(bias + cc + 1);
            #pragma unroll
            for (int half = 0; half < 2; half++) {
                int gr = r + half*8;
                float v0 = acc[mf][nf][half*2+0] + bv0;
                float v1 = acc[mf][nf][half*2+1] + bv1;
                int b = gr >> 11, s = gr & (SS-1), h = cc >> 6, dd = cc & (DK-1);
                size_t idx = ((((size_t)b*HH + h)*SS) + s)*DK + dd;
                __half hh, ll;
                split1h(v0, hh, ll); Ch[idx] = hh;   if (Cl) Cl[idx] = ll;
                split1h(v1, hh, ll); Ch[idx+1] = hh; if (Cl) Cl[idx+1] = ll;
            }
        }
}

// ---------------- scores kernel: E = exp(Q K^T / 8), rowsum atomics ----------
__global__ void __launch_bounds__(256, 2) scores_kernel(
    const __half* __restrict__ Qh, const __half* __restrict__ Ql,
    const __half* __restrict__ Kh,
    float* __restrict__ E, float* __restrict__ rowsum)
{
    constexpr int NF = 4;
    extern __shared__ char smem[];
    const uint32_t sb = smem_u32(smem);
    const int tid = threadIdx.x, wid = tid >> 5, lid = tid & 31;
    const int warp_m = wid >> 2, warp_n = wid & 3;
    const int m0 = blockIdx.y * 128, col0 = blockIdx.x * 128, z = blockIdx.z;

    const char* Ah = (const char*)(Qh + (size_t)z*SS*DK + (size_t)m0*DK);
    const char* Al = (const char*)(Ql + (size_t)z*SS*DK + (size_t)m0*DK);
    const char* Bh = (const char*)(Kh + (size_t)z*SS*DK + (size_t)col0*DK);

    float acc[4][NF][4];
    #pragma unroll
    for (int i=0;i<4;i++) for (int j=0;j<NF;j++) for (int t=0;t<4;t++) acc[i][j][t]=0.0f;

    const uint32_t a_base = (uint32_t)((warp_m*64 + (lid&15))*128 + ((lid>>4)<<4));
    const uint32_t b_base = (uint32_t)((warp_n*32 + ((lid>>4)<<3) + (lid&7))*128
                                       + (((lid>>3)&1)<<4));

    stage_cp<4>(sb,         Ah, 128, tid);
    stage_cp<4>(sb + 16384, Al, 128, tid);
    stage_cp<4>(sb + 32768, Bh, 128, tid);
    cp_commit(); cp_wait0();
    __syncthreads();
    compute_chunk<NF>(sb, sb + 16384, sb + 32768, a_base, b_base, acc);

    #pragma unroll
    for (int mf = 0; mf < 4; mf++) {
        #pragma unroll
        for (int half = 0; half < 2; half++) {
            int gr = m0 + warp_m*64 + mf*16 + (lid>>2) + half*8;
            float rs = 0.0f;
            #pragma unroll
            for (int nf = 0; nf < NF; nf++) {
                int cc = col0 + warp_n*32 + nf*8 + (lid&3)*2;
                float e0 = __expf(acc[mf][nf][half*2+0] * 0.125f);
                float e1 = __expf(acc[mf][nf][half*2+1] * 0.125f);
                size_t idx = (size_t)z*SS*SS + (size_t)gr*SS + cc;
                E[idx] = e0; E[idx+1] = e1;
                rs += e0 + e1;
            }
            rs += __shfl_xor_sync(0xffffffffu, rs, 1);
            rs += __shfl_xor_sync(0xffffffffu, rs, 2);
            if ((lid & 3) == 0) atomicAdd(&rowsum[(size_t)z*SS + gr], rs);
        }
    }
}

// ---------------- AV kernel: ctx = (E/rowsum) @ V ----------------
// smem: EB0 34816 | EB1 34816 | PH0 16K | PL0 16K | PH1 16K | PL1 16K
//       | VB0 8K | VB1 8K | INV 512   (total 152064)
// stageE uses the SAME thread->byte mapping as transform, so each thread's
// cp.async is made visible by its own cp_wait before that thread reads it
// (no extra barrier needed).
__global__ void __launch_bounds__(256) av_kernel(
    const float* __restrict__ E, const __half* __restrict__ Vh,
    const float* __restrict__ rowsum,
    __half* __restrict__ Ch, __half* __restrict__ Cl,
    float* __restrict__ attn_wb, int write_attn)
{
    constexpr int NF = 2, NC = 32;
    constexpr int EB0 = 0, EB1 = 34816;
    constexpr int PH0 = 69632, PL0 = 86016, PH1 = 102400, PL1 = 118784;
    constexpr int VB0 = 135168, VB1 = 143360, INV = 151552;
    extern __shared__ char smem[];
    const uint32_t sb = smem_u32(smem);
    const int tid = threadIdx.x, wid = tid >> 5, lid = tid & 31;
    const int warp_m = wid >> 2, warp_n = wid & 3;
    const int m0 = blockIdx.y * 128, z = blockIdx.z;

    const float* Eb = E + (size_t)z*SS*SS + (size_t)m0*SS;
    const __half* Vb = Vh + (size_t)z*SS*DK;
    float* wb = attn_wb + (size_t)z*SS*SS + (size_t)m0*SS;

    if (tid < 128)
        *(float*)(smem + INV + tid*4) = 1.0f / rowsum[(size_t)z*SS + m0 + tid];

    float acc[4][NF][4];
    #pragma unroll
    for (int i=0;i<4;i++) for (int j=0;j<NF;j++) for (int t=0;t<4;t++) acc[i][j][t]=0.0f;

    const uint32_t a_base = (uint32_t)((warp_m*64 + (lid&15))*128 + ((lid>>4)<<4));
    const uint32_t b_base = (uint32_t)((warp_n*16 + ((lid>>4)<<3) + (lid&7))*128
                                       + (((lid>>3)&1)<<4));

    // thread->byte mapping identical to transform(): row = v>>3, 32B per item
    auto stageE = [&](int ci, int bi) {
        const char* src = (const char*)(Eb + ci*64);
        uint32_t d = sb + (bi ? EB1 : EB0);
        #pragma unroll
        for (int it = 0; it < 4; it++) {
            int v = tid + it*256;
            int row = v >> 3, c32 = (v & 7) * 32;       // byte offset in 256B row
            cp16(d + row*272 + c32,      src + (size_t)row*(SS*4) + c32);
            cp16(d + row*272 + c32 + 16, src + (size_t)row*(SS*4) + c32 + 16);
        }
    };
    auto stageV = [&](int ci, int bi) {
        #pragma unroll
        for (int it = 0; it < 4; it++) {
            int v = tid + it*256;
            int tt = v >> 4, d0 = (v & 15) << 2;
            uint2 hv = *(const uint2*)(Vb + (size_t)(ci*64 + tt)*DK + d0);
            ushort hs[4];
            hs[0] = hv.x & 0xFFFF; hs[1] = hv.x >> 16;
            hs[2] = hv.y & 0xFFFF; hs[3] = hv.y >> 16;
            #pragma unroll
            for (int j = 0; j < 4; j++)
                *(ushort*)(smem + (bi ? VB1 : VB0) + SWZ((d0+j)*128 + (tt<<1))) = hs[j];
        }
    };
    auto transform = [&](int ci) {            // E fp32 smem -> hi/lo fp16 planes
        const char* eb = smem + ((ci&1) ? EB1 : EB0);
        char* ph = smem + ((ci&1) ? PH1 : PH0);
        char* pl = smem + ((ci&1) ? PL1 : PL0);
        #pragma unroll
        for (int it = 0; it < 4; it++) {
            int v = tid + it*256;
            int row = v >> 3, c8 = (v & 7) << 3;        // float offset
            float inv = *(const float*)(smem + INV + row*4);
            float4 x0 = *(const float4*)(eb + row*272 + c8*4);
            float4 x1 = *(const float4*)(eb + row*272 + c8*4 + 16);
            x0.x*=inv; x0.y*=inv; x0.z*=inv; x0.w*=inv;
            x1.x*=inv; x1.y*=inv; x1.z*=inv; x1.w*=inv;
            if (write_attn) {
                *(float4*)(wb + (size_t)row*SS + ci*64 + c8)     = x0;
                *(float4*)(wb + (size_t)row*SS + ci*64 + c8 + 4) = x1;
            }
            uint2 h0,l0,h1,l1;
            split4h(x0, h0, l0); split4h(x1, h1, l1);
            int so = SWZ(row*128 + (c8<<1));
            *(uint4*)(ph + so) = make_uint4(h0.x, h0.y, h1.x, h1.y);
            *(uint4*)(pl + so) = make_uint4(l0.x, l0.y, l1.x, l1.y);
        }
    };

    stageE(0, 0); cp_commit();
    stageV(0, 0);
    cp_wait0();
    __syncthreads();                 // E(0) + INV + V(0) visible
    transform(0);
    stageE(1, 1); cp_commit();
    __syncthreads();                 // planes(0) visible

    for (int ci = 0; ci < NC; ci++) {
        if (ci + 1 < NC) stageV(ci+1, (ci+1)&1);
        compute_chunk<NF>(sb + ((ci&1) ? PH1 : PH0), sb + ((ci&1) ? PL1 : PL0),
                          sb + ((ci&1) ? VB1 : VB0), a_base, b_base, acc);
        if (ci + 1 < NC) {
            if (ci + 2 < NC) { stageE(ci+2, ci&1); cp_commit(); cp_wait1(); }
            else cp_wait0();
            transform(ci+1);         // reads only this thread's own cp'd bytes
        }
        __syncthreads();
    }

    #pragma unroll
    for (int mf = 0; mf < 4; mf++)
        #pragma unroll
        for (int nf = 0; nf < NF; nf++) {
            int r  = m0 + warp_m*64 + mf*16 + (lid>>2);
            int cc = warp_n*16 + nf*8 + (lid&3)*2;
            #pragma unroll
            for (int half = 0; half < 2; half++) {
                int gr = r + half*8;
                float v0 = acc[mf][nf][half*2+0], v1 = acc[mf][nf][half*2+1];
                int b = z >> 4, h = z & (HH-1);
                size_t idx = ((size_t)(b*SS + gr))*DM + h*DK + cc;
                __half hh, ll;
                split1h(v0, hh, ll); Ch[idx] = hh;   Cl[idx] = ll;
                split1h(v1, hh, ll); Ch[idx+1] = hh; Cl[idx+1] = ll;
            }
        }
}

// ---------------- output projection ----------------
__global__ void __launch_bounds__(256, 2) outproj_kernel(
    const __half* __restrict__ Ah, const __half* __restrict__ Al,
    const __half* __restrict__ Bh, const float* __restrict__ bias,
    float* __restrict__ out)
{
    constexpr int NF = 4, NC = 16;
    constexpr int BUF = 49152;
    extern __shared__ char smem[];
    const uint32_t sb = smem_u32(smem);
    const int tid = threadIdx.x, wid = tid >> 5, lid = tid & 31;
    const int warp_m = wid >> 2, warp_n = wid & 3;
    const int m0 = blockIdx.y * 128, col0 = blockIdx.x * 128;

    float acc[4][NF][4];
    #pragma unroll
    for (int i=0;i<4;i++) for (int j=0;j<NF;j++) for (int t=0;t<4;t++) acc[i][j][t]=0.0f;

    const uint32_t a_base = (uint32_t)((warp_m*64 + (lid&15))*128 + ((lid>>4)<<4));
    const uint32_t b_base = (uint32_t)((warp_n*32 + ((lid>>4)<<3) + (lid&7))*128
                                       + (((lid>>3)&1)<<4));

    auto stage = [&](int ci, int bi) {
        size_t aofs = ((size_t)m0 * DM + ci*64) * 2;
        size_t bofs = ((size_t)col0 * DM + ci*64) * 2;
        uint32_t d = sb + bi * BUF;
        stage_cp<4>(d,         (const char*)Ah + aofs, DM*2, tid);
        stage_cp<4>(d + 16384, (const char*)Al + aofs, DM*2, tid);
        stage_cp<4>(d + 32768, (const char*)Bh + bofs, DM*2, tid);
    };

    stage(0, 0); cp_commit();
    for (int ci = 0; ci < NC; ci++) {
        if (ci + 1 < NC) { stage(ci+1, (ci+1)&1); cp_commit(); cp_wait1(); }
        else cp_wait0();
        __syncthreads();
        uint32_t d = sb + (ci&1) * BUF;
        compute_chunk<NF>(d, d + 16384, d + 32768, a_base, b_base, acc);
        __syncthreads();
    }

    #pragma unroll
    for (int mf = 0; mf < 4; mf++)
        #pragma unroll
        for (int nf = 0; nf < NF; nf++) {
            int r  = m0 + warp_m*64 + mf*16 + (lid>>2);
            int cc = col0 + warp_n*32 + nf*8 + (lid&3)*2;
            float bv0 = __ldg(bias + cc), bv1 = __ldg(bias + cc + 1);
            #pragma unroll
            for (int half = 0; half < 2; half++) {
                int gr = r + half*8;
                size_t idx = (size_t)gr*DM + cc;
                out[idx]   = acc[mf][nf][half*2+0] + bv0;
                out[idx+1] = acc[mf][nf][half*2+1] + bv1;
            }
        }
}

// ---------------------------------------------------------------------------
extern "C" void kernel_launch(void* const* d_in, const int* in_sizes, int n_in,
                              void* d_out, int out_size)
{
    const float* q   = (const float*)d_in[0];
    const float* k   = (const float*)d_in[1];
    const float* v   = (const float*)d_in[2];
    const float* w_q = (const float*)d_in[3];
    const float* b_q = (const float*)d_in[4];
    const float* w_k = (const float*)d_in[5];
    const float* b_k = (const float*)d_in[6];
    const float* w_v = (const float*)d_in[7];
    const float* b_v = (const float*)d_in[8];
    const float* w_o = (const float*)d_in[9];
    const float* b_o = (const float*)d_in[10];
    float* out = (float*)d_out;

    __half *in_h, *in_l, *w_h, *qh_h, *qh_l, *kh_h, *vh_h, *cx_h, *cx_l;
    cudaGetSymbolAddress((void**)&in_h, g_in_h);
    cudaGetSymbolAddress((void**)&in_l, g_in_l);
    cudaGetSymbolAddress((void**)&w_h,  g_w_h);
    cudaGetSymbolAddress((void**)&qh_h, g_qh_h);
    cudaGetSymbolAddress((void**)&qh_l, g_qh_l);
    cudaGetSymbolAddress((void**)&kh_h, g_kh_h);
    cudaGetSymbolAddress((void**)&vh_h, g_vh_h);
    cudaGetSymbolAddress((void**)&cx_h, g_cx_h);
    cudaGetSymbolAddress((void**)&cx_l, g_cx_l);
    float* rowsum; cudaGetSymbolAddress((void**)&rowsum, g_rowsum);

    const size_t NN = (size_t)MROWS * DM;
    const size_t WW = (size_t)DM * DM;

    float* attn;
    int write_attn;
    if ((size_t)out_size >= OUT_ELEMS + ATTN_ELEMS) {
        attn = out + OUT_ELEMS; write_attn = 1;
    } else {
        cudaGetSymbolAddress((void**)&attn, g_attn); write_attn = 0;
    }

    const int SMP = 2 * 49152;                 // 96 KB proj / outproj
    const int SMS = 49152;                     // 48 KB scores
    const int SMA = 152064;                    // AV
    cudaFuncSetAttribute(proj_kernel,    cudaFuncAttributeMaxDynamicSharedMemorySize, SMP);
    cudaFuncSetAttribute(outproj_kernel, cudaFuncAttributeMaxDynamicSharedMemorySize, SMP);
    cudaFuncSetAttribute(scores_kernel,  cudaFuncAttributeMaxDynamicSharedMemorySize, SMS);
    cudaFuncSetAttribute(av_kernel,      cudaFuncAttributeMaxDynamicSharedMemorySize, SMA);

    split_kernel<<<dim3((int)(NN/4/256), 1, 3), 256>>>(
        q, k, v, q,
        in_h, in_h + NN, in_h + 2*NN, in_h,
        in_l, in_l + NN, in_l + 2*NN, in_l, (int)NN);
    split_kernel<<<dim3((int)(WW/4/256), 1, 4), 256>>>(
        w_q, w_k, w_v, w_o,
        w_h, w_h + WW, w_h + 2*WW, w_h + 3*WW,
        nullptr, nullptr, nullptr, nullptr, (int)WW);

    zero_rowsum_kernel<<<dim3(BB*HH*SS/256), 256>>>(rowsum);

    ProjArgs P;
    P.ah[0] = in_h;        P.ah[1] = in_h + NN;   P.ah[2] = in_h + 2*NN;
    P.al[0] = in_l;        P.al[1] = in_l + NN;   P.al[2] = in_l + 2*NN;
    P.bh[0] = w_h;         P.bh[1] = w_h + WW;    P.bh[2] = w_h + 2*WW;
    P.bias[0] = b_q;       P.bias[1] = b_k;       P.bias[2] = b_v;
    P.ch[0] = qh_h;        P.ch[1] = kh_h;        P.ch[2] = vh_h;
    P.cl[0] = qh_l;        P.cl[1] = nullptr;     P.cl[2] = nullptr;
    proj_kernel<<<dim3(DM/128, MROWS/128, 3), 256, SMP>>>(P);

    scores_kernel<<<dim3(SS/128, SS/128, BB*HH), 256, SMS>>>(
        qh_h, qh_l, kh_h, attn, rowsum);

    av_kernel<<<dim3(1, SS/128, BB*HH), 256, SMA>>>(
        attn, vh_h, rowsum, cx_h, cx_l, attn, write_attn);

    outproj_kernel<<<dim3(DM/128, MROWS/128), 256, SMP>>>(
        cx_h, cx_l, w_h + 3*WW, b_o, out);
}

// round 10
// speedup vs baseline: 3.3218x; 1.0822x over previous
#include <cuda_runtime.h>
#include <cuda_fp16.h>
#include <cstdint>

// ---------------- problem constants ----------------
#define BB 4
#define SS 2048
#define HH 16
#define DK 64
#define DM 1024
#define MROWS (BB*SS)                        // 8192
#define OUT_ELEMS ((size_t)MROWS*DM)         // 8,388,608
#define ATTN_ELEMS ((size_t)BB*HH*SS*SS)     // 268,435,456

// ---------------- device-global scratch ----------------
__device__ __half g_in_h[3][(size_t)MROWS*DM], g_in_l[3][(size_t)MROWS*DM];
__device__ __half g_w_h[4][(size_t)DM*DM];
__device__ __half g_qh_h[(size_t)MROWS*DM], g_qh_l[(size_t)MROWS*DM];
__device__ __half g_kh_h[(size_t)MROWS*DM];
__device__ __half g_vh_h[(size_t)MROWS*DM];
__device__ __half g_cx_h[(size_t)MROWS*DM], g_cx_l[(size_t)MROWS*DM];
__device__ float g_attn[ATTN_ELEMS];           // reused as 2x half planes (Eh, El)
__device__ float g_rowsum[(size_t)BB*HH*SS];

// ---------------- helpers ----------------
#define SWZ(o) ((o) ^ (((o) >> 3) & 0x70))

__device__ __forceinline__ uint32_t smem_u32(const void* p) {
    uint32_t a;
    asm("{ .reg .u64 t; cvta.to.shared.u64 t, %1; cvt.u32.u64 %0, t; }"
        : "=r"(a) : "l"(p));
    return a;
}
__device__ __forceinline__ void cp16(uint32_t dst, const void* src) {
    asm volatile("cp.async.cg.shared.global [%0], [%1], 16;" :: "r"(dst), "l"(src) : "memory");
}
__device__ __forceinline__ void cp_commit() { asm volatile("cp.async.commit_group;" ::: "memory"); }
__device__ __forceinline__ void cp_wait0()  { asm volatile("cp.async.wait_group 0;" ::: "memory"); }
__device__ __forceinline__ void cp_wait1()  { asm volatile("cp.async.wait_group 1;" ::: "memory"); }

__device__ __forceinline__ void ldm_x4(uint32_t addr, uint32_t& r0, uint32_t& r1,
                                       uint32_t& r2, uint32_t& r3) {
    asm volatile("ldmatrix.sync.aligned.m8n8.x4.shared.b16 {%0,%1,%2,%3}, [%4];"
                 : "=r"(r0), "=r"(r1), "=r"(r2), "=r"(r3) : "r"(addr));
}
__device__ __forceinline__ void mma_f16(float* c, uint32_t a0, uint32_t a1,
                                        uint32_t a2, uint32_t a3,
                                        uint32_t b0, uint32_t b1) {
    asm volatile("mma.sync.aligned.m16n8k16.row.col.f32.f16.f16.f32 "
                 "{%0,%1,%2,%3}, {%4,%5,%6,%7}, {%8,%9}, {%0,%1,%2,%3};"
                 : "+f"(c[0]), "+f"(c[1]), "+f"(c[2]), "+f"(c[3])
                 : "r"(a0), "r"(a1), "r"(a2), "r"(a3), "r"(b0), "r"(b1));
}
__device__ __forceinline__ uint32_t pk2h(__half a, __half b) {
    __half2 t = __halves2half2(a, b);
    return *(uint32_t*)&t;
}
__device__ __forceinline__ void split1h(float x, __half& h, __half& l) {
    h = __float2half_rn(x);
    l = __float2half_rn(x - __half2float(h));
}
__device__ __forceinline__ void split4h(float4 x, uint2& hi, uint2& lo) {
    __half h0,h1,h2,h3,l0,l1,l2,l3;
    split1h(x.x,h0,l0); split1h(x.y,h1,l1); split1h(x.z,h2,l2); split1h(x.w,h3,l3);
    hi = make_uint2(pk2h(h0,h1), pk2h(h2,h3));
    lo = make_uint2(pk2h(l0,l1), pk2h(l2,l3));
}

// fp16x2 compute: 4 ksteps of k16 over one staged 64-K chunk.
template<int NF>
__device__ __forceinline__ void compute_chunk(uint32_t aHi, uint32_t aLo, uint32_t bHi,
                                              uint32_t a_base, uint32_t b_base,
                                              float (&acc)[4][NF][4]) {
    #pragma unroll
    for (int ks = 0; ks < 4; ks++) {
        uint32_t bf[2*NF];
        #pragma unroll
        for (int ng = 0; ng < NF/2; ng++) {
            uint32_t ofs = b_base + (uint32_t)(ng * 16 * 128 + ks * 32);
            ldm_x4(bHi + SWZ(ofs), bf[4*ng], bf[4*ng+1], bf[4*ng+2], bf[4*ng+3]);
        }
        #pragma unroll
        for (int mf = 0; mf < 4; mf++) {
            uint32_t ofs = a_base + (uint32_t)(mf * 16 * 128 + ks * 32);
            uint32_t h0,h1,h2,h3, l0,l1,l2,l3;
            ldm_x4(aHi + SWZ(ofs), h0,h1,h2,h3);
            ldm_x4(aLo + SWZ(ofs), l0,l1,l2,l3);
            #pragma unroll
            for (int nf = 0; nf < NF; nf++) {
                mma_f16(acc[mf][nf], h0,h1,h2,h3, bf[2*nf], bf[2*nf+1]);
                mma_f16(acc[mf][nf], l0,l1,l2,l3, bf[2*nf], bf[2*nf+1]);
            }
        }
    }
}

template<int ITEMS>
__device__ __forceinline__ void stage_cp(uint32_t dstBase, const char* src,
                                         size_t strideB, int tid) {
    #pragma unroll
    for (int it = 0; it < ITEMS; it++) {
        int v = tid + it * 256;
        int row = v >> 3, c16 = (v & 7) * 16;
        cp16(dstBase + SWZ(row * 128 + c16), src + (size_t)row * strideB + c16);
    }
}

// ---------------- pre-split kernels ----------------
__global__ void __launch_bounds__(256) split_kernel(
    const float* __restrict__ s0, const float* __restrict__ s1,
    const float* __restrict__ s2, const float* __restrict__ s3,
    __half* h0, __half* h1, __half* h2, __half* h3,
    __half* l0, __half* l1, __half* l2, __half* l3, int n)
{
    int z = blockIdx.z;
    const float* s = z==0?s0 : z==1?s1 : z==2?s2 : s3;
    __half* h = z==0?h0 : z==1?h1 : z==2?h2 : h3;
    __half* l = z==0?l0 : z==1?l1 : z==2?l2 : l3;
    int i = (blockIdx.x * 256 + threadIdx.x) * 4;
    if (i >= n) return;
    float4 x = *(const float4*)(s + i);
    uint2 hi, lo;
    split4h(x, hi, lo);
    *(uint2*)(h + i) = hi;
    if (l) *(uint2*)(l + i) = lo;
}

__global__ void zero_rowsum_kernel(float* rs) {
    rs[(size_t)blockIdx.x * 256 + threadIdx.x] = 0.0f;
}

// ---------------- projection kernel (q/k/v merged via z) ----------------
struct ProjArgs {
    const __half* ah[3]; const __half* al[3]; const __half* bh[3];
    const float*  bias[3];
    __half* ch[3]; __half* cl[3];
};

__global__ void __launch_bounds__(256, 2) proj_kernel(ProjArgs P)
{
    constexpr int NF = 4, NC = 16;
    constexpr int BUF = 49152;
    extern __shared__ char smem[];
    const uint32_t sb = smem_u32(smem);
    const int tid = threadIdx.x, wid = tid >> 5, lid = tid & 31;
    const int warp_m = wid >> 2, warp_n = wid & 3;
    const int m0 = blockIdx.y * 128, col0 = blockIdx.x * 128, z = blockIdx.z;

    const char* Ah = (const char*)P.ah[z];
    const char* Al = (const char*)P.al[z];
    const char* Bh = (const char*)P.bh[z];
    const float* bias = P.bias[z];
    __half* Ch = P.ch[z];
    __half* Cl = P.cl[z];

    float acc[4][NF][4];
    #pragma unroll
    for (int i=0;i<4;i++) for (int j=0;j<NF;j++) for (int t=0;t<4;t++) acc[i][j][t]=0.0f;

    const uint32_t a_base = (uint32_t)((warp_m*64 + (lid&15))*128 + ((lid>>4)<<4));
    const uint32_t b_base = (uint32_t)((warp_n*32 + ((lid>>4)<<3) + (lid&7))*128
                                       + (((lid>>3)&1)<<4));

    auto stage = [&](int ci, int bi) {
        size_t aofs = ((size_t)m0 * DM + ci * 64) * 2;
        size_t bofs = ((size_t)col0 * DM + ci * 64) * 2;
        uint32_t d = sb + bi * BUF;
        stage_cp<4>(d,         Ah + aofs, DM*2, tid);
        stage_cp<4>(d + 16384, Al + aofs, DM*2, tid);
        stage_cp<4>(d + 32768, Bh + bofs, DM*2, tid);
    };

    stage(0, 0); cp_commit();
    for (int ci = 0; ci < NC; ci++) {
        if (ci + 1 < NC) { stage(ci+1, (ci+1)&1); cp_commit(); cp_wait1(); }
        else cp_wait0();
        __syncthreads();
        uint32_t d = sb + (ci&1) * BUF;
        compute_chunk<NF>(d, d + 16384, d + 32768, a_base, b_base, acc);
        __syncthreads();
    }

    #pragma unroll
    for (int mf = 0; mf < 4; mf++)
        #pragma unroll
        for (int nf = 0; nf < NF; nf++) {
            int r  = m0 + warp_m*64 + mf*16 + (lid>>2);
            int cc = col0 + warp_n*32 + nf*8 + (lid&3)*2;
            float bv0 = __ldg(bias + cc), bv1 = __ldg(bias + cc + 1);
            #pragma unroll
            for (int half = 0; half < 2; half++) {
                int gr = r + half*8;
                float v0 = acc[mf][nf][half*2+0] + bv0;
                float v1 = acc[mf][nf][half*2+1] + bv1;
                int b = gr >> 11, s = gr & (SS-1), h = cc >> 6, dd = cc & (DK-1);
                size_t idx = ((((size_t)b*HH + h)*SS) + s)*DK + dd;
                __half hh, ll;
                split1h(v0, hh, ll); Ch[idx] = hh;   if (Cl) Cl[idx] = ll;
                split1h(v1, hh, ll); Ch[idx+1] = hh; if (Cl) Cl[idx+1] = ll;
            }
        }
}

// ---------------- scores kernel: E = exp(Q K^T / 8) -> hi/lo fp16 planes ----
__global__ void __launch_bounds__(256, 2) scores_kernel(
    const __half* __restrict__ Qh, const __half* __restrict__ Ql,
    const __half* __restrict__ Kh,
    __half* __restrict__ Eh, __half* __restrict__ El,
    float* __restrict__ rowsum)
{
    constexpr int NF = 4;
    extern __shared__ char smem[];
    const uint32_t sb = smem_u32(smem);
    const int tid = threadIdx.x, wid = tid >> 5, lid = tid & 31;
    const int warp_m = wid >> 2, warp_n = wid & 3;
    const int m0 = blockIdx.y * 128, col0 = blockIdx.x * 128, z = blockIdx.z;

    const char* Ah = (const char*)(Qh + (size_t)z*SS*DK + (size_t)m0*DK);
    const char* Al = (const char*)(Ql + (size_t)z*SS*DK + (size_t)m0*DK);
    const char* Bh = (const char*)(Kh + (size_t)z*SS*DK + (size_t)col0*DK);

    float acc[4][NF][4];
    #pragma unroll
    for (int i=0;i<4;i++) for (int j=0;j<NF;j++) for (int t=0;t<4;t++) acc[i][j][t]=0.0f;

    const uint32_t a_base = (uint32_t)((warp_m*64 + (lid&15))*128 + ((lid>>4)<<4));
    const uint32_t b_base = (uint32_t)((warp_n*32 + ((lid>>4)<<3) + (lid&7))*128
                                       + (((lid>>3)&1)<<4));

    stage_cp<4>(sb,         Ah, 128, tid);
    stage_cp<4>(sb + 16384, Al, 128, tid);
    stage_cp<4>(sb + 32768, Bh, 128, tid);
    cp_commit(); cp_wait0();
    __syncthreads();
    compute_chunk<NF>(sb, sb + 16384, sb + 32768, a_base, b_base, acc);

    #pragma unroll
    for (int mf = 0; mf < 4; mf++) {
        #pragma unroll
        for (int half = 0; half < 2; half++) {
            int gr = m0 + warp_m*64 + mf*16 + (lid>>2) + half*8;
            float rs = 0.0f;
            #pragma unroll
            for (int nf = 0; nf < NF; nf++) {
                int cc = col0 + warp_n*32 + nf*8 + (lid&3)*2;
                float e0 = __expf(acc[mf][nf][half*2+0] * 0.125f);
                float e1 = __expf(acc[mf][nf][half*2+1] * 0.125f);
                size_t idx = (size_t)z*SS*SS + (size_t)gr*SS + cc;
                __half h0,l0,h1,l1;
                split1h(e0, h0, l0); split1h(e1, h1, l1);
                *(__half2*)(Eh + idx) = __halves2half2(h0, h1);
                *(__half2*)(El + idx) = __halves2half2(l0, l1);
                rs += e0 + e1;
            }
            rs += __shfl_xor_sync(0xffffffffu, rs, 1);
            rs += __shfl_xor_sync(0xffffffffu, rs, 2);
            if ((lid & 3) == 0) atomicAdd(&rowsum[(size_t)z*SS + gr], rs);
        }
    }
}

// ---------------- AV kernel: ctx = inv[m] * (E @ V) ----------------
// smem: PH0 16K | PL0 16K | PH1 16K | PL1 16K | VB0 8K | VB1 8K | INV 512
//       = 82432 B -> 2 CTAs/SM
__global__ void __launch_bounds__(256, 2) av_kernel(
    const __half* __restrict__ Eh, const __half* __restrict__ El,
    const __half* __restrict__ Vh,
    const float* __restrict__ rowsum,
    __half* __restrict__ Ch, __half* __restrict__ Cl,
    float* __restrict__ attn_wb, int write_attn)
{
    constexpr int NF = 2, NC = 32;
    constexpr int PH0 = 0, PL0 = 16384, PH1 = 32768, PL1 = 49152;
    constexpr int VB0 = 65536, VB1 = 73728, INV = 81920;
    extern __shared__ char smem[];
    const uint32_t sb = smem_u32(smem);
    const int tid = threadIdx.x, wid = tid >> 5, lid = tid & 31;
    const int warp_m = wid >> 2, warp_n = wid & 3;
    const int m0 = blockIdx.y * 128, z = blockIdx.z;

    const char* Ehb = (const char*)(Eh + (size_t)z*SS*SS + (size_t)m0*SS);
    const char* Elb = (const char*)(El + (size_t)z*SS*SS + (size_t)m0*SS);
    const __half* Vb = Vh + (size_t)z*SS*DK;
    float* wb = attn_wb + (size_t)z*SS*SS + (size_t)m0*SS;

    if (tid < 128)
        *(float*)(smem + INV + tid*4) = 1.0f / rowsum[(size_t)z*SS + m0 + tid];

    float acc[4][NF][4];
    #pragma unroll
    for (int i=0;i<4;i++) for (int j=0;j<NF;j++) for (int t=0;t<4;t++) acc[i][j][t]=0.0f;

    const uint32_t a_base = (uint32_t)((warp_m*64 + (lid&15))*128 + ((lid>>4)<<4));
    const uint32_t b_base = (uint32_t)((warp_n*16 + ((lid>>4)<<3) + (lid&7))*128
                                       + (((lid>>3)&1)<<4));

    auto stageP = [&](int ci, int bi) {        // pure cp.async of both planes
        stage_cp<4>(sb + (bi ? PH1 : PH0), Ehb + ci*128, SS*2, tid);
        stage_cp<4>(sb + (bi ? PL1 : PL0), Elb + ci*128, SS*2, tid);
    };
    auto stageV = [&](int ci, int bi) {        // scalar transpose V[t,d] -> smem[d][t]
        #pragma unroll
        for (int it = 0; it < 4; it++) {
            int v = tid + it*256;
            int tt = v >> 4, d0 = (v & 15) << 2;
            uint2 hv = *(const uint2*)(Vb + (size_t)(ci*64 + tt)*DK + d0);
            ushort hs[4];
            hs[0] = hv.x & 0xFFFF; hs[1] = hv.x >> 16;
            hs[2] = hv.y & 0xFFFF; hs[3] = hv.y >> 16;
            #pragma unroll
            for (int j = 0; j < 4; j++)
                *(ushort*)(smem + (bi ? VB1 : VB0) + SWZ((d0+j)*128 + (tt<<1))) = hs[j];
        }
    };
    auto writeback = [&](int ci) {             // attn fp32 = (h+l)*inv from smem planes
        const char* ph = smem + ((ci&1) ? PH1 : PH0);
        const char* pl = smem + ((ci&1) ? PL1 : PL0);
        #pragma unroll
        for (int it = 0; it < 4; it++) {
            int v = tid + it*256;
            int row = v >> 3, c8 = (v & 7) << 3;      // 8 halves per thread-item
            float inv = *(const float*)(smem + INV + row*4);
            int so = SWZ(row*128 + c8*2);
            uint4 hv = *(const uint4*)(ph + so);
            uint4 lv = *(const uint4*)(pl + so);
            float4 o0, o1;
            {
                float2 a = __half22float2(*(__half2*)&hv.x), b = __half22float2(*(__half2*)&lv.x);
                o0.x = (a.x + b.x)*inv; o0.y = (a.y + b.y)*inv;
                float2 c = __half22float2(*(__half2*)&hv.y), d = __half22float2(*(__half2*)&lv.y);
                o0.z = (c.x + d.x)*inv; o0.w = (c.y + d.y)*inv;
                float2 e = __half22float2(*(__half2*)&hv.z), f = __half22float2(*(__half2*)&lv.z);
                o1.x = (e.x + f.x)*inv; o1.y = (e.y + f.y)*inv;
                float2 g = __half22float2(*(__half2*)&hv.w), h = __half22float2(*(__half2*)&lv.w);
                o1.z = (g.x + h.x)*inv; o1.w = (g.y + h.y)*inv;
            }
            *(float4*)(wb + (size_t)row*SS + ci*64 + c8)     = o0;
            *(float4*)(wb + (size_t)row*SS + ci*64 + c8 + 4) = o1;
        }
    };

    stageP(0, 0); cp_commit();
    stageV(0, 0);

    for (int ci = 0; ci < NC; ci++) {
        if (ci + 1 < NC) { stageP(ci+1, (ci+1)&1); cp_commit(); cp_wait1(); }
        else cp_wait0();
        __syncthreads();                       // planes(ci) + V(ci) + INV visible
        if (ci + 1 < NC) stageV(ci+1, (ci+1)&1);
        compute_chunk<NF>(sb + ((ci&1) ? PH1 : PH0), sb + ((ci&1) ? PL1 : PL0),
                          sb + ((ci&1) ? VB1 : VB0), a_base, b_base, acc);
        if (write_attn) writeback(ci);
        __syncthreads();
    }

    #pragma unroll
    for (int mf = 0; mf < 4; mf++)
        #pragma unroll
        for (int nf = 0; nf < NF; nf++) {
            int r  = m0 + warp_m*64 + mf*16 + (lid>>2);
            int cc = warp_n*16 + nf*8 + (lid&3)*2;
            #pragma unroll
            for (int half = 0; half < 2; half++) {
                int gr = r + half*8;
                float inv = *(const float*)(smem + INV + (gr - m0)*4);
                float v0 = acc[mf][nf][half*2+0] * inv;
                float v1 = acc[mf][nf][half*2+1] * inv;
                int b = z >> 4, h = z & (HH-1);
                size_t idx = ((size_t)(b*SS + gr))*DM + h*DK + cc;
                __half hh, ll;
                split1h(v0, hh, ll); Ch[idx] = hh;   Cl[idx] = ll;
                split1h(v1, hh, ll); Ch[idx+1] = hh; Cl[idx+1] = ll;
            }
        }
}

// ---------------- output projection ----------------
__global__ void __launch_bounds__(256, 2) outproj_kernel(
    const __half* __restrict__ Ah, const __half* __restrict__ Al,
    const __half* __restrict__ Bh, const float* __restrict__ bias,
    float* __restrict__ out)
{
    constexpr int NF = 4, NC = 16;
    constexpr int BUF = 49152;
    extern __shared__ char smem[];
    const uint32_t sb = smem_u32(smem);
    const int tid = threadIdx.x, wid = tid >> 5, lid = tid & 31;
    const int warp_m = wid >> 2, warp_n = wid & 3;
    const int m0 = blockIdx.y * 128, col0 = blockIdx.x * 128;

    float acc[4][NF][4];
    #pragma unroll
    for (int i=0;i<4;i++) for (int j=0;j<NF;j++) for (int t=0;t<4;t++) acc[i][j][t]=0.0f;

    const uint32_t a_base = (uint32_t)((warp_m*64 + (lid&15))*128 + ((lid>>4)<<4));
    const uint32_t b_base = (uint32_t)((warp_n*32 + ((lid>>4)<<3) + (lid&7))*128
                                       + (((lid>>3)&1)<<4));

    auto stage = [&](int ci, int bi) {
        size_t aofs = ((size_t)m0 * DM + ci*64) * 2;
        size_t bofs = ((size_t)col0 * DM + ci*64) * 2;
        uint32_t d = sb + bi * BUF;
        stage_cp<4>(d,         (const char*)Ah + aofs, DM*2, tid);
        stage_cp<4>(d + 16384, (const char*)Al + aofs, DM*2, tid);
        stage_cp<4>(d + 32768, (const char*)Bh + bofs, DM*2, tid);
    };

    stage(0, 0); cp_commit();
    for (int ci = 0; ci < NC; ci++) {
        if (ci + 1 < NC) { stage(ci+1, (ci+1)&1); cp_commit(); cp_wait1(); }
        else cp_wait0();
        __syncthreads();
        uint32_t d = sb + (ci&1) * BUF;
        compute_chunk<NF>(d, d + 16384, d + 32768, a_base, b_base, acc);
        __syncthreads();
    }

    #pragma unroll
    for (int mf = 0; mf < 4; mf++)
        #pragma unroll
        for (int nf = 0; nf < NF; nf++) {
            int r  = m0 + warp_m*64 + mf*16 + (lid>>2);
            int cc = col0 + warp_n*32 + nf*8 + (lid&3)*2;
            float bv0 = __ldg(bias + cc), bv1 = __ldg(bias + cc + 1);
            #pragma unroll
            for (int half = 0; half < 2; half++) {
                int gr = r + half*8;
                size_t idx = (size_t)gr*DM + cc;
                out[idx]   = acc[mf][nf][half*2+0] + bv0;
                out[idx+1] = acc[mf][nf][half*2+1] + bv1;
            }
        }
}

// ---------------------------------------------------------------------------
extern "C" void kernel_launch(void* const* d_in, const int* in_sizes, int n_in,
                              void* d_out, int out_size)
{
    const float* q   = (const float*)d_in[0];
    const float* k   = (const float*)d_in[1];
    const float* v   = (const float*)d_in[2];
    const float* w_q = (const float*)d_in[3];
    const float* b_q = (const float*)d_in[4];
    const float* w_k = (const float*)d_in[5];
    const float* b_k = (const float*)d_in[6];
    const float* w_v = (const float*)d_in[7];
    const float* b_v = (const float*)d_in[8];
    const float* w_o = (const float*)d_in[9];
    const float* b_o = (const float*)d_in[10];
    float* out = (float*)d_out;

    __half *in_h, *in_l, *w_h, *qh_h, *qh_l, *kh_h, *vh_h, *cx_h, *cx_l;
    cudaGetSymbolAddress((void**)&in_h, g_in_h);
    cudaGetSymbolAddress((void**)&in_l, g_in_l);
    cudaGetSymbolAddress((void**)&w_h,  g_w_h);
    cudaGetSymbolAddress((void**)&qh_h, g_qh_h);
    cudaGetSymbolAddress((void**)&qh_l, g_qh_l);
    cudaGetSymbolAddress((void**)&kh_h, g_kh_h);
    cudaGetSymbolAddress((void**)&vh_h, g_vh_h);
    cudaGetSymbolAddress((void**)&cx_h, g_cx_h);
    cudaGetSymbolAddress((void**)&cx_l, g_cx_l);
    float* rowsum; cudaGetSymbolAddress((void**)&rowsum, g_rowsum);

    // E hi/lo planes live in g_attn scratch (2 x ATTN_ELEMS halves = 1 GB)
    __half* planes;
    cudaGetSymbolAddress((void**)&planes, g_attn);
    __half* Eh = planes;
    __half* El = planes + ATTN_ELEMS;

    const size_t NN = (size_t)MROWS * DM;
    const size_t WW = (size_t)DM * DM;

    float* attn_wb = nullptr;
    int write_attn = 0;
    if ((size_t)out_size >= OUT_ELEMS + ATTN_ELEMS) {
        attn_wb = out + OUT_ELEMS;
        write_attn = 1;
    }

    const int SMP = 2 * 49152;                 // 96 KB proj / outproj
    const int SMS = 49152;                     // 48 KB scores
    const int SMA = 82432;                     // AV (2 CTAs/SM)
    cudaFuncSetAttribute(proj_kernel,    cudaFuncAttributeMaxDynamicSharedMemorySize, SMP);
    cudaFuncSetAttribute(outproj_kernel, cudaFuncAttributeMaxDynamicSharedMemorySize, SMP);
    cudaFuncSetAttribute(scores_kernel,  cudaFuncAttributeMaxDynamicSharedMemorySize, SMS);
    cudaFuncSetAttribute(av_kernel,      cudaFuncAttributeMaxDynamicSharedMemorySize, SMA);

    split_kernel<<<dim3((int)(NN/4/256), 1, 3), 256>>>(
        q, k, v, q,
        in_h, in_h + NN, in_h + 2*NN, in_h,
        in_l, in_l + NN, in_l + 2*NN, in_l, (int)NN);
    split_kernel<<<dim3((int)(WW/4/256), 1, 4), 256>>>(
        w_q, w_k, w_v, w_o,
        w_h, w_h + WW, w_h + 2*WW, w_h + 3*WW,
        nullptr, nullptr, nullptr, nullptr, (int)WW);

    zero_rowsum_kernel<<<dim3(BB*HH*SS/256), 256>>>(rowsum);

    ProjArgs P;
    P.ah[0] = in_h;        P.ah[1] = in_h + NN;   P.ah[2] = in_h + 2*NN;
    P.al[0] = in_l;        P.al[1] = in_l + NN;   P.al[2] = in_l + 2*NN;
    P.bh[0] = w_h;         P.bh[1] = w_h + WW;    P.bh[2] = w_h + 2*WW;
    P.bias[0] = b_q;       P.bias[1] = b_k;       P.bias[2] = b_v;
    P.ch[0] = qh_h;        P.ch[1] = kh_h;        P.ch[2] = vh_h;
    P.cl[0] = qh_l;        P.cl[1] = nullptr;     P.cl[2] = nullptr;
    proj_kernel<<<dim3(DM/128, MROWS/128, 3), 256, SMP>>>(P);

    scores_kernel<<<dim3(SS/128, SS/128, BB*HH), 256, SMS>>>(
        qh_h, qh_l, kh_h, Eh, El, rowsum);

    av_kernel<<<dim3(1, SS/128, BB*HH), 256, SMA>>>(
        Eh, El, vh_h, rowsum, cx_h, cx_l, attn_wb, write_attn);

    outproj_kernel<<<dim3(DM/128, MROWS/128), 256, SMP>>>(
        cx_h, cx_l, w_h + 3*WW, b_o, out);
}

// round 11
// speedup vs baseline: 3.6789x; 1.1075x over previous
#include <cuda_runtime.h>
#include <cuda_fp16.h>
#include <cstdint>

// ---------------- problem constants ----------------
#define BB 4
#define SS 2048
#define HH 16
#define DK 64
#define DM 1024
#define MROWS (BB*SS)                        // 8192
#define OUT_ELEMS ((size_t)MROWS*DM)         // 8,388,608
#define ATTN_ELEMS ((size_t)BB*HH*SS*SS)     // 268,435,456

// ---------------- device-global scratch ----------------
__device__ __half g_in_h[3][(size_t)MROWS*DM], g_in_l[3][(size_t)MROWS*DM];
__device__ __half g_w_h[4][(size_t)DM*DM];
__device__ __half g_qh_h[(size_t)MROWS*DM], g_qh_l[(size_t)MROWS*DM];
__device__ __half g_kh_h[(size_t)MROWS*DM];
__device__ __half g_vh_h[(size_t)MROWS*DM];
__device__ __half g_cx_h[(size_t)MROWS*DM], g_cx_l[(size_t)MROWS*DM];
__device__ float g_rowsum[(size_t)BB*HH*SS];

// ---------------- helpers ----------------
#define SWZ(o) ((o) ^ (((o) >> 3) & 0x70))

__device__ __forceinline__ uint32_t smem_u32(const void* p) {
    uint32_t a;
    asm("{ .reg .u64 t; cvta.to.shared.u64 t, %1; cvt.u32.u64 %0, t; }"
        : "=r"(a) : "l"(p));
    return a;
}
__device__ __forceinline__ void cp16(uint32_t dst, const void* src) {
    asm volatile("cp.async.cg.shared.global [%0], [%1], 16;" :: "r"(dst), "l"(src) : "memory");
}
__device__ __forceinline__ void cp_commit() { asm volatile("cp.async.commit_group;" ::: "memory"); }
__device__ __forceinline__ void cp_wait0()  { asm volatile("cp.async.wait_group 0;" ::: "memory"); }
__device__ __forceinline__ void cp_wait1()  { asm volatile("cp.async.wait_group 1;" ::: "memory"); }

__device__ __forceinline__ void ldm_x4(uint32_t addr, uint32_t& r0, uint32_t& r1,
                                       uint32_t& r2, uint32_t& r3) {
    asm volatile("ldmatrix.sync.aligned.m8n8.x4.shared.b16 {%0,%1,%2,%3}, [%4];"
                 : "=r"(r0), "=r"(r1), "=r"(r2), "=r"(r3) : "r"(addr));
}
__device__ __forceinline__ void mma_f16(float* c, uint32_t a0, uint32_t a1,
                                        uint32_t a2, uint32_t a3,
                                        uint32_t b0, uint32_t b1) {
    asm volatile("mma.sync.aligned.m16n8k16.row.col.f32.f16.f16.f32 "
                 "{%0,%1,%2,%3}, {%4,%5,%6,%7}, {%8,%9}, {%0,%1,%2,%3};"
                 : "+f"(c[0]), "+f"(c[1]), "+f"(c[2]), "+f"(c[3])
                 : "r"(a0), "r"(a1), "r"(a2), "r"(a3), "r"(b0), "r"(b1));
}
__device__ __forceinline__ uint32_t pk2h(__half a, __half b) {
    __half2 t = __halves2half2(a, b);
    return *(uint32_t*)&t;
}
__device__ __forceinline__ void split1h(float x, __half& h, __half& l) {
    h = __float2half_rn(x);
    l = __float2half_rn(x - __half2float(h));
}
__device__ __forceinline__ void split4h(float4 x, uint2& hi, uint2& lo) {
    __half h0,h1,h2,h3,l0,l1,l2,l3;
    split1h(x.x,h0,l0); split1h(x.y,h1,l1); split1h(x.z,h2,l2); split1h(x.w,h3,l3);
    hi = make_uint2(pk2h(h0,h1), pk2h(h2,h3));
    lo = make_uint2(pk2h(l0,l1), pk2h(l2,l3));
}

// fp16x2 compute: 4 ksteps of k16 over one staged 64-K chunk.
template<int NF>
__device__ __forceinline__ void compute_chunk(uint32_t aHi, uint32_t aLo, uint32_t bHi,
                                              uint32_t a_base, uint32_t b_base,
                                              float (&acc)[4][NF][4]) {
    #pragma unroll
    for (int ks = 0; ks < 4; ks++) {
        uint32_t bf[2*NF];
        #pragma unroll
        for (int ng = 0; ng < NF/2; ng++) {
            uint32_t ofs = b_base + (uint32_t)(ng * 16 * 128 + ks * 32);
            ldm_x4(bHi + SWZ(ofs), bf[4*ng], bf[4*ng+1], bf[4*ng+2], bf[4*ng+3]);
        }
        #pragma unroll
        for (int mf = 0; mf < 4; mf++) {
            uint32_t ofs = a_base + (uint32_t)(mf * 16 * 128 + ks * 32);
            uint32_t h0,h1,h2,h3, l0,l1,l2,l3;
            ldm_x4(aHi + SWZ(ofs), h0,h1,h2,h3);
            ldm_x4(aLo + SWZ(ofs), l0,l1,l2,l3);
            #pragma unroll
            for (int nf = 0; nf < NF; nf++) {
                mma_f16(acc[mf][nf], h0,h1,h2,h3, bf[2*nf], bf[2*nf+1]);
                mma_f16(acc[mf][nf], l0,l1,l2,l3, bf[2*nf], bf[2*nf+1]);
            }
        }
    }
}

template<int ITEMS>
__device__ __forceinline__ void stage_cp(uint32_t dstBase, const char* src,
                                         size_t strideB, int tid) {
    #pragma unroll
    for (int it = 0; it < ITEMS; it++) {
        int v = tid + it * 256;
        int row = v >> 3, c16 = (v & 7) * 16;
        cp16(dstBase + SWZ(row * 128 + c16), src + (size_t)row * strideB + c16);
    }
}

// ---------------- pre-split kernels ----------------
__global__ void __launch_bounds__(256) split_kernel(
    const float* __restrict__ s0, const float* __restrict__ s1,
    const float* __restrict__ s2, const float* __restrict__ s3,
    __half* h0, __half* h1, __half* h2, __half* h3,
    __half* l0, __half* l1, __half* l2, __half* l3, int n)
{
    int z = blockIdx.z;
    const float* s = z==0?s0 : z==1?s1 : z==2?s2 : s3;
    __half* h = z==0?h0 : z==1?h1 : z==2?h2 : h3;
    __half* l = z==0?l0 : z==1?l1 : z==2?l2 : l3;
    int i = (blockIdx.x * 256 + threadIdx.x) * 4;
    if (i >= n) return;
    float4 x = *(const float4*)(s + i);
    uint2 hi, lo;
    split4h(x, hi, lo);
    *(uint2*)(h + i) = hi;
    if (l) *(uint2*)(l + i) = lo;
}

// ---------------- projection kernel (q/k/v merged via z) ----------------
struct ProjArgs {
    const __half* ah[3]; const __half* al[3]; const __half* bh[3];
    const float*  bias[3];
    __half* ch[3]; __half* cl[3];
};

__global__ void __launch_bounds__(256, 2) proj_kernel(ProjArgs P)
{
    constexpr int NF = 4, NC = 16;
    constexpr int BUF = 49152;
    extern __shared__ char smem[];
    const uint32_t sb = smem_u32(smem);
    const int tid = threadIdx.x, wid = tid >> 5, lid = tid & 31;
    const int warp_m = wid >> 2, warp_n = wid & 3;
    const int m0 = blockIdx.y * 128, col0 = blockIdx.x * 128, z = blockIdx.z;

    const char* Ah = (const char*)P.ah[z];
    const char* Al = (const char*)P.al[z];
    const char* Bh = (const char*)P.bh[z];
    const float* bias = P.bias[z];
    __half* Ch = P.ch[z];
    __half* Cl = P.cl[z];

    float acc[4][NF][4];
    #pragma unroll
    for (int i=0;i<4;i++) for (int j=0;j<NF;j++) for (int t=0;t<4;t++) acc[i][j][t]=0.0f;

    const uint32_t a_base = (uint32_t)((warp_m*64 + (lid&15))*128 + ((lid>>4)<<4));
    const uint32_t b_base = (uint32_t)((warp_n*32 + ((lid>>4)<<3) + (lid&7))*128
                                       + (((lid>>3)&1)<<4));

    auto stage = [&](int ci, int bi) {
        size_t aofs = ((size_t)m0 * DM + ci * 64) * 2;
        size_t bofs = ((size_t)col0 * DM + ci * 64) * 2;
        uint32_t d = sb + bi * BUF;
        stage_cp<4>(d,         Ah + aofs, DM*2, tid);
        stage_cp<4>(d + 16384, Al + aofs, DM*2, tid);
        stage_cp<4>(d + 32768, Bh + bofs, DM*2, tid);
    };

    stage(0, 0); cp_commit();
    for (int ci = 0; ci < NC; ci++) {
        if (ci + 1 < NC) { stage(ci+1, (ci+1)&1); cp_commit(); cp_wait1(); }
        else cp_wait0();
        __syncthreads();
        uint32_t d = sb + (ci&1) * BUF;
        compute_chunk<NF>(d, d + 16384, d + 32768, a_base, b_base, acc);
        __syncthreads();
    }

    #pragma unroll
    for (int mf = 0; mf < 4; mf++)
        #pragma unroll
        for (int nf = 0; nf < NF; nf++) {
            int r  = m0 + warp_m*64 + mf*16 + (lid>>2);
            int cc = col0 + warp_n*32 + nf*8 + (lid&3)*2;
            float bv0 = __ldg(bias + cc), bv1 = __ldg(bias + cc + 1);
            #pragma unroll
            for (int half = 0; half < 2; half++) {
                int gr = r + half*8;
                float v0 = acc[mf][nf][half*2+0] + bv0;
                float v1 = acc[mf][nf][half*2+1] + bv1;
                int b = gr >> 11, s = gr & (SS-1), h = cc >> 6, dd = cc & (DK-1);
                size_t idx = ((((size_t)b*HH + h)*SS) + s)*DK + dd;
                __half hh, ll;
                split1h(v0, hh, ll); Ch[idx] = hh;   if (Cl) Cl[idx] = ll;
                split1h(v1, hh, ll); Ch[idx+1] = hh; if (Cl) Cl[idx+1] = ll;
            }
        }
}

// ---------------- pass A: rowsum[z, m] = sum_t exp(QK^T/8) ----------------
// smem: QH 16K | QL 16K | KB0 16K | KB1 16K | RS 512  = 66048
__global__ void __launch_bounds__(256, 2) rowsum_kernel(
    const __half* __restrict__ Qh, const __half* __restrict__ Ql,
    const __half* __restrict__ Kh, float* __restrict__ rowsum)
{
    constexpr int QH = 0, QL = 16384, KB0 = 32768, KB1 = 49152, RS = 65536;
    extern __shared__ char smem[];
    const uint32_t sb = smem_u32(smem);
    const int tid = threadIdx.x, wid = tid >> 5, lid = tid & 31;
    const int warp_m = wid >> 2, warp_n = wid & 3;
    const int m0 = blockIdx.y * 128, z = blockIdx.z;

    const char* Qhp = (const char*)(Qh + (size_t)z*SS*DK + (size_t)m0*DK);
    const char* Qlp = (const char*)(Ql + (size_t)z*SS*DK + (size_t)m0*DK);
    const char* Kp  = (const char*)(Kh + (size_t)z*SS*DK);

    if (tid < 128) *(float*)(smem + RS + tid*4) = 0.0f;

    const uint32_t a_base = (uint32_t)((warp_m*64 + (lid&15))*128 + ((lid>>4)<<4));
    const uint32_t b_base = (uint32_t)((warp_n*32 + ((lid>>4)<<3) + (lid&7))*128
                                       + (((lid>>3)&1)<<4));

    stage_cp<4>(sb + QH, Qhp, 128, tid);
    stage_cp<4>(sb + QL, Qlp, 128, tid);
    stage_cp<4>(sb + KB0, Kp, 128, tid);
    cp_commit();

    float rsum[4][2];
    #pragma unroll
    for (int i=0;i<4;i++) { rsum[i][0]=0.0f; rsum[i][1]=0.0f; }

    for (int j = 0; j < 16; j++) {
        if (j + 1 < 16) {
            stage_cp<4>(sb + (((j+1)&1) ? KB1 : KB0), Kp + (size_t)(j+1)*16384, 128, tid);
            cp_commit(); cp_wait1();
        } else cp_wait0();
        __syncthreads();
        float sacc[4][4][4];
        #pragma unroll
        for (int i=0;i<4;i++) for (int n=0;n<4;n++) for (int t=0;t<4;t++) sacc[i][n][t]=0.0f;
        compute_chunk<4>(sb + QH, sb + QL, sb + ((j&1) ? KB1 : KB0), a_base, b_base, sacc);
        #pragma unroll
        for (int mf = 0; mf < 4; mf++)
            #pragma unroll
            for (int half = 0; half < 2; half++)
                #pragma unroll
                for (int nf = 0; nf < 4; nf++)
                    rsum[mf][half] += __expf(sacc[mf][nf][half*2+0]*0.125f)
                                    + __expf(sacc[mf][nf][half*2+1]*0.125f);
        __syncthreads();
    }

    #pragma unroll
    for (int mf = 0; mf < 4; mf++)
        #pragma unroll
        for (int half = 0; half < 2; half++) {
            float v = rsum[mf][half];
            v += __shfl_xor_sync(0xffffffffu, v, 1);
            v += __shfl_xor_sync(0xffffffffu, v, 2);
            if ((lid & 3) == 0) {
                int rloc = warp_m*64 + mf*16 + (lid>>2) + half*8;
                atomicAdd((float*)(smem + RS + rloc*4), v);
            }
        }
    __syncthreads();
    if (tid < 128) rowsum[(size_t)z*SS + m0 + tid] = *(float*)(smem + RS + tid*4);
}

// ---------------- pass B: fused scores+AV ----------------
// Per (z, m-block): recompute S chunk, E=exp, write normalized attn fp32
// (optional), E->smem planes, ctx += E @ V. Epilogue: ctx*inv -> planes.
// smem: QH 0 | QL 16K | KB0 32K | KB1 48K | VB0 64K | VB1 80K
//       | EH 96K(32K) | EL 128K(32K) | INV 160K(512)  = 164352
__global__ void __launch_bounds__(256, 1) fusedav_kernel(
    const __half* __restrict__ Qh, const __half* __restrict__ Ql,
    const __half* __restrict__ Kh, const __half* __restrict__ Vh,
    const float* __restrict__ rowsum,
    __half* __restrict__ Ch, __half* __restrict__ Cl,
    float* __restrict__ attn_wb, int write_attn)
{
    constexpr int QH = 0, QL = 16384, KB0 = 32768, KB1 = 49152;
    constexpr int VB0 = 65536, VB1 = 81920;
    constexpr int EH = 98304, EL = 131072, INV = 163840;
    extern __shared__ char smem[];
    const uint32_t sb = smem_u32(smem);
    const int tid = threadIdx.x, wid = tid >> 5, lid = tid & 31;
    const int warp_m = wid >> 2, warp_n = wid & 3;
    const int m0 = blockIdx.y * 128, z = blockIdx.z;

    const char* Qhp = (const char*)(Qh + (size_t)z*SS*DK + (size_t)m0*DK);
    const char* Qlp = (const char*)(Ql + (size_t)z*SS*DK + (size_t)m0*DK);
    const char* Kp  = (const char*)(Kh + (size_t)z*SS*DK);
    const __half* Vb = Vh + (size_t)z*SS*DK;
    float* wb = attn_wb ? (attn_wb + (size_t)z*SS*SS + (size_t)m0*SS) : nullptr;

    if (tid < 128)
        *(float*)(smem + INV + tid*4) = 1.0f / rowsum[(size_t)z*SS + m0 + tid];

    const uint32_t a_base  = (uint32_t)((warp_m*64 + (lid&15))*128 + ((lid>>4)<<4));
    const uint32_t b_baseS = (uint32_t)((warp_n*32 + ((lid>>4)<<3) + (lid&7))*128
                                        + (((lid>>3)&1)<<4));
    const uint32_t b_baseV = (uint32_t)((warp_n*16 + ((lid>>4)<<3) + (lid&7))*128
                                        + (((lid>>3)&1)<<4));

    auto stageV = [&](int j, int bi) {   // V[t,d] chunk (128 t) -> smem [d][t] 2 subtiles
        #pragma unroll
        for (int it = 0; it < 8; it++) {
            int v = tid + it*256;
            int tt = v >> 4, d0 = (v & 15) << 2;
            uint2 hv = *(const uint2*)(Vb + (size_t)(j*128 + tt)*DK + d0);
            ushort hs[4];
            hs[0] = hv.x & 0xFFFF; hs[1] = hv.x >> 16;
            hs[2] = hv.y & 0xFFFF; hs[3] = hv.y >> 16;
            int base = (bi ? VB1 : VB0) + (tt >> 6) * 8192;
            #pragma unroll
            for (int jj = 0; jj < 4; jj++)
                *(ushort*)(smem + base + SWZ((d0+jj)*128 + ((tt & 63) << 1))) = hs[jj];
        }
    };

    stage_cp<4>(sb + QH, Qhp, 128, tid);
    stage_cp<4>(sb + QL, Qlp, 128, tid);
    stage_cp<4>(sb + KB0, Kp, 128, tid);
    cp_commit();
    stageV(0, 0);

    float ctx[4][2][4];
    #pragma unroll
    for (int i=0;i<4;i++) for (int n=0;n<2;n++) for (int t=0;t<4;t++) ctx[i][n][t]=0.0f;

    for (int j = 0; j < 16; j++) {
        if (j + 1 < 16) {
            stage_cp<4>(sb + (((j+1)&1) ? KB1 : KB0), Kp + (size_t)(j+1)*16384, 128, tid);
            cp_commit();
            stageV(j+1, (j+1)&1);
            cp_wait1();
        } else cp_wait0();
        __syncthreads();                          // K(j), V(j), Q, INV visible

        float sacc[4][4][4];
        #pragma unroll
        for (int i=0;i<4;i++) for (int n=0;n<4;n++) for (int t=0;t<4;t++) sacc[i][n][t]=0.0f;
        compute_chunk<4>(sb + QH, sb + QL, sb + ((j&1) ? KB1 : KB0), a_base, b_baseS, sacc);

        // E = exp, write attn (optional), store hi/lo planes to smem
        #pragma unroll
        for (int mf = 0; mf < 4; mf++)
            #pragma unroll
            for (int half = 0; half < 2; half++) {
                int rloc = warp_m*64 + mf*16 + (lid>>2) + half*8;
                float inv = *(const float*)(smem + INV + rloc*4);
                #pragma unroll
                for (int nf = 0; nf < 4; nf++) {
                    int cc = warp_n*32 + nf*8 + (lid&3)*2;
                    float e0 = __expf(sacc[mf][nf][half*2+0]*0.125f);
                    float e1 = __expf(sacc[mf][nf][half*2+1]*0.125f);
                    if (write_attn)
                        *(float2*)(wb + (size_t)rloc*SS + j*128 + cc)
                            = make_float2(e0*inv, e1*inv);
                    __half h0,l0,h1,l1;
                    split1h(e0, h0, l0); split1h(e1, h1, l1);
                    int st = cc >> 6;
                    int boff = st*16384 + SWZ(rloc*128 + ((cc & 63) << 1));
                    *(__half2*)(smem + EH + boff) = __halves2half2(h0, h1);
                    *(__half2*)(smem + EL + boff) = __halves2half2(l0, l1);
                }
            }
        __syncthreads();                          // E planes visible

        #pragma unroll
        for (int st = 0; st < 2; st++)
            compute_chunk<2>(sb + EH + st*16384, sb + EL + st*16384,
                             sb + ((j&1) ? VB1 : VB0) + st*8192,
                             a_base, b_baseV, ctx);
        __syncthreads();                          // protect E planes / V buffer
    }

    #pragma unroll
    for (int mf = 0; mf < 4; mf++)
        #pragma unroll
        for (int nf = 0; nf < 2; nf++) {
            int r  = m0 + warp_m*64 + mf*16 + (lid>>2);
            int cc = warp_n*16 + nf*8 + (lid&3)*2;
            #pragma unroll
            for (int half = 0; half < 2; half++) {
                int gr = r + half*8;
                float inv = *(const float*)(smem + INV + (gr - m0)*4);
                float v0 = ctx[mf][nf][half*2+0] * inv;
                float v1 = ctx[mf][nf][half*2+1] * inv;
                int b = z >> 4, h = z & (HH-1);
                size_t idx = ((size_t)(b*SS + gr))*DM + h*DK + cc;
                __half hh, ll;
                split1h(v0, hh, ll); Ch[idx] = hh;   Cl[idx] = ll;
                split1h(v1, hh, ll); Ch[idx+1] = hh; Cl[idx+1] = ll;
            }
        }
}

// ---------------- output projection ----------------
__global__ void __launch_bounds__(256, 2) outproj_kernel(
    const __half* __restrict__ Ah, const __half* __restrict__ Al,
    const __half* __restrict__ Bh, const float* __restrict__ bias,
    float* __restrict__ out)
{
    constexpr int NF = 4, NC = 16;
    constexpr int BUF = 49152;
    extern __shared__ char smem[];
    const uint32_t sb = smem_u32(smem);
    const int tid = threadIdx.x, wid = tid >> 5, lid = tid & 31;
    const int warp_m = wid >> 2, warp_n = wid & 3;
    const int m0 = blockIdx.y * 128, col0 = blockIdx.x * 128;

    float acc[4][NF][4];
    #pragma unroll
    for (int i=0;i<4;i++) for (int j=0;j<NF;j++) for (int t=0;t<4;t++) acc[i][j][t]=0.0f;

    const uint32_t a_base = (uint32_t)((warp_m*64 + (lid&15))*128 + ((lid>>4)<<4));
    const uint32_t b_base = (uint32_t)((warp_n*32 + ((lid>>4)<<3) + (lid&7))*128
                                       + (((lid>>3)&1)<<4));

    auto stage = [&](int ci, int bi) {
        size_t aofs = ((size_t)m0 * DM + ci*64) * 2;
        size_t bofs = ((size_t)col0 * DM + ci*64) * 2;
        uint32_t d = sb + bi * BUF;
        stage_cp<4>(d,         (const char*)Ah + aofs, DM*2, tid);
        stage_cp<4>(d + 16384, (const char*)Al + aofs, DM*2, tid);
        stage_cp<4>(d + 32768, (const char*)Bh + bofs, DM*2, tid);
    };

    stage(0, 0); cp_commit();
    for (int ci = 0; ci < NC; ci++) {
        if (ci + 1 < NC) { stage(ci+1, (ci+1)&1); cp_commit(); cp_wait1(); }
        else cp_wait0();
        __syncthreads();
        uint32_t d = sb + (ci&1) * BUF;
        compute_chunk<NF>(d, d + 16384, d + 32768, a_base, b_base, acc);
        __syncthreads();
    }

    #pragma unroll
    for (int mf = 0; mf < 4; mf++)
        #pragma unroll
        for (int nf = 0; nf < NF; nf++) {
            int r  = m0 + warp_m*64 + mf*16 + (lid>>2);
            int cc = col0 + warp_n*32 + nf*8 + (lid&3)*2;
            float bv0 = __ldg(bias + cc), bv1 = __ldg(bias + cc + 1);
            #pragma unroll
            for (int half = 0; half < 2; half++) {
                int gr = r + half*8;
                size_t idx = (size_t)gr*DM + cc;
                out[idx]   = acc[mf][nf][half*2+0] + bv0;
                out[idx+1] = acc[mf][nf][half*2+1] + bv1;
            }
        }
}

// ---------------------------------------------------------------------------
extern "C" void kernel_launch(void* const* d_in, const int* in_sizes, int n_in,
                              void* d_out, int out_size)
{
    const float* q   = (const float*)d_in[0];
    const float* k   = (const float*)d_in[1];
    const float* v   = (const float*)d_in[2];
    const float* w_q = (const float*)d_in[3];
    const float* b_q = (const float*)d_in[4];
    const float* w_k = (const float*)d_in[5];
    const float* b_k = (const float*)d_in[6];
    const float* w_v = (const float*)d_in[7];
    const float* b_v = (const float*)d_in[8];
    const float* w_o = (const float*)d_in[9];
    const float* b_o = (const float*)d_in[10];
    float* out = (float*)d_out;

    __half *in_h, *in_l, *w_h, *qh_h, *qh_l, *kh_h, *vh_h, *cx_h, *cx_l;
    cudaGetSymbolAddress((void**)&in_h, g_in_h);
    cudaGetSymbolAddress((void**)&in_l, g_in_l);
    cudaGetSymbolAddress((void**)&w_h,  g_w_h);
    cudaGetSymbolAddress((void**)&qh_h, g_qh_h);
    cudaGetSymbolAddress((void**)&qh_l, g_qh_l);
    cudaGetSymbolAddress((void**)&kh_h, g_kh_h);
    cudaGetSymbolAddress((void**)&vh_h, g_vh_h);
    cudaGetSymbolAddress((void**)&cx_h, g_cx_h);
    cudaGetSymbolAddress((void**)&cx_l, g_cx_l);
    float* rowsum; cudaGetSymbolAddress((void**)&rowsum, g_rowsum);

    const size_t NN = (size_t)MROWS * DM;
    const size_t WW = (size_t)DM * DM;

    float* attn_wb = nullptr;
    int write_attn = 0;
    if ((size_t)out_size >= OUT_ELEMS + ATTN_ELEMS) {
        attn_wb = out + OUT_ELEMS;
        write_attn = 1;
    }

    const int SMP = 2 * 49152;                 // 96 KB proj / outproj
    const int SMR = 66048;                     // pass A
    const int SMF = 164352;                    // pass B
    cudaFuncSetAttribute(proj_kernel,    cudaFuncAttributeMaxDynamicSharedMemorySize, SMP);
    cudaFuncSetAttribute(outproj_kernel, cudaFuncAttributeMaxDynamicSharedMemorySize, SMP);
    cudaFuncSetAttribute(rowsum_kernel,  cudaFuncAttributeMaxDynamicSharedMemorySize, SMR);
    cudaFuncSetAttribute(fusedav_kernel, cudaFuncAttributeMaxDynamicSharedMemorySize, SMF);

    split_kernel<<<dim3((int)(NN/4/256), 1, 3), 256>>>(
        q, k, v, q,
        in_h, in_h + NN, in_h + 2*NN, in_h,
        in_l, in_l + NN, in_l + 2*NN, in_l, (int)NN);
    split_kernel<<<dim3((int)(WW/4/256), 1, 4), 256>>>(
        w_q, w_k, w_v, w_o,
        w_h, w_h + WW, w_h + 2*WW, w_h + 3*WW,
        nullptr, nullptr, nullptr, nullptr, (int)WW);

    ProjArgs P;
    P.ah[0] = in_h;        P.ah[1] = in_h + NN;   P.ah[2] = in_h + 2*NN;
    P.al[0] = in_l;        P.al[1] = in_l + NN;   P.al[2] = in_l + 2*NN;
    P.bh[0] = w_h;         P.bh[1] = w_h + WW;    P.bh[2] = w_h + 2*WW;
    P.bias[0] = b_q;       P.bias[1] = b_k;       P.bias[2] = b_v;
    P.ch[0] = qh_h;        P.ch[1] = kh_h;        P.ch[2] = vh_h;
    P.cl[0] = qh_l;        P.cl[1] = nullptr;     P.cl[2] = nullptr;
    proj_kernel<<<dim3(DM/128, MROWS/128, 3), 256, SMP>>>(P);

    rowsum_kernel<<<dim3(1, SS/128, BB*HH), 256, SMR>>>(qh_h, qh_l, kh_h, rowsum);

    fusedav_kernel<<<dim3(1, SS/128, BB*HH), 256, SMF>>>(
        qh_h, qh_l, kh_h, vh_h, rowsum, cx_h, cx_l, attn_wb, write_attn);

    outproj_kernel<<<dim3(DM/128, MROWS/128), 256, SMP>>>(
        cx_h, cx_l, w_h + 3*WW, b_o, out);
}

// round 12
// speedup vs baseline: 4.2621x; 1.1585x over previous
#include <cuda_runtime.h>
#include <cuda_fp16.h>
#include <cstdint>

// ---------------- problem constants ----------------
#define BB 4
#define SS 2048
#define HH 16
#define DK 64
#define DM 1024
#define MROWS (BB*SS)                        // 8192
#define OUT_ELEMS ((size_t)MROWS*DM)         // 8,388,608
#define ATTN_ELEMS ((size_t)BB*HH*SS*SS)     // 268,435,456

// ---------------- device-global scratch ----------------
__device__ __half g_in_h[3][(size_t)MROWS*DM], g_in_l[3][(size_t)MROWS*DM];
__device__ __half g_w_h[4][(size_t)DM*DM];
__device__ __half g_qh_h[(size_t)MROWS*DM], g_qh_l[(size_t)MROWS*DM];
__device__ __half g_kh_h[(size_t)MROWS*DM];
__device__ __half g_vh_h[(size_t)MROWS*DM];
__device__ __half g_cx_h[(size_t)MROWS*DM], g_cx_l[(size_t)MROWS*DM];
__device__ float g_rowsum[(size_t)BB*HH*SS];

// ---------------- helpers ----------------
#define SWZ(o) ((o) ^ (((o) >> 3) & 0x70))

__device__ __forceinline__ uint32_t smem_u32(const void* p) {
    uint32_t a;
    asm("{ .reg .u64 t; cvta.to.shared.u64 t, %1; cvt.u32.u64 %0, t; }"
        : "=r"(a) : "l"(p));
    return a;
}
__device__ __forceinline__ void cp16(uint32_t dst, const void* src) {
    asm volatile("cp.async.cg.shared.global [%0], [%1], 16;" :: "r"(dst), "l"(src) : "memory");
}
__device__ __forceinline__ void cp_commit() { asm volatile("cp.async.commit_group;" ::: "memory"); }
__device__ __forceinline__ void cp_wait0()  { asm volatile("cp.async.wait_group 0;" ::: "memory"); }
__device__ __forceinline__ void cp_wait1()  { asm volatile("cp.async.wait_group 1;" ::: "memory"); }

__device__ __forceinline__ void ldm_x4(uint32_t addr, uint32_t& r0, uint32_t& r1,
                                       uint32_t& r2, uint32_t& r3) {
    asm volatile("ldmatrix.sync.aligned.m8n8.x4.shared.b16 {%0,%1,%2,%3}, [%4];"
                 : "=r"(r0), "=r"(r1), "=r"(r2), "=r"(r3) : "r"(addr));
}
__device__ __forceinline__ void mma_f16(float* c, uint32_t a0, uint32_t a1,
                                        uint32_t a2, uint32_t a3,
                                        uint32_t b0, uint32_t b1) {
    asm volatile("mma.sync.aligned.m16n8k16.row.col.f32.f16.f16.f32 "
                 "{%0,%1,%2,%3}, {%4,%5,%6,%7}, {%8,%9}, {%0,%1,%2,%3};"
                 : "+f"(c[0]), "+f"(c[1]), "+f"(c[2]), "+f"(c[3])
                 : "r"(a0), "r"(a1), "r"(a2), "r"(a3), "r"(b0), "r"(b1));
}
__device__ __forceinline__ uint32_t pk2h(__half a, __half b) {
    __half2 t = __halves2half2(a, b);
    return *(uint32_t*)&t;
}
__device__ __forceinline__ void split1h(float x, __half& h, __half& l) {
    h = __float2half_rn(x);
    l = __float2half_rn(x - __half2float(h));
}
__device__ __forceinline__ void split4h(float4 x, uint2& hi, uint2& lo) {
    __half h0,h1,h2,h3,l0,l1,l2,l3;
    split1h(x.x,h0,l0); split1h(x.y,h1,l1); split1h(x.z,h2,l2); split1h(x.w,h3,l3);
    hi = make_uint2(pk2h(h0,h1), pk2h(h2,h3));
    lo = make_uint2(pk2h(l0,l1), pk2h(l2,l3));
}

// fp16x2 compute: 4 ksteps of k16 over one staged 64-K chunk (A hi+lo x B hi).
template<int NF>
__device__ __forceinline__ void compute_chunk(uint32_t aHi, uint32_t aLo, uint32_t bHi,
                                              uint32_t a_base, uint32_t b_base,
                                              float (&acc)[4][NF][4]) {
    #pragma unroll
    for (int ks = 0; ks < 4; ks++) {
        uint32_t bf[2*NF];
        #pragma unroll
        for (int ng = 0; ng < NF/2; ng++) {
            uint32_t ofs = b_base + (uint32_t)(ng * 16 * 128 + ks * 32);
            ldm_x4(bHi + SWZ(ofs), bf[4*ng], bf[4*ng+1], bf[4*ng+2], bf[4*ng+3]);
        }
        #pragma unroll
        for (int mf = 0; mf < 4; mf++) {
            uint32_t ofs = a_base + (uint32_t)(mf * 16 * 128 + ks * 32);
            uint32_t h0,h1,h2,h3, l0,l1,l2,l3;
            ldm_x4(aHi + SWZ(ofs), h0,h1,h2,h3);
            ldm_x4(aLo + SWZ(ofs), l0,l1,l2,l3);
            #pragma unroll
            for (int nf = 0; nf < NF; nf++) {
                mma_f16(acc[mf][nf], h0,h1,h2,h3, bf[2*nf], bf[2*nf+1]);
                mma_f16(acc[mf][nf], l0,l1,l2,l3, bf[2*nf], bf[2*nf+1]);
            }
        }
    }
}

// single-plane variant (A hi only) for the rowsum pass
template<int NF>
__device__ __forceinline__ void compute_chunk_1p(uint32_t aHi, uint32_t bHi,
                                                 uint32_t a_base, uint32_t b_base,
                                                 float (&acc)[4][NF][4]) {
    #pragma unroll
    for (int ks = 0; ks < 4; ks++) {
        uint32_t bf[2*NF];
        #pragma unroll
        for (int ng = 0; ng < NF/2; ng++) {
            uint32_t ofs = b_base + (uint32_t)(ng * 16 * 128 + ks * 32);
            ldm_x4(bHi + SWZ(ofs), bf[4*ng], bf[4*ng+1], bf[4*ng+2], bf[4*ng+3]);
        }
        #pragma unroll
        for (int mf = 0; mf < 4; mf++) {
            uint32_t ofs = a_base + (uint32_t)(mf * 16 * 128 + ks * 32);
            uint32_t h0,h1,h2,h3;
            ldm_x4(aHi + SWZ(ofs), h0,h1,h2,h3);
            #pragma unroll
            for (int nf = 0; nf < NF; nf++)
                mma_f16(acc[mf][nf], h0,h1,h2,h3, bf[2*nf], bf[2*nf+1]);
        }
    }
}

template<int ITEMS>
__device__ __forceinline__ void stage_cp(uint32_t dstBase, const char* src,
                                         size_t strideB, int tid) {
    #pragma unroll
    for (int it = 0; it < ITEMS; it++) {
        int v = tid + it * 256;
        int row = v >> 3, c16 = (v & 7) * 16;
        cp16(dstBase + SWZ(row * 128 + c16), src + (size_t)row * strideB + c16);
    }
}

// ---------------- pre-split kernels ----------------
__global__ void __launch_bounds__(256) split_kernel(
    const float* __restrict__ s0, const float* __restrict__ s1,
    const float* __restrict__ s2, const float* __restrict__ s3,
    __half* h0, __half* h1, __half* h2, __half* h3,
    __half* l0, __half* l1, __half* l2, __half* l3, int n)
{
    int z = blockIdx.z;
    const float* s = z==0?s0 : z==1?s1 : z==2?s2 : s3;
    __half* h = z==0?h0 : z==1?h1 : z==2?h2 : h3;
    __half* l = z==0?l0 : z==1?l1 : z==2?l2 : l3;
    int i = (blockIdx.x * 256 + threadIdx.x) * 4;
    if (i >= n) return;
    float4 x = *(const float4*)(s + i);
    uint2 hi, lo;
    split4h(x, hi, lo);
    *(uint2*)(h + i) = hi;
    if (l) *(uint2*)(l + i) = lo;
}

// ---------------- projection kernel (q/k/v merged via z) ----------------
struct ProjArgs {
    const __half* ah[3]; const __half* al[3]; const __half* bh[3];
    const float*  bias[3];
    __half* ch[3]; __half* cl[3];
};

__global__ void __launch_bounds__(256, 2) proj_kernel(ProjArgs P)
{
    constexpr int NF = 4, NC = 16;
    constexpr int BUF = 49152;
    extern __shared__ char smem[];
    const uint32_t sb = smem_u32(smem);
    const int tid = threadIdx.x, wid = tid >> 5, lid = tid & 31;
    const int warp_m = wid >> 2, warp_n = wid & 3;
    const int m0 = blockIdx.y * 128, col0 = blockIdx.x * 128, z = blockIdx.z;

    const char* Ah = (const char*)P.ah[z];
    const char* Al = (const char*)P.al[z];
    const char* Bh = (const char*)P.bh[z];
    const float* bias = P.bias[z];
    __half* Ch = P.ch[z];
    __half* Cl = P.cl[z];

    float acc[4][NF][4];
    #pragma unroll
    for (int i=0;i<4;i++) for (int j=0;j<NF;j++) for (int t=0;t<4;t++) acc[i][j][t]=0.0f;

    const uint32_t a_base = (uint32_t)((warp_m*64 + (lid&15))*128 + ((lid>>4)<<4));
    const uint32_t b_base = (uint32_t)((warp_n*32 + ((lid>>4)<<3) + (lid&7))*128
                                       + (((lid>>3)&1)<<4));

    auto stage = [&](int ci, int bi) {
        size_t aofs = ((size_t)m0 * DM + ci * 64) * 2;
        size_t bofs = ((size_t)col0 * DM + ci * 64) * 2;
        uint32_t d = sb + bi * BUF;
        stage_cp<4>(d,         Ah + aofs, DM*2, tid);
        stage_cp<4>(d + 16384, Al + aofs, DM*2, tid);
        stage_cp<4>(d + 32768, Bh + bofs, DM*2, tid);
    };

    stage(0, 0); cp_commit();
    for (int ci = 0; ci < NC; ci++) {
        if (ci + 1 < NC) { stage(ci+1, (ci+1)&1); cp_commit(); cp_wait1(); }
        else cp_wait0();
        __syncthreads();
        uint32_t d = sb + (ci&1) * BUF;
        compute_chunk<NF>(d, d + 16384, d + 32768, a_base, b_base, acc);
        __syncthreads();
    }

    #pragma unroll
    for (int mf = 0; mf < 4; mf++)
        #pragma unroll
        for (int nf = 0; nf < NF; nf++) {
            int r  = m0 + warp_m*64 + mf*16 + (lid>>2);
            int cc = col0 + warp_n*32 + nf*8 + (lid&3)*2;
            float bv0 = __ldg(bias + cc), bv1 = __ldg(bias + cc + 1);
            #pragma unroll
            for (int half = 0; half < 2; half++) {
                int gr = r + half*8;
                float v0 = acc[mf][nf][half*2+0] + bv0;
                float v1 = acc[mf][nf][half*2+1] + bv1;
                int b = gr >> 11, s = gr & (SS-1), h = cc >> 6, dd = cc & (DK-1);
                size_t idx = ((((size_t)b*HH + h)*SS) + s)*DK + dd;
                __half hh, ll;
                split1h(v0, hh, ll); Ch[idx] = hh;   if (Cl) Cl[idx] = ll;
                split1h(v1, hh, ll); Ch[idx+1] = hh; if (Cl) Cl[idx+1] = ll;
            }
        }
}

// ---------------- pass A: rowsum[z, m] = sum_t exp(QK^T/8), hi-only Q -------
// smem: QH 16K | KB0 16K | KB1 16K | RS 512  = 49664
__global__ void __launch_bounds__(256, 2) rowsum_kernel(
    const __half* __restrict__ Qh, const __half* __restrict__ Kh,
    float* __restrict__ rowsum)
{
    constexpr int QH = 0, KB0 = 16384, KB1 = 32768, RS = 49152;
    extern __shared__ char smem[];
    const uint32_t sb = smem_u32(smem);
    const int tid = threadIdx.x, wid = tid >> 5, lid = tid & 31;
    const int warp_m = wid >> 2, warp_n = wid & 3;
    const int m0 = blockIdx.y * 128, z = blockIdx.z;

    const char* Qhp = (const char*)(Qh + (size_t)z*SS*DK + (size_t)m0*DK);
    const char* Kp  = (const char*)(Kh + (size_t)z*SS*DK);

    if (tid < 128) *(float*)(smem + RS + tid*4) = 0.0f;

    const uint32_t a_base = (uint32_t)((warp_m*64 + (lid&15))*128 + ((lid>>4)<<4));
    const uint32_t b_base = (uint32_t)((warp_n*32 + ((lid>>4)<<3) + (lid&7))*128
                                       + (((lid>>3)&1)<<4));

    stage_cp<4>(sb + QH, Qhp, 128, tid);
    stage_cp<4>(sb + KB0, Kp, 128, tid);
    cp_commit();

    float rsum[4][2];
    #pragma unroll
    for (int i=0;i<4;i++) { rsum[i][0]=0.0f; rsum[i][1]=0.0f; }

    for (int j = 0; j < 16; j++) {
        if (j + 1 < 16) {
            stage_cp<4>(sb + (((j+1)&1) ? KB1 : KB0), Kp + (size_t)(j+1)*16384, 128, tid);
            cp_commit(); cp_wait1();
        } else cp_wait0();
        __syncthreads();
        float sacc[4][4][4];
        #pragma unroll
        for (int i=0;i<4;i++) for (int n=0;n<4;n++) for (int t=0;t<4;t++) sacc[i][n][t]=0.0f;
        compute_chunk_1p<4>(sb + QH, sb + ((j&1) ? KB1 : KB0), a_base, b_base, sacc);
        #pragma unroll
        for (int mf = 0; mf < 4; mf++)
            #pragma unroll
            for (int half = 0; half < 2; half++)
                #pragma unroll
                for (int nf = 0; nf < 4; nf++)
                    rsum[mf][half] += __expf(sacc[mf][nf][half*2+0]*0.125f)
                                    + __expf(sacc[mf][nf][half*2+1]*0.125f);
        __syncthreads();
    }

    #pragma unroll
    for (int mf = 0; mf < 4; mf++)
        #pragma unroll
        for (int half = 0; half < 2; half++) {
            float v = rsum[mf][half];
            v += __shfl_xor_sync(0xffffffffu, v, 1);
            v += __shfl_xor_sync(0xffffffffu, v, 2);
            if ((lid & 3) == 0) {
                int rloc = warp_m*64 + mf*16 + (lid>>2) + half*8;
                atomicAdd((float*)(smem + RS + rloc*4), v);
            }
        }
    __syncthreads();
    if (tid < 128) rowsum[(size_t)z*SS + m0 + tid] = *(float*)(smem + RS + tid*4);
}

// ---------------- pass B: fused scores+AV, register-resident E --------------
// 8 warps x 16 rows. E stays in registers (S-accum layout == A-frag layout).
// smem: QH 16K | QL 16K | KB0 8K | KB1 8K | VB0 8K | VB1 8K | INV 512 = 66048
__global__ void __launch_bounds__(256, 2) fusedav_kernel(
    const __half* __restrict__ Qh, const __half* __restrict__ Ql,
    const __half* __restrict__ Kh, const __half* __restrict__ Vh,
    const float* __restrict__ rowsum,
    __half* __restrict__ Ch, __half* __restrict__ Cl,
    float* __restrict__ attn_wb, int write_attn)
{
    constexpr int QH = 0, QL = 16384, KB0 = 32768, KB1 = 40960;
    constexpr int VB0 = 49152, VB1 = 57344, INV = 65536;
    extern __shared__ char smem[];
    const uint32_t sb = smem_u32(smem);
    const int tid = threadIdx.x, wid = tid >> 5, lid = tid & 31;
    const int m0 = blockIdx.y * 128, z = blockIdx.z;

    const char* Qhp = (const char*)(Qh + (size_t)z*SS*DK + (size_t)m0*DK);
    const char* Qlp = (const char*)(Ql + (size_t)z*SS*DK + (size_t)m0*DK);
    const char* Kp  = (const char*)(Kh + (size_t)z*SS*DK);
    const __half* Vb = Vh + (size_t)z*SS*DK;
    float* wb = attn_wb ? (attn_wb + (size_t)z*SS*SS + (size_t)m0*SS) : nullptr;

    if (tid < 128)
        *(float*)(smem + INV + tid*4) = 1.0f / rowsum[(size_t)z*SS + m0 + tid];

    // warp owns rows wid*16 .. wid*16+15
    const uint32_t a_base = (uint32_t)((wid*16 + (lid&15))*128 + ((lid>>4)<<4));
    const uint32_t b_base = (uint32_t)((((lid>>4)<<3) + (lid&7))*128
                                       + (((lid>>3)&1)<<4));

    auto stageK = [&](int j, int bi) {           // 64 t x 64 dk hi
        stage_cp<2>(sb + (bi ? KB1 : KB0), Kp + (size_t)j*64*128, 128, tid);
    };
    auto stageV = [&](int j, int bi) {           // V[t,d] -> smem [d][t] (64x64)
        #pragma unroll
        for (int it = 0; it < 4; it++) {
            int v = tid + it*256;
            int tt = v >> 4, d0 = (v & 15) << 2;
            uint2 hv = *(const uint2*)(Vb + (size_t)(j*64 + tt)*DK + d0);
            ushort hs[4];
            hs[0] = hv.x & 0xFFFF; hs[1] = hv.x >> 16;
            hs[2] = hv.y & 0xFFFF; hs[3] = hv.y >> 16;
            #pragma unroll
            for (int jj = 0; jj < 4; jj++)
                *(ushort*)(smem + (bi ? VB1 : VB0) + SWZ((d0+jj)*128 + (tt<<1))) = hs[jj];
        }
    };

    stage_cp<4>(sb + QH, Qhp, 128, tid);
    stage_cp<4>(sb + QL, Qlp, 128, tid);
    stageK(0, 0);
    cp_commit();
    stageV(0, 0);

    float ctx[8][4];
    #pragma unroll
    for (int i=0;i<8;i++) for (int t=0;t<4;t++) ctx[i][t]=0.0f;

    for (int j = 0; j < 32; j++) {
        if (j + 1 < 32) { stageK(j+1, (j+1)&1); cp_commit(); cp_wait1(); }
        else cp_wait0();
        __syncthreads();                         // K(j), V(j), Q, INV visible
        if (j + 1 < 32) stageV(j+1, (j+1)&1);

        // ---- S = Q.K^T over this 64-t chunk ----
        float sacc[8][4];
        #pragma unroll
        for (int i=0;i<8;i++) for (int t=0;t<4;t++) sacc[i][t]=0.0f;
        const uint32_t kb = sb + ((j&1) ? KB1 : KB0);
        #pragma unroll
        for (int ks = 0; ks < 4; ks++) {
            uint32_t bf[16];
            #pragma unroll
            for (int ng = 0; ng < 4; ng++)
                ldm_x4(kb + SWZ(b_base + ng*16*128 + ks*32),
                       bf[4*ng], bf[4*ng+1], bf[4*ng+2], bf[4*ng+3]);
            uint32_t h0,h1,h2,h3, l0,l1,l2,l3;
            ldm_x4(sb + QH + SWZ(a_base + ks*32), h0,h1,h2,h3);
            ldm_x4(sb + QL + SWZ(a_base + ks*32), l0,l1,l2,l3);
            #pragma unroll
            for (int nf = 0; nf < 8; nf++) {
                mma_f16(sacc[nf], h0,h1,h2,h3, bf[2*nf], bf[2*nf+1]);
                mma_f16(sacc[nf], l0,l1,l2,l3, bf[2*nf], bf[2*nf+1]);
            }
        }

        // ---- E = exp in regs; optional normalized attn writeback ----
        const float inv0 = *(const float*)(smem + INV + (wid*16 + (lid>>2))*4);
        const float inv1 = *(const float*)(smem + INV + (wid*16 + (lid>>2) + 8)*4);
        #pragma unroll
        for (int nf = 0; nf < 8; nf++) {
            float e0 = __expf(sacc[nf][0]*0.125f);
            float e1 = __expf(sacc[nf][1]*0.125f);
            float e2 = __expf(sacc[nf][2]*0.125f);
            float e3 = __expf(sacc[nf][3]*0.125f);
            if (write_attn) {
                int row0 = wid*16 + (lid>>2);
                int col  = j*64 + nf*8 + (lid&3)*2;
                *(float2*)(wb + (size_t)row0*SS + col)     = make_float2(e0*inv0, e1*inv0);
                *(float2*)(wb + (size_t)(row0+8)*SS + col) = make_float2(e2*inv1, e3*inv1);
            }
            sacc[nf][0]=e0; sacc[nf][1]=e1; sacc[nf][2]=e2; sacc[nf][3]=e3;
        }

        // ---- ctx += E @ V  (E fragments straight from registers) ----
        const uint32_t vb = sb + ((j&1) ? VB1 : VB0);
        #pragma unroll
        for (int ks = 0; ks < 4; ks++) {
            uint32_t vf[16];
            #pragma unroll
            for (int ng = 0; ng < 4; ng++)
                ldm_x4(vb + SWZ(b_base + ng*16*128 + ks*32),
                       vf[4*ng], vf[4*ng+1], vf[4*ng+2], vf[4*ng+3]);
            // A-fragments from E tiles (2ks, 2ks+1)
            const float* eA = sacc[2*ks];
            const float* eB = sacc[2*ks+1];
            __half hA0,lA0,hA1,lA1,hA2,lA2,hA3,lA3;
            __half hB0,lB0,hB1,lB1,hB2,lB2,hB3,lB3;
            split1h(eA[0],hA0,lA0); split1h(eA[1],hA1,lA1);
            split1h(eA[2],hA2,lA2); split1h(eA[3],hA3,lA3);
            split1h(eB[0],hB0,lB0); split1h(eB[1],hB1,lB1);
            split1h(eB[2],hB2,lB2); split1h(eB[3],hB3,lB3);
            uint32_t ah0 = pk2h(hA0,hA1), ah1 = pk2h(hA2,hA3);
            uint32_t ah2 = pk2h(hB0,hB1), ah3 = pk2h(hB2,hB3);
            uint32_t al0 = pk2h(lA0,lA1), al1 = pk2h(lA2,lA3);
            uint32_t al2 = pk2h(lB0,lB1), al3 = pk2h(lB2,lB3);
            #pragma unroll
            for (int nd = 0; nd < 8; nd++) {
                mma_f16(ctx[nd], ah0,ah1,ah2,ah3, vf[2*nd], vf[2*nd+1]);
                mma_f16(ctx[nd], al0,al1,al2,al3, vf[2*nd], vf[2*nd+1]);
            }
        }
        __syncthreads();                         // protect K/V buffers
    }

    // ---- epilogue: ctx * inv -> hi/lo ctx planes ----
    const float inv0 = *(const float*)(smem + INV + (wid*16 + (lid>>2))*4);
    const float inv1 = *(const float*)(smem + INV + (wid*16 + (lid>>2) + 8)*4);
    #pragma unroll
    for (int nd = 0; nd < 8; nd++) {
        int r0 = m0 + wid*16 + (lid>>2);
        int cc = nd*8 + (lid&3)*2;
        int b = z >> 4, h = z & (HH-1);
        #pragma unroll
        for (int half = 0; half < 2; half++) {
            int gr = r0 + half*8;
            float inv = half ? inv1 : inv0;
            float v0 = ctx[nd][half*2+0] * inv;
            float v1 = ctx[nd][half*2+1] * inv;
            size_t idx = ((size_t)(b*SS + gr))*DM + h*DK + cc;
            __half hh, ll;
            split1h(v0, hh, ll); Ch[idx] = hh;   Cl[idx] = ll;
            split1h(v1, hh, ll); Ch[idx+1] = hh; Cl[idx+1] = ll;
        }
    }
}

// ---------------- output projection ----------------
__global__ void __launch_bounds__(256, 2) outproj_kernel(
    const __half* __restrict__ Ah, const __half* __restrict__ Al,
    const __half* __restrict__ Bh, const float* __restrict__ bias,
    float* __restrict__ out)
{
    constexpr int NF = 4, NC = 16;
    constexpr int BUF = 49152;
    extern __shared__ char smem[];
    const uint32_t sb = smem_u32(smem);
    const int tid = threadIdx.x, wid = tid >> 5, lid = tid & 31;
    const int warp_m = wid >> 2, warp_n = wid & 3;
    const int m0 = blockIdx.y * 128, col0 = blockIdx.x * 128;

    float acc[4][NF][4];
    #pragma unroll
    for (int i=0;i<4;i++) for (int j=0;j<NF;j++) for (int t=0;t<4;t++) acc[i][j][t]=0.0f;

    const uint32_t a_base = (uint32_t)((warp_m*64 + (lid&15))*128 + ((lid>>4)<<4));
    const uint32_t b_base = (uint32_t)((warp_n*32 + ((lid>>4)<<3) + (lid&7))*128
                                       + (((lid>>3)&1)<<4));

    auto stage = [&](int ci, int bi) {
        size_t aofs = ((size_t)m0 * DM + ci*64) * 2;
        size_t bofs = ((size_t)col0 * DM + ci*64) * 2;
        uint32_t d = sb + bi * BUF;
        stage_cp<4>(d,         (const char*)Ah + aofs, DM*2, tid);
        stage_cp<4>(d + 16384, (const char*)Al + aofs, DM*2, tid);
        stage_cp<4>(d + 32768, (const char*)Bh + bofs, DM*2, tid);
    };

    stage(0, 0); cp_commit();
    for (int ci = 0; ci < NC; ci++) {
        if (ci + 1 < NC) { stage(ci+1, (ci+1)&1); cp_commit(); cp_wait1(); }
        else cp_wait0();
        __syncthreads();
        uint32_t d = sb + (ci&1) * BUF;
        compute_chunk<NF>(d, d + 16384, d + 32768, a_base, b_base, acc);
        __syncthreads();
    }

    #pragma unroll
    for (int mf = 0; mf < 4; mf++)
        #pragma unroll
        for (int nf = 0; nf < NF; nf++) {
            int r  = m0 + warp_m*64 + mf*16 + (lid>>2);
            int cc = col0 + warp_n*32 + nf*8 + (lid&3)*2;
            float bv0 = __ldg(bias + cc), bv1 = __ldg(bias + cc + 1);
            #pragma unroll
            for (int half = 0; half < 2; half++) {
                int gr = r + half*8;
                size_t idx = (size_t)gr*DM + cc;
                out[idx]   = acc[mf][nf][half*2+0] + bv0;
                out[idx+1] = acc[mf][nf][half*2+1] + bv1;
            }
        }
}

// ---------------------------------------------------------------------------
extern "C" void kernel_launch(void* const* d_in, const int* in_sizes, int n_in,
                              void* d_out, int out_size)
{
    const float* q   = (const float*)d_in[0];
    const float* k   = (const float*)d_in[1];
    const float* v   = (const float*)d_in[2];
    const float* w_q = (const float*)d_in[3];
    const float* b_q = (const float*)d_in[4];
    const float* w_k = (const float*)d_in[5];
    const float* b_k = (const float*)d_in[6];
    const float* w_v = (const float*)d_in[7];
    const float* b_v = (const float*)d_in[8];
    const float* w_o = (const float*)d_in[9];
    const float* b_o = (const float*)d_in[10];
    float* out = (float*)d_out;

    __half *in_h, *in_l, *w_h, *qh_h, *qh_l, *kh_h, *vh_h, *cx_h, *cx_l;
    cudaGetSymbolAddress((void**)&in_h, g_in_h);
    cudaGetSymbolAddress((void**)&in_l, g_in_l);
    cudaGetSymbolAddress((void**)&w_h,  g_w_h);
    cudaGetSymbolAddress((void**)&qh_h, g_qh_h);
    cudaGetSymbolAddress((void**)&qh_l, g_qh_l);
    cudaGetSymbolAddress((void**)&kh_h, g_kh_h);
    cudaGetSymbolAddress((void**)&vh_h, g_vh_h);
    cudaGetSymbolAddress((void**)&cx_h, g_cx_h);
    cudaGetSymbolAddress((void**)&cx_l, g_cx_l);
    float* rowsum; cudaGetSymbolAddress((void**)&rowsum, g_rowsum);

    const size_t NN = (size_t)MROWS * DM;
    const size_t WW = (size_t)DM * DM;

    float* attn_wb = nullptr;
    int write_attn = 0;
    if ((size_t)out_size >= OUT_ELEMS + ATTN_ELEMS) {
        attn_wb = out + OUT_ELEMS;
        write_attn = 1;
    }

    const int SMP = 2 * 49152;                 // 96 KB proj / outproj
    const int SMR = 49664;                     // pass A
    const int SMF = 66048;                     // pass B
    cudaFuncSetAttribute(proj_kernel,    cudaFuncAttributeMaxDynamicSharedMemorySize, SMP);
    cudaFuncSetAttribute(outproj_kernel, cudaFuncAttributeMaxDynamicSharedMemorySize, SMP);
    cudaFuncSetAttribute(rowsum_kernel,  cudaFuncAttributeMaxDynamicSharedMemorySize, SMR);
    cudaFuncSetAttribute(fusedav_kernel, cudaFuncAttributeMaxDynamicSharedMemorySize, SMF);

    split_kernel<<<dim3((int)(NN/4/256), 1, 3), 256>>>(
        q, k, v, q,
        in_h, in_h + NN, in_h + 2*NN, in_h,
        in_l, in_l + NN, in_l + 2*NN, in_l, (int)NN);
    split_kernel<<<dim3((int)(WW/4/256), 1, 4), 256>>>(
        w_q, w_k, w_v, w_o,
        w_h, w_h + WW, w_h + 2*WW, w_h + 3*WW,
        nullptr, nullptr, nullptr, nullptr, (int)WW);

    ProjArgs P;
    P.ah[0] = in_h;        P.ah[1] = in_h + NN;   P.ah[2] = in_h + 2*NN;
    P.al[0] = in_l;        P.al[1] = in_l + NN;   P.al[2] = in_l + 2*NN;
    P.bh[0] = w_h;         P.bh[1] = w_h + WW;    P.bh[2] = w_h + 2*WW;
    P.bias[0] = b_q;       P.bias[1] = b_k;       P.bias[2] = b_v;
    P.ch[0] = qh_h;        P.ch[1] = kh_h;        P.ch[2] = vh_h;
    P.cl[0] = qh_l;        P.cl[1] = nullptr;     P.cl[2] = nullptr;
    proj_kernel<<<dim3(DM/128, MROWS/128, 3), 256, SMP>>>(P);

    rowsum_kernel<<<dim3(1, SS/128, BB*HH), 256, SMR>>>(qh_h, kh_h, rowsum);

    fusedav_kernel<<<dim3(1, SS/128, BB*HH), 256, SMF>>>(
        qh_h, qh_l, kh_h, vh_h, rowsum, cx_h, cx_l, attn_wb, write_attn);

    outproj_kernel<<<dim3(DM/128, MROWS/128), 256, SMP>>>(
        cx_h, cx_l, w_h + 3*WW, b_o, out);
}

// round 14
// speedup vs baseline: 4.5967x; 1.0785x over previous
#include <cuda_runtime.h>
#include <cuda_fp16.h>
#include <cstdint>

// ---------------- problem constants ----------------
#define BB 4
#define SS 2048
#define HH 16
#define DK 64
#define DM 1024
#define MROWS (BB*SS)                        // 8192
#define OUT_ELEMS ((size_t)MROWS*DM)         // 8,388,608
#define ATTN_ELEMS ((size_t)BB*HH*SS*SS)     // 268,435,456

// ---------------- device-global scratch ----------------
__device__ __half g_in_h[3][(size_t)MROWS*DM], g_in_l[(size_t)MROWS*DM];
__device__ __half g_w_h[4][(size_t)DM*DM];
__device__ __half g_qh_h[(size_t)MROWS*DM], g_qh_l[(size_t)MROWS*DM];
__device__ __half g_kh_h[(size_t)MROWS*DM];
__device__ __half g_vh_h[(size_t)MROWS*DM];
__device__ __half g_cx_h[(size_t)MROWS*DM], g_cx_l[(size_t)MROWS*DM];
__device__ float g_rowsum[(size_t)BB*HH*SS];

// ---------------- helpers ----------------
#define SWZ(o) ((o) ^ (((o) >> 3) & 0x70))

__device__ __forceinline__ uint32_t smem_u32(const void* p) {
    uint32_t a;
    asm("{ .reg .u64 t; cvta.to.shared.u64 t, %1; cvt.u32.u64 %0, t; }"
        : "=r"(a) : "l"(p));
    return a;
}
__device__ __forceinline__ void cp16(uint32_t dst, const void* src) {
    asm volatile("cp.async.cg.shared.global [%0], [%1], 16;" :: "r"(dst), "l"(src) : "memory");
}
__device__ __forceinline__ void cp_commit() { asm volatile("cp.async.commit_group;" ::: "memory"); }
__device__ __forceinline__ void cp_wait0()  { asm volatile("cp.async.wait_group 0;" ::: "memory"); }
__device__ __forceinline__ void cp_wait1()  { asm volatile("cp.async.wait_group 1;" ::: "memory"); }

__device__ __forceinline__ void ldm_x4(uint32_t addr, uint32_t& r0, uint32_t& r1,
                                       uint32_t& r2, uint32_t& r3) {
    asm volatile("ldmatrix.sync.aligned.m8n8.x4.shared.b16 {%0,%1,%2,%3}, [%4];"
                 : "=r"(r0), "=r"(r1), "=r"(r2), "=r"(r3) : "r"(addr));
}
__device__ __forceinline__ void mma_f16(float* c, uint32_t a0, uint32_t a1,
                                        uint32_t a2, uint32_t a3,
                                        uint32_t b0, uint32_t b1) {
    asm volatile("mma.sync.aligned.m16n8k16.row.col.f32.f16.f16.f32 "
                 "{%0,%1,%2,%3}, {%4,%5,%6,%7}, {%8,%9}, {%0,%1,%2,%3};"
                 : "+f"(c[0]), "+f"(c[1]), "+f"(c[2]), "+f"(c[3])
                 : "r"(a0), "r"(a1), "r"(a2), "r"(a3), "r"(b0), "r"(b1));
}
__device__ __forceinline__ uint32_t pk2h(__half a, __half b) {
    __half2 t = __halves2half2(a, b);
    return *(uint32_t*)&t;
}
__device__ __forceinline__ void split1h(float x, __half& h, __half& l) {
    h = __float2half_rn(x);
    l = __float2half_rn(x - __half2float(h));
}
__device__ __forceinline__ void split4h(float4 x, uint2& hi, uint2& lo) {
    __half h0,h1,h2,h3,l0,l1,l2,l3;
    split1h(x.x,h0,l0); split1h(x.y,h1,l1); split1h(x.z,h2,l2); split1h(x.w,h3,l3);
    hi = make_uint2(pk2h(h0,h1), pk2h(h2,h3));
    lo = make_uint2(pk2h(l0,l1), pk2h(l2,l3));
}

// fp16x2 compute: 4 ksteps of k16 over one staged 64-K chunk (A hi+lo x B hi).
template<int NF>
__device__ __forceinline__ void compute_chunk(uint32_t aHi, uint32_t aLo, uint32_t bHi,
                                              uint32_t a_base, uint32_t b_base,
                                              float (&acc)[4][NF][4]) {
    #pragma unroll
    for (int ks = 0; ks < 4; ks++) {
        uint32_t bf[2*NF];
        #pragma unroll
        for (int ng = 0; ng < NF/2; ng++) {
            uint32_t ofs = b_base + (uint32_t)(ng * 16 * 128 + ks * 32);
            ldm_x4(bHi + SWZ(ofs), bf[4*ng], bf[4*ng+1], bf[4*ng+2], bf[4*ng+3]);
        }
        #pragma unroll
        for (int mf = 0; mf < 4; mf++) {
            uint32_t ofs = a_base + (uint32_t)(mf * 16 * 128 + ks * 32);
            uint32_t h0,h1,h2,h3, l0,l1,l2,l3;
            ldm_x4(aHi + SWZ(ofs), h0,h1,h2,h3);
            ldm_x4(aLo + SWZ(ofs), l0,l1,l2,l3);
            #pragma unroll
            for (int nf = 0; nf < NF; nf++) {
                mma_f16(acc[mf][nf], h0,h1,h2,h3, bf[2*nf], bf[2*nf+1]);
                mma_f16(acc[mf][nf], l0,l1,l2,l3, bf[2*nf], bf[2*nf+1]);
            }
        }
    }
}

// single-A-plane variant
template<int NF>
__device__ __forceinline__ void compute_chunk_1p(uint32_t aHi, uint32_t bHi,
                                                 uint32_t a_base, uint32_t b_base,
                                                 float (&acc)[4][NF][4]) {
    #pragma unroll
    for (int ks = 0; ks < 4; ks++) {
        uint32_t bf[2*NF];
        #pragma unroll
        for (int ng = 0; ng < NF/2; ng++) {
            uint32_t ofs = b_base + (uint32_t)(ng * 16 * 128 + ks * 32);
            ldm_x4(bHi + SWZ(ofs), bf[4*ng], bf[4*ng+1], bf[4*ng+2], bf[4*ng+3]);
        }
        #pragma unroll
        for (int mf = 0; mf < 4; mf++) {
            uint32_t ofs = a_base + (uint32_t)(mf * 16 * 128 + ks * 32);
            uint32_t h0,h1,h2,h3;
            ldm_x4(aHi + SWZ(ofs), h0,h1,h2,h3);
            #pragma unroll
            for (int nf = 0; nf < NF; nf++)
                mma_f16(acc[mf][nf], h0,h1,h2,h3, bf[2*nf], bf[2*nf+1]);
        }
    }
}

template<int ITEMS>
__device__ __forceinline__ void stage_cp(uint32_t dstBase, const char* src,
                                         size_t strideB, int tid) {
    #pragma unroll
    for (int it = 0; it < ITEMS; it++) {
        int v = tid + it * 256;
        int row = v >> 3, c16 = (v & 7) * 16;
        cp16(dstBase + SWZ(row * 128 + c16), src + (size_t)row * strideB + c16);
    }
}

// ---------------- pre-split kernels ----------------
__global__ void __launch_bounds__(256) split_kernel(
    const float* __restrict__ s0, const float* __restrict__ s1,
    const float* __restrict__ s2, const float* __restrict__ s3,
    __half* h0, __half* h1, __half* h2, __half* h3,
    __half* l0, __half* l1, __half* l2, __half* l3, int n)
{
    int z = blockIdx.z;
    const float* s = z==0?s0 : z==1?s1 : z==2?s2 : s3;
    __half* h = z==0?h0 : z==1?h1 : z==2?h2 : h3;
    __half* l = z==0?l0 : z==1?l1 : z==2?l2 : l3;
    int i = (blockIdx.x * 256 + threadIdx.x) * 4;
    if (i >= n) return;
    float4 x = *(const float4*)(s + i);
    uint2 hi, lo;
    split4h(x, hi, lo);
    *(uint2*)(h + i) = hi;
    if (l) *(uint2*)(l + i) = lo;
}

// ---------------- projection kernel (q/k/v merged via z) ----------------
// Q projection uses A hi+lo (output lo plane is consumed downstream);
// K/V projections use A hi only (their outputs are hi-only anyway).
struct ProjArgs {
    const __half* ah[3]; const __half* al[3]; const __half* bh[3];
    const float*  bias[3];
    __half* ch[3]; __half* cl[3];
};

__global__ void __launch_bounds__(256, 2) proj_kernel(ProjArgs P)
{
    constexpr int NF = 4, NC = 16;
    constexpr int BUF = 49152;
    extern __shared__ char smem[];
    const uint32_t sb = smem_u32(smem);
    const int tid = threadIdx.x, wid = tid >> 5, lid = tid & 31;
    const int warp_m = wid >> 2, warp_n = wid & 3;
    const int m0 = blockIdx.y * 128, col0 = blockIdx.x * 128, z = blockIdx.z;

    const char* Ah = (const char*)P.ah[z];
    const char* Al = (const char*)P.al[z];
    const char* Bh = (const char*)P.bh[z];
    const float* bias = P.bias[z];
    __half* Ch = P.ch[z];
    __half* Cl = P.cl[z];
    const bool twoPlane = (Al != nullptr);

    float acc[4][NF][4];
    #pragma unroll
    for (int i=0;i<4;i++) for (int j=0;j<NF;j++) for (int t=0;t<4;t++) acc[i][j][t]=0.0f;

    const uint32_t a_base = (uint32_t)((warp_m*64 + (lid&15))*128 + ((lid>>4)<<4));
    const uint32_t b_base = (uint32_t)((warp_n*32 + ((lid>>4)<<3) + (lid&7))*128
                                       + (((lid>>3)&1)<<4));

    auto stage = [&](int ci, int bi) {
        size_t aofs = ((size_t)m0 * DM + ci * 64) * 2;
        size_t bofs = ((size_t)col0 * DM + ci * 64) * 2;
        uint32_t d = sb + bi * BUF;
        stage_cp<4>(d, Ah + aofs, DM*2, tid);
        if (twoPlane) stage_cp<4>(d + 16384, Al + aofs, DM*2, tid);
        stage_cp<4>(d + 32768, Bh + bofs, DM*2, tid);
    };

    stage(0, 0); cp_commit();
    for (int ci = 0; ci < NC; ci++) {
        if (ci + 1 < NC) { stage(ci+1, (ci+1)&1); cp_commit(); cp_wait1(); }
        else cp_wait0();
        __syncthreads();
        uint32_t d = sb + (ci&1) * BUF;
        if (twoPlane)
            compute_chunk<NF>(d, d + 16384, d + 32768, a_base, b_base, acc);
        else
            compute_chunk_1p<NF>(d, d + 32768, a_base, b_base, acc);
        __syncthreads();
    }

    #pragma unroll
    for (int mf = 0; mf < 4; mf++)
        #pragma unroll
        for (int nf = 0; nf < NF; nf++) {
            int r  = m0 + warp_m*64 + mf*16 + (lid>>2);
            int cc = col0 + warp_n*32 + nf*8 + (lid&3)*2;
            float bv0 = __ldg(bias + cc), bv1 = __ldg(bias + cc + 1);
            #pragma unroll
            for (int half = 0; half < 2; half++) {
                int gr = r + half*8;
                float v0 = acc[mf][nf][half*2+0] + bv0;
                float v1 = acc[mf][nf][half*2+1] + bv1;
                int b = gr >> 11, s = gr & (SS-1), h = cc >> 6, dd = cc & (DK-1);
                size_t idx = ((((size_t)b*HH + h)*SS) + s)*DK + dd;
                __half hh, ll;
                split1h(v0, hh, ll); Ch[idx] = hh;   if (Cl) Cl[idx] = ll;
                split1h(v1, hh, ll); Ch[idx+1] = hh; if (Cl) Cl[idx+1] = ll;
            }
        }
}

// ---------------- pass A: rowsum[z, m] = sum_t exp(QK^T/8), hi-only Q -------
// smem: QH 16K | KB0 16K | KB1 16K | RS 512  = 49664
__global__ void __launch_bounds__(256, 2) rowsum_kernel(
    const __half* __restrict__ Qh, const __half* __restrict__ Kh,
    float* __restrict__ rowsum)
{
    constexpr int QH = 0, KB0 = 16384, KB1 = 32768, RS = 49152;
    extern __shared__ char smem[];
    const uint32_t sb = smem_u32(smem);
    const int tid = threadIdx.x, wid = tid >> 5, lid = tid & 31;
    const int warp_m = wid >> 2, warp_n = wid & 3;
    const int m0 = blockIdx.y * 128, z = blockIdx.z;

    const char* Qhp = (const char*)(Qh + (size_t)z*SS*DK + (size_t)m0*DK);
    const char* Kp  = (const char*)(Kh + (size_t)z*SS*DK);

    if (tid < 128) *(float*)(smem + RS + tid*4) = 0.0f;

    const uint32_t a_base = (uint32_t)((warp_m*64 + (lid&15))*128 + ((lid>>4)<<4));
    const uint32_t b_base = (uint32_t)((warp_n*32 + ((lid>>4)<<3) + (lid&7))*128
                                       + (((lid>>3)&1)<<4));

    stage_cp<4>(sb + QH, Qhp, 128, tid);
    stage_cp<4>(sb + KB0, Kp, 128, tid);
    cp_commit();

    float rsum[4][2];
    #pragma unroll
    for (int i=0;i<4;i++) { rsum[i][0]=0.0f; rsum[i][1]=0.0f; }

    for (int j = 0; j < 16; j++) {
        if (j + 1 < 16) {
            stage_cp<4>(sb + (((j+1)&1) ? KB1 : KB0), Kp + (size_t)(j+1)*16384, 128, tid);
            cp_commit(); cp_wait1();
        } else cp_wait0();
        __syncthreads();
        float sacc[4][4][4];
        #pragma unroll
        for (int i=0;i<4;i++) for (int n=0;n<4;n++) for (int t=0;t<4;t++) sacc[i][n][t]=0.0f;
        compute_chunk_1p<4>(sb + QH, sb + ((j&1) ? KB1 : KB0), a_base, b_base, sacc);
        #pragma unroll
        for (int mf = 0; mf < 4; mf++)
            #pragma unroll
            for (int half = 0; half < 2; half++)
                #pragma unroll
                for (int nf = 0; nf < 4; nf++)
                    rsum[mf][half] += __expf(sacc[mf][nf][half*2+0]*0.125f)
                                    + __expf(sacc[mf][nf][half*2+1]*0.125f);
        __syncthreads();
    }

    #pragma unroll
    for (int mf = 0; mf < 4; mf++)
        #pragma unroll
        for (int half = 0; half < 2; half++) {
            float v = rsum[mf][half];
            v += __shfl_xor_sync(0xffffffffu, v, 1);
            v += __shfl_xor_sync(0xffffffffu, v, 2);
            if ((lid & 3) == 0) {
                int rloc = warp_m*64 + mf*16 + (lid>>2) + half*8;
                atomicAdd((float*)(smem + RS + rloc*4), v);
            }
        }
    __syncthreads();
    if (tid < 128) rowsum[(size_t)z*SS + m0 + tid] = *(float*)(smem + RS + tid*4);
}

// ---------------- pass B: fused scores+AV, register-resident E --------------
// 8 warps x 16 rows. E in registers; AV MMA uses E hi only (fp16).
// smem: QH 16K | QL 16K | KB0 8K | KB1 8K | VB0 8K | VB1 8K | INV 512 = 66048
__global__ void __launch_bounds__(256, 2) fusedav_kernel(
    const __half* __restrict__ Qh, const __half* __restrict__ Ql,
    const __half* __restrict__ Kh, const __half* __restrict__ Vh,
    const float* __restrict__ rowsum,
    __half* __restrict__ Ch, __half* __restrict__ Cl,
    float* __restrict__ attn_wb, int write_attn)
{
    constexpr int QH = 0, QL = 16384, KB0 = 32768, KB1 = 40960;
    constexpr int VB0 = 49152, VB1 = 57344, INV = 65536;
    extern __shared__ char smem[];
    const uint32_t sb = smem_u32(smem);
    const int tid = threadIdx.x, wid = tid >> 5, lid = tid & 31;
    const int m0 = blockIdx.y * 128, z = blockIdx.z;

    const char* Qhp = (const char*)(Qh + (size_t)z*SS*DK + (size_t)m0*DK);
    const char* Qlp = (const char*)(Ql + (size_t)z*SS*DK + (size_t)m0*DK);
    const char* Kp  = (const char*)(Kh + (size_t)z*SS*DK);
    const __half* Vb = Vh + (size_t)z*SS*DK;
    float* wb = attn_wb ? (attn_wb + (size_t)z*SS*SS + (size_t)m0*SS) : nullptr;

    if (tid < 128)
        *(float*)(smem + INV + tid*4) = 1.0f / rowsum[(size_t)z*SS + m0 + tid];

    const uint32_t a_base = (uint32_t)((wid*16 + (lid&15))*128 + ((lid>>4)<<4));
    const uint32_t b_base = (uint32_t)((((lid>>4)<<3) + (lid&7))*128
                                       + (((lid>>3)&1)<<4));

    auto stageK = [&](int j, int bi) {
        stage_cp<2>(sb + (bi ? KB1 : KB0), Kp + (size_t)j*64*128, 128, tid);
    };
    auto stageV = [&](int j, int bi) {
        #pragma unroll
        for (int it = 0; it < 4; it++) {
            int v = tid + it*256;
            int tt = v >> 4, d0 = (v & 15) << 2;
            uint2 hv = *(const uint2*)(Vb + (size_t)(j*64 + tt)*DK + d0);
            ushort hs[4];
            hs[0] = hv.x & 0xFFFF; hs[1] = hv.x >> 16;
            hs[2] = hv.y & 0xFFFF; hs[3] = hv.y >> 16;
            #pragma unroll
            for (int jj = 0; jj < 4; jj++)
                *(ushort*)(smem + (bi ? VB1 : VB0) + SWZ((d0+jj)*128 + (tt<<1))) = hs[jj];
        }
    };

    stage_cp<4>(sb + QH, Qhp, 128, tid);
    stage_cp<4>(sb + QL, Qlp, 128, tid);
    stageK(0, 0);
    cp_commit();
    stageV(0, 0);

    float ctx[8][4];
    #pragma unroll
    for (int i=0;i<8;i++) for (int t=0;t<4;t++) ctx[i][t]=0.0f;

    for (int j = 0; j < 32; j++) {
        if (j + 1 < 32) { stageK(j+1, (j+1)&1); cp_commit(); cp_wait1(); }
        else cp_wait0();
        __syncthreads();
        if (j + 1 < 32) stageV(j+1, (j+1)&1);

        // ---- S = Q.K^T over this 64-t chunk ----
        float sacc[8][4];
        #pragma unroll
        for (int i=0;i<8;i++) for (int t=0;t<4;t++) sacc[i][t]=0.0f;
        const uint32_t kb = sb + ((j&1) ? KB1 : KB0);
        #pragma unroll
        for (int ks = 0; ks < 4; ks++) {
            uint32_t bf[16];
            #pragma unroll
            for (int ng = 0; ng < 4; ng++)
                ldm_x4(kb + SWZ(b_base + ng*16*128 + ks*32),
                       bf[4*ng], bf[4*ng+1], bf[4*ng+2], bf[4*ng+3]);
            uint32_t h0,h1,h2,h3, l0,l1,l2,l3;
            ldm_x4(sb + QH + SWZ(a_base + ks*32), h0,h1,h2,h3);
            ldm_x4(sb + QL + SWZ(a_base + ks*32), l0,l1,l2,l3);
            #pragma unroll
            for (int nf = 0; nf < 8; nf++) {
                mma_f16(sacc[nf], h0,h1,h2,h3, bf[2*nf], bf[2*nf+1]);
                mma_f16(sacc[nf], l0,l1,l2,l3, bf[2*nf], bf[2*nf+1]);
            }
        }

        // ---- E = exp in regs; optional normalized attn writeback ----
        const float inv0 = *(const float*)(smem + INV + (wid*16 + (lid>>2))*4);
        const float inv1 = *(const float*)(smem + INV + (wid*16 + (lid>>2) + 8)*4);
        #pragma unroll
        for (int nf = 0; nf < 8; nf++) {
            float e0 = __expf(sacc[nf][0]*0.125f);
            float e1 = __expf(sacc[nf][1]*0.125f);
            float e2 = __expf(sacc[nf][2]*0.125f);
            float e3 = __expf(sacc[nf][3]*0.125f);
            if (write_attn) {
                int row0 = wid*16 + (lid>>2);
                int col  = j*64 + nf*8 + (lid&3)*2;
                *(float2*)(wb + (size_t)row0*SS + col)     = make_float2(e0*inv0, e1*inv0);
                *(float2*)(wb + (size_t)(row0+8)*SS + col) = make_float2(e2*inv1, e3*inv1);
            }
            sacc[nf][0]=e0; sacc[nf][1]=e1; sacc[nf][2]=e2; sacc[nf][3]=e3;
        }

        // ---- ctx += E @ V  (E hi-only fp16 fragments from registers) ----
        const uint32_t vb = sb + ((j&1) ? VB1 : VB0);
        #pragma unroll
        for (int ks = 0; ks < 4; ks++) {
            uint32_t vf[16];
            #pragma unroll
            for (int ng = 0; ng < 4; ng++)
                ldm_x4(vb + SWZ(b_base + ng*16*128 + ks*32),
                       vf[4*ng], vf[4*ng+1], vf[4*ng+2], vf[4*ng+3]);
            const float* eA = sacc[2*ks];
            const float* eB = sacc[2*ks+1];
            uint32_t ah0 = pk2h(__float2half_rn(eA[0]), __float2half_rn(eA[1]));
            uint32_t ah1 = pk2h(__float2half_rn(eA[2]), __float2half_rn(eA[3]));
            uint32_t ah2 = pk2h(__float2half_rn(eB[0]), __float2half_rn(eB[1]));
            uint32_t ah3 = pk2h(__float2half_rn(eB[2]), __float2half_rn(eB[3]));
            #pragma unroll
            for (int nd = 0; nd < 8; nd++)
                mma_f16(ctx[nd], ah0,ah1,ah2,ah3, vf[2*nd], vf[2*nd+1]);
        }
        __syncthreads();
    }

    // ---- epilogue: ctx * inv -> hi/lo ctx planes ----
    const float inv0 = *(const float*)(smem + INV + (wid*16 + (lid>>2))*4);
    const float inv1 = *(const float*)(smem + INV + (wid*16 + (lid>>2) + 8)*4);
    #pragma unroll
    for (int nd = 0; nd < 8; nd++) {
        int r0 = m0 + wid*16 + (lid>>2);
        int cc = nd*8 + (lid&3)*2;
        int b = z >> 4, h = z & (HH-1);
        #pragma unroll
        for (int half = 0; half < 2; half++) {
            int gr = r0 + half*8;
            float inv = half ? inv1 : inv0;
            float v0 = ctx[nd][half*2+0] * inv;
            float v1 = ctx[nd][half*2+1] * inv;
            size_t idx = ((size_t)(b*SS + gr))*DM + h*DK + cc;
            __half hh, ll;
            split1h(v0, hh, ll); Ch[idx] = hh;   Cl[idx] = ll;
            split1h(v1, hh, ll); Ch[idx+1] = hh; Cl[idx+1] = ll;
        }
    }
}

// ---------------- output projection ----------------
__global__ void __launch_bounds__(256, 2) outproj_kernel(
    const __half* __restrict__ Ah, const __half* __restrict__ Al,
    const __half* __restrict__ Bh, const float* __restrict__ bias,
    float* __restrict__ out)
{
    constexpr int NF = 4, NC = 16;
    constexpr int BUF = 49152;
    extern __shared__ char smem[];
    const uint32_t sb = smem_u32(smem);
    const int tid = threadIdx.x, wid = tid >> 5, lid = tid & 31;
    const int warp_m = wid >> 2, warp_n = wid & 3;
    const int m0 = blockIdx.y * 128, col0 = blockIdx.x * 128;

    float acc[4][NF][4];
    #pragma unroll
    for (int i=0;i<4;i++) for (int j=0;j<NF;j++) for (int t=0;t<4;t++) acc[i][j][t]=0.0f;

    const uint32_t a_base = (uint32_t)((warp_m*64 + (lid&15))*128 + ((lid>>4)<<4));
    const uint32_t b_base = (uint32_t)((warp_n*32 + ((lid>>4)<<3) + (lid&7))*128
                                       + (((lid>>3)&1)<<4));

    auto stage = [&](int ci, int bi) {
        size_t aofs = ((size_t)m0 * DM + ci*64) * 2;
        size_t bofs = ((size_t)col0 * DM + ci*64) * 2;
        uint32_t d = sb + bi * BUF;
        stage_cp<4>(d,         (const char*)Ah + aofs, DM*2, tid);
        stage_cp<4>(d + 16384, (const char*)Al + aofs, DM*2, tid);
        stage_cp<4>(d + 32768, (const char*)Bh + bofs, DM*2, tid);
    };

    stage(0, 0); cp_commit();
    for (int ci = 0; ci < NC; ci++) {
        if (ci + 1 < NC) { stage(ci+1, (ci+1)&1); cp_commit(); cp_wait1(); }
        else cp_wait0();
        __syncthreads();
        uint32_t d = sb + (ci&1) * BUF;
        compute_chunk<NF>(d, d + 16384, d + 32768, a_base, b_base, acc);
        __syncthreads();
    }

    #pragma unroll
    for (int mf = 0; mf < 4; mf++)
        #pragma unroll
        for (int nf = 0; nf < NF; nf++) {
            int r  = m0 + warp_m*64 + mf*16 + (lid>>2);
            int cc = col0 + warp_n*32 + nf*8 + (lid&3)*2;
            float bv0 = __ldg(bias + cc), bv1 = __ldg(bias + cc + 1);
            #pragma unroll
            for (int half = 0; half < 2; half++) {
                int gr = r + half*8;
                size_t idx = (size_t)gr*DM + cc;
                out[idx]   = acc[mf][nf][half*2+0] + bv0;
                out[idx+1] = acc[mf][nf][half*2+1] + bv1;
            }
        }
}

// ---------------------------------------------------------------------------
extern "C" void kernel_launch(void* const* d_in, const int* in_sizes, int n_in,
                              void* d_out, int out_size)
{
    const float* q   = (const float*)d_in[0];
    const float* k   = (const float*)d_in[1];
    const float* v   = (const float*)d_in[2];
    const float* w_q = (const float*)d_in[3];
    const float* b_q = (const float*)d_in[4];
    const float* w_k = (const float*)d_in[5];
    const float* b_k = (const float*)d_in[6];
    const float* w_v = (const float*)d_in[7];
    const float* b_v = (const float*)d_in[8];
    const float* w_o = (const float*)d_in[9];
    const float* b_o = (const float*)d_in[10];
    float* out = (float*)d_out;

    __half *in_h, *in_l, *w_h, *qh_h, *qh_l, *kh_h, *vh_h, *cx_h, *cx_l;
    cudaGetSymbolAddress((void**)&in_h, g_in_h);
    cudaGetSymbolAddress((void**)&in_l, g_in_l);
    cudaGetSymbolAddress((void**)&w_h,  g_w_h);
    cudaGetSymbolAddress((void**)&qh_h, g_qh_h);
    cudaGetSymbolAddress((void**)&qh_l, g_qh_l);
    cudaGetSymbolAddress((void**)&kh_h, g_kh_h);
    cudaGetSymbolAddress((void**)&vh_h, g_vh_h);
    cudaGetSymbolAddress((void**)&cx_h, g_cx_h);
    cudaGetSymbolAddress((void**)&cx_l, g_cx_l);
    float* rowsum; cudaGetSymbolAddress((void**)&rowsum, g_rowsum);

    const size_t NN = (size_t)MROWS * DM;
    const size_t WW = (size_t)DM * DM;

    float* attn_wb = nullptr;
    int write_attn = 0;
    if ((size_t)out_size >= OUT_ELEMS + ATTN_ELEMS) {
        attn_wb = out + OUT_ELEMS;
        write_attn = 1;
    }

    const int SMP = 2 * 49152;                 // 96 KB proj / outproj
    const int SMR = 49664;                     // pass A
    const int SMF = 66048;                     // pass B
    cudaFuncSetAttribute(proj_kernel,    cudaFuncAttributeMaxDynamicSharedMemorySize, SMP);
    cudaFuncSetAttribute(outproj_kernel, cudaFuncAttributeMaxDynamicSharedMemorySize, SMP);
    cudaFuncSetAttribute(rowsum_kernel,  cudaFuncAttributeMaxDynamicSharedMemorySize, SMR);
    cudaFuncSetAttribute(fusedav_kernel, cudaFuncAttributeMaxDynamicSharedMemorySize, SMF);

    // inputs: q gets hi+lo planes; k, v hi-only
    split_kernel<<<dim3((int)(NN/4/256), 1, 3), 256>>>(
        q, k, v, q,
        in_h, in_h + NN, in_h + 2*NN, in_h,
        in_l, nullptr, nullptr, nullptr, (int)NN);
    split_kernel<<<dim3((int)(WW/4/256), 1, 4), 256>>>(
        w_q, w_k, w_v, w_o,
        w_h, w_h + WW, w_h + 2*WW, w_h + 3*WW,
        nullptr, nullptr, nullptr, nullptr, (int)WW);

    ProjArgs P;
    P.ah[0] = in_h;        P.ah[1] = in_h + NN;   P.ah[2] = in_h + 2*NN;
    P.al[0] = in_l;        P.al[1] = nullptr;     P.al[2] = nullptr;
    P.bh[0] = w_h;         P.bh[1] = w_h + WW;    P.bh[2] = w_h + 2*WW;
    P.bias[0] = b_q;       P.bias[1] = b_k;       P.bias[2] = b_v;
    P.ch[0] = qh_h;        P.ch[1] = kh_h;        P.ch[2] = vh_h;
    P.cl[0] = qh_l;        P.cl[1] = nullptr;     P.cl[2] = nullptr;
    proj_kernel<<<dim3(DM/128, MROWS/128, 3), 256, SMP>>>(P);

    rowsum_kernel<<<dim3(1, SS/128, BB*HH), 256, SMR>>>(qh_h, kh_h, rowsum);

    fusedav_kernel<<<dim3(1, SS/128, BB*HH), 256, SMF>>>(
        qh_h, qh_l, kh_h, vh_h, rowsum, cx_h, cx_l, attn_wb, write_attn);

    outproj_kernel<<<dim3(DM/128, MROWS/128), 256, SMP>>>(
        cx_h, cx_l, w_h + 3*WW, b_o, out);
}

// round 15
// speedup vs baseline: 4.8673x; 1.0589x over previous
#include <cuda_runtime.h>
#include <cuda_fp16.h>
#include <cstdint>

// ---------------- problem constants ----------------
#define BB 4
#define SS 2048
#define HH 16
#define DK 64
#define DM 1024
#define MROWS (BB*SS)                        // 8192
#define OUT_ELEMS ((size_t)MROWS*DM)         // 8,388,608
#define ATTN_ELEMS ((size_t)BB*HH*SS*SS)     // 268,435,456

// ---------------- device-global scratch ----------------
__device__ __half g_in_h[3][(size_t)MROWS*DM];
__device__ __half g_w_h[4][(size_t)DM*DM];
__device__ __half g_qh_h[(size_t)MROWS*DM];
__device__ __half g_kh_h[(size_t)MROWS*DM];
__device__ __half g_vh_h[(size_t)MROWS*DM];
__device__ __half g_cx_h[(size_t)MROWS*DM], g_cx_l[(size_t)MROWS*DM];
__device__ float g_rowsum[(size_t)BB*HH*SS];

// ---------------- helpers ----------------
#define SWZ(o) ((o) ^ (((o) >> 3) & 0x70))

__device__ __forceinline__ uint32_t smem_u32(const void* p) {
    uint32_t a;
    asm("{ .reg .u64 t; cvta.to.shared.u64 t, %1; cvt.u32.u64 %0, t; }"
        : "=r"(a) : "l"(p));
    return a;
}
__device__ __forceinline__ void cp16(uint32_t dst, const void* src) {
    asm volatile("cp.async.cg.shared.global [%0], [%1], 16;" :: "r"(dst), "l"(src) : "memory");
}
__device__ __forceinline__ void cp_commit() { asm volatile("cp.async.commit_group;" ::: "memory"); }
__device__ __forceinline__ void cp_wait0()  { asm volatile("cp.async.wait_group 0;" ::: "memory"); }
__device__ __forceinline__ void cp_wait1()  { asm volatile("cp.async.wait_group 1;" ::: "memory"); }

__device__ __forceinline__ void ldm_x4(uint32_t addr, uint32_t& r0, uint32_t& r1,
                                       uint32_t& r2, uint32_t& r3) {
    asm volatile("ldmatrix.sync.aligned.m8n8.x4.shared.b16 {%0,%1,%2,%3}, [%4];"
                 : "=r"(r0), "=r"(r1), "=r"(r2), "=r"(r3) : "r"(addr));
}
__device__ __forceinline__ void mma_f16(float* c, uint32_t a0, uint32_t a1,
                                        uint32_t a2, uint32_t a3,
                                        uint32_t b0, uint32_t b1) {
    asm volatile("mma.sync.aligned.m16n8k16.row.col.f32.f16.f16.f32 "
                 "{%0,%1,%2,%3}, {%4,%5,%6,%7}, {%8,%9}, {%0,%1,%2,%3};"
                 : "+f"(c[0]), "+f"(c[1]), "+f"(c[2]), "+f"(c[3])
                 : "r"(a0), "r"(a1), "r"(a2), "r"(a3), "r"(b0), "r"(b1));
}
__device__ __forceinline__ uint32_t pk2h(__half a, __half b) {
    __half2 t = __halves2half2(a, b);
    return *(uint32_t*)&t;
}
__device__ __forceinline__ void split1h(float x, __half& h, __half& l) {
    h = __float2half_rn(x);
    l = __float2half_rn(x - __half2float(h));
}

// fp16x2 compute: 4 ksteps of k16 over one staged 64-K chunk (A hi+lo x B hi).
template<int NF>
__device__ __forceinline__ void compute_chunk(uint32_t aHi, uint32_t aLo, uint32_t bHi,
                                              uint32_t a_base, uint32_t b_base,
                                              float (&acc)[4][NF][4]) {
    #pragma unroll
    for (int ks = 0; ks < 4; ks++) {
        uint32_t bf[2*NF];
        #pragma unroll
        for (int ng = 0; ng < NF/2; ng++) {
            uint32_t ofs = b_base + (uint32_t)(ng * 16 * 128 + ks * 32);
            ldm_x4(bHi + SWZ(ofs), bf[4*ng], bf[4*ng+1], bf[4*ng+2], bf[4*ng+3]);
        }
        #pragma unroll
        for (int mf = 0; mf < 4; mf++) {
            uint32_t ofs = a_base + (uint32_t)(mf * 16 * 128 + ks * 32);
            uint32_t h0,h1,h2,h3, l0,l1,l2,l3;
            ldm_x4(aHi + SWZ(ofs), h0,h1,h2,h3);
            ldm_x4(aLo + SWZ(ofs), l0,l1,l2,l3);
            #pragma unroll
            for (int nf = 0; nf < NF; nf++) {
                mma_f16(acc[mf][nf], h0,h1,h2,h3, bf[2*nf], bf[2*nf+1]);
                mma_f16(acc[mf][nf], l0,l1,l2,l3, bf[2*nf], bf[2*nf+1]);
            }
        }
    }
}

// single-A-plane variant
template<int NF>
__device__ __forceinline__ void compute_chunk_1p(uint32_t aHi, uint32_t bHi,
                                                 uint32_t a_base, uint32_t b_base,
                                                 float (&acc)[4][NF][4]) {
    #pragma unroll
    for (int ks = 0; ks < 4; ks++) {
        uint32_t bf[2*NF];
        #pragma unroll
        for (int ng = 0; ng < NF/2; ng++) {
            uint32_t ofs = b_base + (uint32_t)(ng * 16 * 128 + ks * 32);
            ldm_x4(bHi + SWZ(ofs), bf[4*ng], bf[4*ng+1], bf[4*ng+2], bf[4*ng+3]);
        }
        #pragma unroll
        for (int mf = 0; mf < 4; mf++) {
            uint32_t ofs = a_base + (uint32_t)(mf * 16 * 128 + ks * 32);
            uint32_t h0,h1,h2,h3;
            ldm_x4(aHi + SWZ(ofs), h0,h1,h2,h3);
            #pragma unroll
            for (int nf = 0; nf < NF; nf++)
                mma_f16(acc[mf][nf], h0,h1,h2,h3, bf[2*nf], bf[2*nf+1]);
        }
    }
}

template<int ITEMS>
__device__ __forceinline__ void stage_cp(uint32_t dstBase, const char* src,
                                         size_t strideB, int tid) {
    #pragma unroll
    for (int it = 0; it < ITEMS; it++) {
        int v = tid + it * 256;
        int row = v >> 3, c16 = (v & 7) * 16;
        cp16(dstBase + SWZ(row * 128 + c16), src + (size_t)row * strideB + c16);
    }
}

// ---------------- pre-split kernel (hi plane only) ----------------
__global__ void __launch_bounds__(256) split_kernel(
    const float* __restrict__ s0, const float* __restrict__ s1,
    const float* __restrict__ s2, const float* __restrict__ s3,
    __half* h0, __half* h1, __half* h2, __half* h3, int n)
{
    int z = blockIdx.z;
    const float* s = z==0?s0 : z==1?s1 : z==2?s2 : s3;
    __half* h = z==0?h0 : z==1?h1 : z==2?h2 : h3;
    int i = (blockIdx.x * 256 + threadIdx.x) * 4;
    if (i >= n) return;
    float4 x = *(const float4*)(s + i);
    uint2 hi;
    hi.x = pk2h(__float2half_rn(x.x), __float2half_rn(x.y));
    hi.y = pk2h(__float2half_rn(x.z), __float2half_rn(x.w));
    *(uint2*)(h + i) = hi;
}

// ---------------- projection kernel (q/k/v merged via z, all 1-plane A) -----
struct ProjArgs {
    const __half* ah[3]; const __half* bh[3];
    const float*  bias[3];
    __half* ch[3];
};

__global__ void __launch_bounds__(256, 2) proj_kernel(ProjArgs P)
{
    constexpr int NF = 4, NC = 16;
    constexpr int BUF = 32768;                 // AHI 16K + BHI 16K
    extern __shared__ char smem[];
    const uint32_t sb = smem_u32(smem);
    const int tid = threadIdx.x, wid = tid >> 5, lid = tid & 31;
    const int warp_m = wid >> 2, warp_n = wid & 3;
    const int m0 = blockIdx.y * 128, col0 = blockIdx.x * 128, z = blockIdx.z;

    const char* Ah = (const char*)P.ah[z];
    const char* Bh = (const char*)P.bh[z];
    const float* bias = P.bias[z];
    __half* Ch = P.ch[z];

    float acc[4][NF][4];
    #pragma unroll
    for (int i=0;i<4;i++) for (int j=0;j<NF;j++) for (int t=0;t<4;t++) acc[i][j][t]=0.0f;

    const uint32_t a_base = (uint32_t)((warp_m*64 + (lid&15))*128 + ((lid>>4)<<4));
    const uint32_t b_base = (uint32_t)((warp_n*32 + ((lid>>4)<<3) + (lid&7))*128
                                       + (((lid>>3)&1)<<4));

    auto stage = [&](int ci, int bi) {
        size_t aofs = ((size_t)m0 * DM + ci * 64) * 2;
        size_t bofs = ((size_t)col0 * DM + ci * 64) * 2;
        uint32_t d = sb + bi * BUF;
        stage_cp<4>(d,         Ah + aofs, DM*2, tid);
        stage_cp<4>(d + 16384, Bh + bofs, DM*2, tid);
    };

    stage(0, 0); cp_commit();
    for (int ci = 0; ci < NC; ci++) {
        if (ci + 1 < NC) { stage(ci+1, (ci+1)&1); cp_commit(); cp_wait1(); }
        else cp_wait0();
        __syncthreads();
        uint32_t d = sb + (ci&1) * BUF;
        compute_chunk_1p<NF>(d, d + 16384, a_base, b_base, acc);
        __syncthreads();
    }

    #pragma unroll
    for (int mf = 0; mf < 4; mf++)
        #pragma unroll
        for (int nf = 0; nf < NF; nf++) {
            int r  = m0 + warp_m*64 + mf*16 + (lid>>2);
            int cc = col0 + warp_n*32 + nf*8 + (lid&3)*2;
            float bv0 = __ldg(bias + cc), bv1 = __ldg(bias + cc + 1);
            #pragma unroll
            for (int half = 0; half < 2; half++) {
                int gr = r + half*8;
                float v0 = acc[mf][nf][half*2+0] + bv0;
                float v1 = acc[mf][nf][half*2+1] + bv1;
                int b = gr >> 11, s = gr & (SS-1), h = cc >> 6, dd = cc & (DK-1);
                size_t idx = ((((size_t)b*HH + h)*SS) + s)*DK + dd;
                Ch[idx]   = __float2half_rn(v0);
                Ch[idx+1] = __float2half_rn(v1);
            }
        }
}

// ---------------- pass A: rowsum[z, m] = sum_t exp(QK^T/8) ----------------
// smem: QH 16K | KB0 16K | KB1 16K | RS 512  = 49664
__global__ void __launch_bounds__(256, 2) rowsum_kernel(
    const __half* __restrict__ Qh, const __half* __restrict__ Kh,
    float* __restrict__ rowsum)
{
    constexpr int QH = 0, KB0 = 16384, KB1 = 32768, RS = 49152;
    extern __shared__ char smem[];
    const uint32_t sb = smem_u32(smem);
    const int tid = threadIdx.x, wid = tid >> 5, lid = tid & 31;
    const int warp_m = wid >> 2, warp_n = wid & 3;
    const int m0 = blockIdx.y * 128, z = blockIdx.z;

    const char* Qhp = (const char*)(Qh + (size_t)z*SS*DK + (size_t)m0*DK);
    const char* Kp  = (const char*)(Kh + (size_t)z*SS*DK);

    if (tid < 128) *(float*)(smem + RS + tid*4) = 0.0f;

    const uint32_t a_base = (uint32_t)((warp_m*64 + (lid&15))*128 + ((lid>>4)<<4));
    const uint32_t b_base = (uint32_t)((warp_n*32 + ((lid>>4)<<3) + (lid&7))*128
                                       + (((lid>>3)&1)<<4));

    stage_cp<4>(sb + QH, Qhp, 128, tid);
    stage_cp<4>(sb + KB0, Kp, 128, tid);
    cp_commit();

    float rsum[4][2];
    #pragma unroll
    for (int i=0;i<4;i++) { rsum[i][0]=0.0f; rsum[i][1]=0.0f; }

    for (int j = 0; j < 16; j++) {
        if (j + 1 < 16) {
            stage_cp<4>(sb + (((j+1)&1) ? KB1 : KB0), Kp + (size_t)(j+1)*16384, 128, tid);
            cp_commit(); cp_wait1();
        } else cp_wait0();
        __syncthreads();
        float sacc[4][4][4];
        #pragma unroll
        for (int i=0;i<4;i++) for (int n=0;n<4;n++) for (int t=0;t<4;t++) sacc[i][n][t]=0.0f;
        compute_chunk_1p<4>(sb + QH, sb + ((j&1) ? KB1 : KB0), a_base, b_base, sacc);
        #pragma unroll
        for (int mf = 0; mf < 4; mf++)
            #pragma unroll
            for (int half = 0; half < 2; half++)
                #pragma unroll
                for (int nf = 0; nf < 4; nf++)
                    rsum[mf][half] += __expf(sacc[mf][nf][half*2+0]*0.125f)
                                    + __expf(sacc[mf][nf][half*2+1]*0.125f);
        __syncthreads();
    }

    #pragma unroll
    for (int mf = 0; mf < 4; mf++)
        #pragma unroll
        for (int half = 0; half < 2; half++) {
            float v = rsum[mf][half];
            v += __shfl_xor_sync(0xffffffffu, v, 1);
            v += __shfl_xor_sync(0xffffffffu, v, 2);
            if ((lid & 3) == 0) {
                int rloc = warp_m*64 + mf*16 + (lid>>2) + half*8;
                atomicAdd((float*)(smem + RS + rloc*4), v);
            }
        }
    __syncthreads();
    if (tid < 128) rowsum[(size_t)z*SS + m0 + tid] = *(float*)(smem + RS + tid*4);
}

// ---------------- pass B: fused scores+AV, register-resident E --------------
// 8 warps x 16 rows. Q hi-only, E hi-only fp16 from registers.
// smem: QH 16K | KB0 8K | KB1 8K | VB0 8K | VB1 8K | INV 512 = 49664
__global__ void __launch_bounds__(256, 2) fusedav_kernel(
    const __half* __restrict__ Qh,
    const __half* __restrict__ Kh, const __half* __restrict__ Vh,
    const float* __restrict__ rowsum,
    __half* __restrict__ Ch, __half* __restrict__ Cl,
    float* __restrict__ attn_wb, int write_attn)
{
    constexpr int QH = 0, KB0 = 16384, KB1 = 24576;
    constexpr int VB0 = 32768, VB1 = 40960, INV = 49152;
    extern __shared__ char smem[];
    const uint32_t sb = smem_u32(smem);
    const int tid = threadIdx.x, wid = tid >> 5, lid = tid & 31;
    const int m0 = blockIdx.y * 128, z = blockIdx.z;

    const char* Qhp = (const char*)(Qh + (size_t)z*SS*DK + (size_t)m0*DK);
    const char* Kp  = (const char*)(Kh + (size_t)z*SS*DK);
    const __half* Vb = Vh + (size_t)z*SS*DK;
    float* wb = attn_wb ? (attn_wb + (size_t)z*SS*SS + (size_t)m0*SS) : nullptr;

    if (tid < 128)
        *(float*)(smem + INV + tid*4) = 1.0f / rowsum[(size_t)z*SS + m0 + tid];

    const uint32_t a_base = (uint32_t)((wid*16 + (lid&15))*128 + ((lid>>4)<<4));
    const uint32_t b_base = (uint32_t)((((lid>>4)<<3) + (lid&7))*128
                                       + (((lid>>3)&1)<<4));

    auto stageK = [&](int j, int bi) {
        stage_cp<2>(sb + (bi ? KB1 : KB0), Kp + (size_t)j*64*128, 128, tid);
    };
    auto stageV = [&](int j, int bi) {
        #pragma unroll
        for (int it = 0; it < 4; it++) {
            int v = tid + it*256;
            int tt = v >> 4, d0 = (v & 15) << 2;
            uint2 hv = *(const uint2*)(Vb + (size_t)(j*64 + tt)*DK + d0);
            ushort hs[4];
            hs[0] = hv.x & 0xFFFF; hs[1] = hv.x >> 16;
            hs[2] = hv.y & 0xFFFF; hs[3] = hv.y >> 16;
            #pragma unroll
            for (int jj = 0; jj < 4; jj++)
                *(ushort*)(smem + (bi ? VB1 : VB0) + SWZ((d0+jj)*128 + (tt<<1))) = hs[jj];
        }
    };

    stage_cp<4>(sb + QH, Qhp, 128, tid);
    stageK(0, 0);
    cp_commit();
    stageV(0, 0);

    float ctx[8][4];
    #pragma unroll
    for (int i=0;i<8;i++) for (int t=0;t<4;t++) ctx[i][t]=0.0f;

    for (int j = 0; j < 32; j++) {
        if (j + 1 < 32) { stageK(j+1, (j+1)&1); cp_commit(); cp_wait1(); }
        else cp_wait0();
        __syncthreads();
        if (j + 1 < 32) stageV(j+1, (j+1)&1);

        // ---- S = Q.K^T over this 64-t chunk (Q hi only) ----
        float sacc[8][4];
        #pragma unroll
        for (int i=0;i<8;i++) for (int t=0;t<4;t++) sacc[i][t]=0.0f;
        const uint32_t kb = sb + ((j&1) ? KB1 : KB0);
        #pragma unroll
        for (int ks = 0; ks < 4; ks++) {
            uint32_t bf[16];
            #pragma unroll
            for (int ng = 0; ng < 4; ng++)
                ldm_x4(kb + SWZ(b_base + ng*16*128 + ks*32),
                       bf[4*ng], bf[4*ng+1], bf[4*ng+2], bf[4*ng+3]);
            uint32_t h0,h1,h2,h3;
            ldm_x4(sb + QH + SWZ(a_base + ks*32), h0,h1,h2,h3);
            #pragma unroll
            for (int nf = 0; nf < 8; nf++)
                mma_f16(sacc[nf], h0,h1,h2,h3, bf[2*nf], bf[2*nf+1]);
        }

        // ---- E = exp in regs; optional normalized attn writeback ----
        const float inv0 = *(const float*)(smem + INV + (wid*16 + (lid>>2))*4);
        const float inv1 = *(const float*)(smem + INV + (wid*16 + (lid>>2) + 8)*4);
        #pragma unroll
        for (int nf = 0; nf < 8; nf++) {
            float e0 = __expf(sacc[nf][0]*0.125f);
            float e1 = __expf(sacc[nf][1]*0.125f);
            float e2 = __expf(sacc[nf][2]*0.125f);
            float e3 = __expf(sacc[nf][3]*0.125f);
            if (write_attn) {
                int row0 = wid*16 + (lid>>2);
                int col  = j*64 + nf*8 + (lid&3)*2;
                *(float2*)(wb + (size_t)row0*SS + col)     = make_float2(e0*inv0, e1*inv0);
                *(float2*)(wb + (size_t)(row0+8)*SS + col) = make_float2(e2*inv1, e3*inv1);
            }
            sacc[nf][0]=e0; sacc[nf][1]=e1; sacc[nf][2]=e2; sacc[nf][3]=e3;
        }

        // ---- ctx += E @ V  (E hi-only fp16 fragments from registers) ----
        const uint32_t vb = sb + ((j&1) ? VB1 : VB0);
        #pragma unroll
        for (int ks = 0; ks < 4; ks++) {
            uint32_t vf[16];
            #pragma unroll
            for (int ng = 0; ng < 4; ng++)
                ldm_x4(vb + SWZ(b_base + ng*16*128 + ks*32),
                       vf[4*ng], vf[4*ng+1], vf[4*ng+2], vf[4*ng+3]);
            const float* eA = sacc[2*ks];
            const float* eB = sacc[2*ks+1];
            uint32_t ah0 = pk2h(__float2half_rn(eA[0]), __float2half_rn(eA[1]));
            uint32_t ah1 = pk2h(__float2half_rn(eA[2]), __float2half_rn(eA[3]));
            uint32_t ah2 = pk2h(__float2half_rn(eB[0]), __float2half_rn(eB[1]));
            uint32_t ah3 = pk2h(__float2half_rn(eB[2]), __float2half_rn(eB[3]));
            #pragma unroll
            for (int nd = 0; nd < 8; nd++)
                mma_f16(ctx[nd], ah0,ah1,ah2,ah3, vf[2*nd], vf[2*nd+1]);
        }
        __syncthreads();
    }

    // ---- epilogue: ctx * inv -> hi/lo ctx planes ----
    const float inv0 = *(const float*)(smem + INV + (wid*16 + (lid>>2))*4);
    const float inv1 = *(const float*)(smem + INV + (wid*16 + (lid>>2) + 8)*4);
    #pragma unroll
    for (int nd = 0; nd < 8; nd++) {
        int r0 = m0 + wid*16 + (lid>>2);
        int cc = nd*8 + (lid&3)*2;
        int b = z >> 4, h = z & (HH-1);
        #pragma unroll
        for (int half = 0; half < 2; half++) {
            int gr = r0 + half*8;
            float inv = half ? inv1 : inv0;
            float v0 = ctx[nd][half*2+0] * inv;
            float v1 = ctx[nd][half*2+1] * inv;
            size_t idx = ((size_t)(b*SS + gr))*DM + h*DK + cc;
            __half hh, ll;
            split1h(v0, hh, ll); Ch[idx] = hh;   Cl[idx] = ll;
            split1h(v1, hh, ll); Ch[idx+1] = hh; Cl[idx+1] = ll;
        }
    }
}

// ---------------- output projection (ctx hi+lo x W hi) ----------------
__global__ void __launch_bounds__(256, 2) outproj_kernel(
    const __half* __restrict__ Ah, const __half* __restrict__ Al,
    const __half* __restrict__ Bh, const float* __restrict__ bias,
    float* __restrict__ out)
{
    constexpr int NF = 4, NC = 16;
    constexpr int BUF = 49152;
    extern __shared__ char smem[];
    const uint32_t sb = smem_u32(smem);
    const int tid = threadIdx.x, wid = tid >> 5, lid = tid & 31;
    const int warp_m = wid >> 2, warp_n = wid & 3;
    const int m0 = blockIdx.y * 128, col0 = blockIdx.x * 128;

    float acc[4][NF][4];
    #pragma unroll
    for (int i=0;i<4;i++) for (int j=0;j<NF;j++) for (int t=0;t<4;t++) acc[i][j][t]=0.0f;

    const uint32_t a_base = (uint32_t)((warp_m*64 + (lid&15))*128 + ((lid>>4)<<4));
    const uint32_t b_base = (uint32_t)((warp_n*32 + ((lid>>4)<<3) + (lid&7))*128
                                       + (((lid>>3)&1)<<4));

    auto stage = [&](int ci, int bi) {
        size_t aofs = ((size_t)m0 * DM + ci*64) * 2;
        size_t bofs = ((size_t)col0 * DM + ci*64) * 2;
        uint32_t d = sb + bi * BUF;
        stage_cp<4>(d,         (const char*)Ah + aofs, DM*2, tid);
        stage_cp<4>(d + 16384, (const char*)Al + aofs, DM*2, tid);
        stage_cp<4>(d + 32768, (const char*)Bh + bofs, DM*2, tid);
    };

    stage(0, 0); cp_commit();
    for (int ci = 0; ci < NC; ci++) {
        if (ci + 1 < NC) { stage(ci+1, (ci+1)&1); cp_commit(); cp_wait1(); }
        else cp_wait0();
        __syncthreads();
        uint32_t d = sb + (ci&1) * BUF;
        compute_chunk<NF>(d, d + 16384, d + 32768, a_base, b_base, acc);
        __syncthreads();
    }

    #pragma unroll
    for (int mf = 0; mf < 4; mf++)
        #pragma unroll
        for (int nf = 0; nf < NF; nf++) {
            int r  = m0 + warp_m*64 + mf*16 + (lid>>2);
            int cc = col0 + warp_n*32 + nf*8 + (lid&3)*2;
            float bv0 = __ldg(bias + cc), bv1 = __ldg(bias + cc + 1);
            #pragma unroll
            for (int half = 0; half < 2; half++) {
                int gr = r + half*8;
                size_t idx = (size_t)gr*DM + cc;
                out[idx]   = acc[mf][nf][half*2+0] + bv0;
                out[idx+1] = acc[mf][nf][half*2+1] + bv1;
            }
        }
}

// ---------------------------------------------------------------------------
extern "C" void kernel_launch(void* const* d_in, const int* in_sizes, int n_in,
                              void* d_out, int out_size)
{
    const float* q   = (const float*)d_in[0];
    const float* k   = (const float*)d_in[1];
    const float* v   = (const float*)d_in[2];
    const float* w_q = (const float*)d_in[3];
    const float* b_q = (const float*)d_in[4];
    const float* w_k = (const float*)d_in[5];
    const float* b_k = (const float*)d_in[6];
    const float* w_v = (const float*)d_in[7];
    const float* b_v = (const float*)d_in[8];
    const float* w_o = (const float*)d_in[9];
    const float* b_o = (const float*)d_in[10];
    float* out = (float*)d_out;

    __half *in_h, *w_h, *qh_h, *kh_h, *vh_h, *cx_h, *cx_l;
    cudaGetSymbolAddress((void**)&in_h, g_in_h);
    cudaGetSymbolAddress((void**)&w_h,  g_w_h);
    cudaGetSymbolAddress((void**)&qh_h, g_qh_h);
    cudaGetSymbolAddress((void**)&kh_h, g_kh_h);
    cudaGetSymbolAddress((void**)&vh_h, g_vh_h);
    cudaGetSymbolAddress((void**)&cx_h, g_cx_h);
    cudaGetSymbolAddress((void**)&cx_l, g_cx_l);
    float* rowsum; cudaGetSymbolAddress((void**)&rowsum, g_rowsum);

    const size_t NN = (size_t)MROWS * DM;
    const size_t WW = (size_t)DM * DM;

    float* attn_wb = nullptr;
    int write_attn = 0;
    if ((size_t)out_size >= OUT_ELEMS + ATTN_ELEMS) {
        attn_wb = out + OUT_ELEMS;
        write_attn = 1;
    }

    const int SMP = 2 * 32768;                 // 64 KB proj
    const int SMO = 2 * 49152;                 // 96 KB outproj
    const int SMR = 49664;                     // pass A
    const int SMF = 49664;                     // pass B
    cudaFuncSetAttribute(proj_kernel,    cudaFuncAttributeMaxDynamicSharedMemorySize, SMP);
    cudaFuncSetAttribute(outproj_kernel, cudaFuncAttributeMaxDynamicSharedMemorySize, SMO);
    cudaFuncSetAttribute(rowsum_kernel,  cudaFuncAttributeMaxDynamicSharedMemorySize, SMR);
    cudaFuncSetAttribute(fusedav_kernel, cudaFuncAttributeMaxDynamicSharedMemorySize, SMF);

    // hi-only splits: inputs q/k/v and weights
    split_kernel<<<dim3((int)(NN/4/256), 1, 3), 256>>>(
        q, k, v, q, in_h, in_h + NN, in_h + 2*NN, in_h, (int)NN);
    split_kernel<<<dim3((int)(WW/4/256), 1, 4), 256>>>(
        w_q, w_k, w_v, w_o, w_h, w_h + WW, w_h + 2*WW, w_h + 3*WW, (int)WW);

    ProjArgs P;
    P.ah[0] = in_h;   P.ah[1] = in_h + NN;  P.ah[2] = in_h + 2*NN;
    P.bh[0] = w_h;    P.bh[1] = w_h + WW;   P.bh[2] = w_h + 2*WW;
    P.bias[0] = b_q;  P.bias[1] = b_k;      P.bias[2] = b_v;
    P.ch[0] = qh_h;   P.ch[1] = kh_h;       P.ch[2] = vh_h;
    proj_kernel<<<dim3(DM/128, MROWS/128, 3), 256, SMP>>>(P);

    rowsum_kernel<<<dim3(1, SS/128, BB*HH), 256, SMR>>>(qh_h, kh_h, rowsum);

    fusedav_kernel<<<dim3(1, SS/128, BB*HH), 256, SMF>>>(
        qh_h, kh_h, vh_h, rowsum, cx_h, cx_l, attn_wb, write_attn);

    outproj_kernel<<<dim3(DM/128, MROWS/128), 256, SMO>>>(
        cx_h, cx_l, w_h + 3*WW, b_o, out);
}

// round 17
// speedup vs baseline: 6.8951x; 1.4166x over previous
#include <cuda_runtime.h>
#include <cuda_fp16.h>
#include <cstdint>

// ---------------- problem constants ----------------
#define BB 4
#define SS 2048
#define HH 16
#define DK 64
#define DM 1024
#define MROWS (BB*SS)                        // 8192
#define OUT_ELEMS ((size_t)MROWS*DM)         // 8,388,608
#define ATTN_ELEMS ((size_t)BB*HH*SS*SS)     // 268,435,456

// ---------------- device-global scratch ----------------
__device__ __half g_in_h[3][(size_t)MROWS*DM];
__device__ __half g_w_h[4][(size_t)DM*DM];
__device__ __half g_qh_h[(size_t)MROWS*DM];
__device__ __half g_kh_h[(size_t)MROWS*DM];
__device__ __half g_vh_h[(size_t)MROWS*DM];
__device__ __half g_cx_h[(size_t)MROWS*DM];
__device__ float g_rowsum[(size_t)BB*HH*SS];

// ---------------- helpers ----------------
#define SWZ(o) ((o) ^ (((o) >> 3) & 0x70))

__device__ __forceinline__ uint32_t smem_u32(const void* p) {
    uint32_t a;
    asm("{ .reg .u64 t; cvta.to.shared.u64 t, %1; cvt.u32.u64 %0, t; }"
        : "=r"(a) : "l"(p));
    return a;
}
__device__ __forceinline__ void cp16(uint32_t dst, const void* src) {
    asm volatile("cp.async.cg.shared.global [%0], [%1], 16;" :: "r"(dst), "l"(src) : "memory");
}
__device__ __forceinline__ void cp_commit() { asm volatile("cp.async.commit_group;" ::: "memory"); }
__device__ __forceinline__ void cp_wait0()  { asm volatile("cp.async.wait_group 0;" ::: "memory"); }
__device__ __forceinline__ void cp_wait1()  { asm volatile("cp.async.wait_group 1;" ::: "memory"); }

__device__ __forceinline__ void ldm_x4(uint32_t addr, uint32_t& r0, uint32_t& r1,
                                       uint32_t& r2, uint32_t& r3) {
    asm volatile("ldmatrix.sync.aligned.m8n8.x4.shared.b16 {%0,%1,%2,%3}, [%4];"
                 : "=r"(r0), "=r"(r1), "=r"(r2), "=r"(r3) : "r"(addr));
}
__device__ __forceinline__ void ldm_x4_t(uint32_t addr, uint32_t& r0, uint32_t& r1,
                                         uint32_t& r2, uint32_t& r3) {
    asm volatile("ldmatrix.sync.aligned.m8n8.x4.trans.shared.b16 {%0,%1,%2,%3}, [%4];"
                 : "=r"(r0), "=r"(r1), "=r"(r2), "=r"(r3) : "r"(addr));
}
__device__ __forceinline__ void mma_f16(float* c, uint32_t a0, uint32_t a1,
                                        uint32_t a2, uint32_t a3,
                                        uint32_t b0, uint32_t b1) {
    asm volatile("mma.sync.aligned.m16n8k16.row.col.f32.f16.f16.f32 "
                 "{%0,%1,%2,%3}, {%4,%5,%6,%7}, {%8,%9}, {%0,%1,%2,%3};"
                 : "+f"(c[0]), "+f"(c[1]), "+f"(c[2]), "+f"(c[3])
                 : "r"(a0), "r"(a1), "r"(a2), "r"(a3), "r"(b0), "r"(b1));
}
__device__ __forceinline__ uint32_t pk2h(__half a, __half b) {
    __half2 t = __halves2half2(a, b);
    return *(uint32_t*)&t;
}
// packed pair convert: result = {lo16: loVal, hi16: hiVal}
__device__ __forceinline__ uint32_t cvt2(float hiVal, float loVal) {
    uint32_t r;
    asm("cvt.rn.f16x2.f32 %0, %1, %2;" : "=r"(r) : "f"(hiVal), "f"(loVal));
    return r;
}

// single-A-plane fp16 GEMM chunk: 4 ksteps of k16 (A hi x B hi)
template<int NF>
__device__ __forceinline__ void compute_chunk_1p(uint32_t aHi, uint32_t bHi,
                                                 uint32_t a_base, uint32_t b_base,
                                                 float (&acc)[4][NF][4]) {
    #pragma unroll
    for (int ks = 0; ks < 4; ks++) {
        uint32_t bf[2*NF];
        #pragma unroll
        for (int ng = 0; ng < NF/2; ng++) {
            uint32_t ofs = b_base + (uint32_t)(ng * 16 * 128 + ks * 32);
            ldm_x4(bHi + SWZ(ofs), bf[4*ng], bf[4*ng+1], bf[4*ng+2], bf[4*ng+3]);
        }
        #pragma unroll
        for (int mf = 0; mf < 4; mf++) {
            uint32_t ofs = a_base + (uint32_t)(mf * 16 * 128 + ks * 32);
            uint32_t h0,h1,h2,h3;
            ldm_x4(aHi + SWZ(ofs), h0,h1,h2,h3);
            #pragma unroll
            for (int nf = 0; nf < NF; nf++)
                mma_f16(acc[mf][nf], h0,h1,h2,h3, bf[2*nf], bf[2*nf+1]);
        }
    }
}

template<int ITEMS>
__device__ __forceinline__ void stage_cp(uint32_t dstBase, const char* src,
                                         size_t strideB, int tid) {
    #pragma unroll
    for (int it = 0; it < ITEMS; it++) {
        int v = tid + it * 256;
        int row = v >> 3, c16 = (v & 7) * 16;
        cp16(dstBase + SWZ(row * 128 + c16), src + (size_t)row * strideB + c16);
    }
}

// ---------------- pre-split kernel (hi plane only) ----------------
__global__ void __launch_bounds__(256) split_kernel(
    const float* __restrict__ s0, const float* __restrict__ s1,
    const float* __restrict__ s2, const float* __restrict__ s3,
    __half* h0, __half* h1, __half* h2, __half* h3, int n)
{
    int z = blockIdx.z;
    const float* s = z==0?s0 : z==1?s1 : z==2?s2 : s3;
    __half* h = z==0?h0 : z==1?h1 : z==2?h2 : h3;
    int i = (blockIdx.x * 256 + threadIdx.x) * 4;
    if (i >= n) return;
    float4 x = *(const float4*)(s + i);
    uint2 hi;
    hi.x = cvt2(x.y, x.x);
    hi.y = cvt2(x.w, x.z);
    *(uint2*)(h + i) = hi;
}

// ---------------- projection kernel (q/k/v merged via z, all 1-plane) -------
struct ProjArgs {
    const __half* ah[3]; const __half* bh[3];
    const float*  bias[3];
    __half* ch[3];
};

__global__ void __launch_bounds__(256, 2) proj_kernel(ProjArgs P)
{
    constexpr int NF = 4, NC = 16;
    constexpr int BUF = 32768;
    extern __shared__ char smem[];
    const uint32_t sb = smem_u32(smem);
    const int tid = threadIdx.x, wid = tid >> 5, lid = tid & 31;
    const int warp_m = wid >> 2, warp_n = wid & 3;
    const int m0 = blockIdx.y * 128, col0 = blockIdx.x * 128, z = blockIdx.z;

    const char* Ah = (const char*)P.ah[z];
    const char* Bh = (const char*)P.bh[z];
    const float* bias = P.bias[z];
    __half* Ch = P.ch[z];

    float acc[4][NF][4];
    #pragma unroll
    for (int i=0;i<4;i++) for (int j=0;j<NF;j++) for (int t=0;t<4;t++) acc[i][j][t]=0.0f;

    const uint32_t a_base = (uint32_t)((warp_m*64 + (lid&15))*128 + ((lid>>4)<<4));
    const uint32_t b_base = (uint32_t)((warp_n*32 + ((lid>>4)<<3) + (lid&7))*128
                                       + (((lid>>3)&1)<<4));

    auto stage = [&](int ci, int bi) {
        size_t aofs = ((size_t)m0 * DM + ci * 64) * 2;
        size_t bofs = ((size_t)col0 * DM + ci * 64) * 2;
        uint32_t d = sb + bi * BUF;
        stage_cp<4>(d,         Ah + aofs, DM*2, tid);
        stage_cp<4>(d + 16384, Bh + bofs, DM*2, tid);
    };

    stage(0, 0); cp_commit();
    for (int ci = 0; ci < NC; ci++) {
        if (ci + 1 < NC) { stage(ci+1, (ci+1)&1); cp_commit(); cp_wait1(); }
        else cp_wait0();
        __syncthreads();
        uint32_t d = sb + (ci&1) * BUF;
        compute_chunk_1p<NF>(d, d + 16384, a_base, b_base, acc);
        __syncthreads();
    }

    #pragma unroll
    for (int mf = 0; mf < 4; mf++)
        #pragma unroll
        for (int nf = 0; nf < NF; nf++) {
            int r  = m0 + warp_m*64 + mf*16 + (lid>>2);
            int cc = col0 + warp_n*32 + nf*8 + (lid&3)*2;
            float bv0 = __ldg(bias + cc), bv1 = __ldg(bias + cc + 1);
            #pragma unroll
            for (int half = 0; half < 2; half++) {
                int gr = r + half*8;
                float v0 = acc[mf][nf][half*2+0] + bv0;
                float v1 = acc[mf][nf][half*2+1] + bv1;
                int b = gr >> 11, s = gr & (SS-1), h = cc >> 6, dd = cc & (DK-1);
                size_t idx = ((((size_t)b*HH + h)*SS) + s)*DK + dd;
                *(uint32_t*)(Ch + idx) = cvt2(v1, v0);
            }
        }
}

// ---------------- pass A: rowsum[z, m] = sum_t exp(QK^T/8) ----------------
// smem: QH 16K | KB0 16K | KB1 16K | RS 512  = 49664
__global__ void __launch_bounds__(256, 2) rowsum_kernel(
    const __half* __restrict__ Qh, const __half* __restrict__ Kh,
    float* __restrict__ rowsum)
{
    constexpr int QH = 0, KB0 = 16384, KB1 = 32768, RS = 49152;
    extern __shared__ char smem[];
    const uint32_t sb = smem_u32(smem);
    const int tid = threadIdx.x, wid = tid >> 5, lid = tid & 31;
    const int warp_m = wid >> 2, warp_n = wid & 3;
    const int m0 = blockIdx.y * 128, z = blockIdx.z;

    const char* Qhp = (const char*)(Qh + (size_t)z*SS*DK + (size_t)m0*DK);
    const char* Kp  = (const char*)(Kh + (size_t)z*SS*DK);

    if (tid < 128) *(float*)(smem + RS + tid*4) = 0.0f;

    const uint32_t a_base = (uint32_t)((warp_m*64 + (lid&15))*128 + ((lid>>4)<<4));
    const uint32_t b_base = (uint32_t)((warp_n*32 + ((lid>>4)<<3) + (lid&7))*128
                                       + (((lid>>3)&1)<<4));

    stage_cp<4>(sb + QH, Qhp, 128, tid);
    stage_cp<4>(sb + KB0, Kp, 128, tid);
    cp_commit();

    float rsum[4][2];
    #pragma unroll
    for (int i=0;i<4;i++) { rsum[i][0]=0.0f; rsum[i][1]=0.0f; }

    for (int j = 0; j < 16; j++) {
        if (j + 1 < 16) {
            stage_cp<4>(sb + (((j+1)&1) ? KB1 : KB0), Kp + (size_t)(j+1)*16384, 128, tid);
            cp_commit(); cp_wait1();
        } else cp_wait0();
        __syncthreads();
        float sacc[4][4][4];
        #pragma unroll
        for (int i=0;i<4;i++) for (int n=0;n<4;n++) for (int t=0;t<4;t++) sacc[i][n][t]=0.0f;
        compute_chunk_1p<4>(sb + QH, sb + ((j&1) ? KB1 : KB0), a_base, b_base, sacc);
        #pragma unroll
        for (int mf = 0; mf < 4; mf++)
            #pragma unroll
            for (int half = 0; half < 2; half++)
                #pragma unroll
                for (int nf = 0; nf < 4; nf++)
                    rsum[mf][half] += __expf(sacc[mf][nf][half*2+0]*0.125f)
                                    + __expf(sacc[mf][nf][half*2+1]*0.125f);
        __syncthreads();
    }

    #pragma unroll
    for (int mf = 0; mf < 4; mf++)
        #pragma unroll
        for (int half = 0; half < 2; half++) {
            float v = rsum[mf][half];
            v += __shfl_xor_sync(0xffffffffu, v, 1);
            v += __shfl_xor_sync(0xffffffffu, v, 2);
            if ((lid & 3) == 0) {
                int rloc = warp_m*64 + mf*16 + (lid>>2) + half*8;
                atomicAdd((float*)(smem + RS + rloc*4), v);
            }
        }
    __syncthreads();
    if (tid < 128) rowsum[(size_t)z*SS + m0 + tid] = *(float*)(smem + RS + tid*4);
}

// ---------------- pass B: fused scores+AV, register-resident E --------------
// 8 warps x 16 rows. Q hi-only; V staged raw + ldmatrix.trans B-fragments.
// smem: QH 16K | KB0 8K | KB1 8K | VB0 8K | VB1 8K | INV 512 = 49664
__global__ void __launch_bounds__(256, 2) fusedav_kernel(
    const __half* __restrict__ Qh,
    const __half* __restrict__ Kh, const __half* __restrict__ Vh,
    const float* __restrict__ rowsum,
    __half* __restrict__ Ch,
    float* __restrict__ attn_wb, int write_attn)
{
    constexpr int QH = 0, KB0 = 16384, KB1 = 24576;
    constexpr int VB0 = 32768, VB1 = 40960, INV = 49152;
    extern __shared__ char smem[];
    const uint32_t sb = smem_u32(smem);
    const int tid = threadIdx.x, wid = tid >> 5, lid = tid & 31;
    const int m0 = blockIdx.y * 128, z = blockIdx.z;

    const char* Qhp = (const char*)(Qh + (size_t)z*SS*DK + (size_t)m0*DK);
    const char* Kp  = (const char*)(Kh + (size_t)z*SS*DK);
    const char* Vp  = (const char*)(Vh + (size_t)z*SS*DK);
    float* wb = attn_wb ? (attn_wb + (size_t)z*SS*SS + (size_t)m0*SS) : nullptr;

    if (tid < 128)
        *(float*)(smem + INV + tid*4) = 1.0f / rowsum[(size_t)z*SS + m0 + tid];

    const uint32_t a_base = (uint32_t)((wid*16 + (lid&15))*128 + ((lid>>4)<<4));
    const uint32_t b_base = (uint32_t)((((lid>>4)<<3) + (lid&7))*128
                                       + (((lid>>3)&1)<<4));
    // per-lane base for V trans-ldsm: row = ((lid>>3)&1)*8 + (lid&7), col = ((lid>>4)&1)*16
    const uint32_t vt_base = (uint32_t)(((((lid>>3)&1)*8 + (lid&7))*128)
                                        + (((lid>>4)&1)*16));

    auto stageKV = [&](int j, int bi) {
        stage_cp<2>(sb + (bi ? KB1 : KB0), Kp + (size_t)j*64*128, 128, tid);
        stage_cp<2>(sb + (bi ? VB1 : VB0), Vp + (size_t)j*64*128, 128, tid);
    };

    stage_cp<4>(sb + QH, Qhp, 128, tid);
    stageKV(0, 0);
    cp_commit();

    float ctx[8][4];
    #pragma unroll
    for (int i=0;i<8;i++) for (int t=0;t<4;t++) ctx[i][t]=0.0f;

    for (int j = 0; j < 32; j++) {
        if (j + 1 < 32) { stageKV(j+1, (j+1)&1); cp_commit(); cp_wait1(); }
        else cp_wait0();
        __syncthreads();                         // K(j), V(j), Q, INV visible

        // ---- S = Q.K^T over this 64-t chunk (Q hi only) ----
        float sacc[8][4];
        #pragma unroll
        for (int i=0;i<8;i++) for (int t=0;t<4;t++) sacc[i][t]=0.0f;
        const uint32_t kb = sb + ((j&1) ? KB1 : KB0);
        #pragma unroll
        for (int ks = 0; ks < 4; ks++) {
            uint32_t bf[16];
            #pragma unroll
            for (int ng = 0; ng < 4; ng++)
                ldm_x4(kb + SWZ(b_base + ng*16*128 + ks*32),
                       bf[4*ng], bf[4*ng+1], bf[4*ng+2], bf[4*ng+3]);
            uint32_t h0,h1,h2,h3;
            ldm_x4(sb + QH + SWZ(a_base + ks*32), h0,h1,h2,h3);
            #pragma unroll
            for (int nf = 0; nf < 8; nf++)
                mma_f16(sacc[nf], h0,h1,h2,h3, bf[2*nf], bf[2*nf+1]);
        }

        // ---- E = exp in regs; optional normalized attn writeback ----
        const float inv0 = *(const float*)(smem + INV + (wid*16 + (lid>>2))*4);
        const float inv1 = *(const float*)(smem + INV + (wid*16 + (lid>>2) + 8)*4);
        #pragma unroll
        for (int nf = 0; nf < 8; nf++) {
            float e0 = __expf(sacc[nf][0]*0.125f);
            float e1 = __expf(sacc[nf][1]*0.125f);
            float e2 = __expf(sacc[nf][2]*0.125f);
            float e3 = __expf(sacc[nf][3]*0.125f);
            if (write_attn) {
                int row0 = wid*16 + (lid>>2);
                int col  = j*64 + nf*8 + (lid&3)*2;
                *(float2*)(wb + (size_t)row0*SS + col)     = make_float2(e0*inv0, e1*inv0);
                *(float2*)(wb + (size_t)(row0+8)*SS + col) = make_float2(e2*inv1, e3*inv1);
            }
            sacc[nf][0]=e0; sacc[nf][1]=e1; sacc[nf][2]=e2; sacc[nf][3]=e3;
        }

        // ---- ctx += E @ V  (E fp16 via packed cvt; V via trans-ldsm) ----
        const uint32_t vbase = sb + ((j&1) ? VB1 : VB0);
        #pragma unroll
        for (int ks = 0; ks < 4; ks++) {
            uint32_t vf[16];
            #pragma unroll
            for (int g = 0; g < 4; g++)
                ldm_x4_t(vbase + SWZ(vt_base + ks*2048 + g*32),
                         vf[4*g], vf[4*g+1], vf[4*g+2], vf[4*g+3]);
            const float* eA = sacc[2*ks];
            const float* eB = sacc[2*ks+1];
            uint32_t ah0 = cvt2(eA[1], eA[0]);
            uint32_t ah1 = cvt2(eA[3], eA[2]);
            uint32_t ah2 = cvt2(eB[1], eB[0]);
            uint32_t ah3 = cvt2(eB[3], eB[2]);
            #pragma unroll
            for (int g = 0; g < 4; g++) {
                mma_f16(ctx[2*g],   ah0,ah1,ah2,ah3, vf[4*g],   vf[4*g+1]);
                mma_f16(ctx[2*g+1], ah0,ah1,ah2,ah3, vf[4*g+2], vf[4*g+3]);
            }
        }
        __syncthreads();                         // protect K/V buffers
    }

    // ---- epilogue: ctx * inv -> ctx hi plane ----
    const float inv0 = *(const float*)(smem + INV + (wid*16 + (lid>>2))*4);
    const float inv1 = *(const float*)(smem + INV + (wid*16 + (lid>>2) + 8)*4);
    #pragma unroll
    for (int nd = 0; nd < 8; nd++) {
        int r0 = m0 + wid*16 + (lid>>2);
        int cc = nd*8 + (lid&3)*2;
        int b = z >> 4, h = z & (HH-1);
        #pragma unroll
        for (int half = 0; half < 2; half++) {
            int gr = r0 + half*8;
            float inv = half ? inv1 : inv0;
            float v0 = ctx[nd][half*2+0] * inv;
            float v1 = ctx[nd][half*2+1] * inv;
            size_t idx = ((size_t)(b*SS + gr))*DM + h*DK + cc;
            *(uint32_t*)(Ch + idx) = cvt2(v1, v0);
        }
    }
}

// ---------------- output projection (ctx hi x W hi, 1-plane) ----------------
__global__ void __launch_bounds__(256, 2) outproj_kernel(
    const __half* __restrict__ Ah, const __half* __restrict__ Bh,
    const float* __restrict__ bias, float* __restrict__ out)
{
    constexpr int NF = 4, NC = 16;
    constexpr int BUF = 32768;
    extern __shared__ char smem[];
    const uint32_t sb = smem_u32(smem);
    const int tid = threadIdx.x, wid = tid >> 5, lid = tid & 31;
    const int warp_m = wid >> 2, warp_n = wid & 3;
    const int m0 = blockIdx.y * 128, col0 = blockIdx.x * 128;

    float acc[4][NF][4];
    #pragma unroll
    for (int i=0;i<4;i++) for (int j=0;j<NF;j++) for (int t=0;t<4;t++) acc[i][j][t]=0.0f;

    const uint32_t a_base = (uint32_t)((warp_m*64 + (lid&15))*128 + ((lid>>4)<<4));
    const uint32_t b_base = (uint32_t)((warp_n*32 + ((lid>>4)<<3) + (lid&7))*128
                                       + (((lid>>3)&1)<<4));

    auto stage = [&](int ci, int bi) {
        size_t aofs = ((size_t)m0 * DM + ci*64) * 2;
        size_t bofs = ((size_t)col0 * DM + ci*64) * 2;
        uint32_t d = sb + bi * BUF;
        stage_cp<4>(d,         (const char*)Ah + aofs, DM*2, tid);
        stage_cp<4>(d + 16384, (const char*)Bh + bofs, DM*2, tid);
    };

    stage(0, 0); cp_commit();
    for (int ci = 0; ci < NC; ci++) {
        if (ci + 1 < NC) { stage(ci+1, (ci+1)&1); cp_commit(); cp_wait1(); }
        else cp_wait0();
        __syncthreads();
        uint32_t d = sb + (ci&1) * BUF;
        compute_chunk_1p<NF>(d, d + 16384, a_base, b_base, acc);
        __syncthreads();
    }

    #pragma unroll
    for (int mf = 0; mf < 4; mf++)
        #pragma unroll
        for (int nf = 0; nf < NF; nf++) {
            int r  = m0 + warp_m*64 + mf*16 + (lid>>2);
            int cc = col0 + warp_n*32 + nf*8 + (lid&3)*2;
            float bv0 = __ldg(bias + cc), bv1 = __ldg(bias + cc + 1);
            #pragma unroll
            for (int half = 0; half < 2; half++) {
                int gr = r + half*8;
                size_t idx = (size_t)gr*DM + cc;
                out[idx]   = acc[mf][nf][half*2+0] + bv0;
                out[idx+1] = acc[mf][nf][half*2+1] + bv1;
            }
        }
}

// ---------------------------------------------------------------------------
extern "C" void kernel_launch(void* const* d_in, const int* in_sizes, int n_in,
                              void* d_out, int out_size)
{
    const float* q   = (const float*)d_in[0];
    const float* k   = (const float*)d_in[1];
    const float* v   = (const float*)d_in[2];
    const float* w_q = (const float*)d_in[3];
    const float* b_q = (const float*)d_in[4];
    const float* w_k = (const float*)d_in[5];
    const float* b_k = (const float*)d_in[6];
    const float* w_v = (const float*)d_in[7];
    const float* b_v = (const float*)d_in[8];
    const float* w_o = (const float*)d_in[9];
    const float* b_o = (const float*)d_in[10];
    float* out = (float*)d_out;

    __half *in_h, *w_h, *qh_h, *kh_h, *vh_h, *cx_h;
    cudaGetSymbolAddress((void**)&in_h, g_in_h);
    cudaGetSymbolAddress((void**)&w_h,  g_w_h);
    cudaGetSymbolAddress((void**)&qh_h, g_qh_h);
    cudaGetSymbolAddress((void**)&kh_h, g_kh_h);
    cudaGetSymbolAddress((void**)&vh_h, g_vh_h);
    cudaGetSymbolAddress((void**)&cx_h, g_cx_h);
    float* rowsum; cudaGetSymbolAddress((void**)&rowsum, g_rowsum);

    const size_t NN = (size_t)MROWS * DM;
    const size_t WW = (size_t)DM * DM;

    float* attn_wb = nullptr;
    int write_attn = 0;
    if ((size_t)out_size >= OUT_ELEMS + ATTN_ELEMS) {
        attn_wb = out + OUT_ELEMS;
        write_attn = 1;
    }

    const int SMP = 2 * 32768;                 // 64 KB proj / outproj
    const int SMR = 49664;                     // pass A
    const int SMF = 49664;                     // pass B
    cudaFuncSetAttribute(proj_kernel,    cudaFuncAttributeMaxDynamicSharedMemorySize, SMP);
    cudaFuncSetAttribute(outproj_kernel, cudaFuncAttributeMaxDynamicSharedMemorySize, SMP);
    cudaFuncSetAttribute(rowsum_kernel,  cudaFuncAttributeMaxDynamicSharedMemorySize, SMR);
    cudaFuncSetAttribute(fusedav_kernel, cudaFuncAttributeMaxDynamicSharedMemorySize, SMF);

    split_kernel<<<dim3((int)(NN/4/256), 1, 3), 256>>>(
        q, k, v, q, in_h, in_h + NN, in_h + 2*NN, in_h, (int)NN);
    split_kernel<<<dim3((int)(WW/4/256), 1, 4), 256>>>(
        w_q, w_k, w_v, w_o, w_h, w_h + WW, w_h + 2*WW, w_h + 3*WW, (int)WW);

    ProjArgs P;
    P.ah[0] = in_h;   P.ah[1] = in_h + NN;  P.ah[2] = in_h + 2*NN;
    P.bh[0] = w_h;    P.bh[1] = w_h + WW;   P.bh[2] = w_h + 2*WW;
    P.bias[0] = b_q;  P.bias[1] = b_k;      P.bias[2] = b_v;
    P.ch[0] = qh_h;   P.ch[1] = kh_h;       P.ch[2] = vh_h;
    proj_kernel<<<dim3(DM/128, MROWS/128, 3), 256, SMP>>>(P);

    rowsum_kernel<<<dim3(1, SS/128, BB*HH), 256, SMR>>>(qh_h, kh_h, rowsum);

    fusedav_kernel<<<dim3(1, SS/128, BB*HH), 256, SMF>>>(
        qh_h, kh_h, vh_h, rowsum, cx_h, attn_wb, write_attn);

    outproj_kernel<<<dim3(DM/128, MROWS/128), 256, SMP>>>(
        cx_h, w_h + 3*WW, b_o, out);
}